// round 1
// baseline (speedup 1.0000x reference)
#include <cuda_runtime.h>
#include <math.h>

#define S_LEN 2048
#define HIDDIM 2048
#define NH 16
#define NKV 4
#define HD 128
#define NQD (NH*HD)    // 2048
#define NKD (NKV*HD)   // 512
#define WIN 1024

// Scratch (allocation-free rule: __device__ globals)
__device__ float g_Q[S_LEN * NQD];
__device__ float g_K[S_LEN * NKD];
__device__ float g_V[S_LEN * NKD];
__device__ float g_A[S_LEN * NQD];

// ---------------------------------------------------------------------------
// GEMM: C[M,N] = A[M,K_] * B[N,K_]^T   (both A and B are K-contiguous, NT)
// BM=BN=128, BK=8, TM=TN=8, 256 threads
// ---------------------------------------------------------------------------
#define BM 128
#define BN 128
#define BK 8
#define TM 8
#define TN 8

__global__ __launch_bounds__(256) void gemm_nt(const float* __restrict__ A,
                                               const float* __restrict__ B,
                                               float* __restrict__ C,
                                               int M, int N, int K_) {
    __shared__ float As[BK][BM];
    __shared__ float Bs[BK][BN];
    int tid = threadIdx.x;
    int mBase = blockIdx.y * BM;
    int nBase = blockIdx.x * BN;
    int tRow = (tid / 16) * TM;
    int tCol = (tid % 16) * TN;

    float acc[TM][TN] = {};

    int lr = tid >> 1;            // 0..127
    int lc = (tid & 1) << 2;      // 0 or 4
    const float* Aptr = A + (size_t)(mBase + lr) * K_ + lc;
    const float* Bptr = B + (size_t)(nBase + lr) * K_ + lc;

    for (int kt = 0; kt < K_; kt += BK) {
        float4 av = *(const float4*)(Aptr + kt);
        float4 bv = *(const float4*)(Bptr + kt);
        As[lc + 0][lr] = av.x; As[lc + 1][lr] = av.y;
        As[lc + 2][lr] = av.z; As[lc + 3][lr] = av.w;
        Bs[lc + 0][lr] = bv.x; Bs[lc + 1][lr] = bv.y;
        Bs[lc + 2][lr] = bv.z; Bs[lc + 3][lr] = bv.w;
        __syncthreads();
#pragma unroll
        for (int k = 0; k < BK; k++) {
            float ra[TM], rb[TN];
#pragma unroll
            for (int i = 0; i < TM; i++) ra[i] = As[k][tRow + i];
#pragma unroll
            for (int j = 0; j < TN; j++) rb[j] = Bs[k][tCol + j];
#pragma unroll
            for (int i = 0; i < TM; i++)
#pragma unroll
                for (int j = 0; j < TN; j++) acc[i][j] += ra[i] * rb[j];
        }
        __syncthreads();
    }

#pragma unroll
    for (int i = 0; i < TM; i++) {
        float* crow = C + (size_t)(mBase + tRow + i) * N + nBase + tCol;
        *(float4*)(crow + 0) = make_float4(acc[i][0], acc[i][1], acc[i][2], acc[i][3]);
        *(float4*)(crow + 4) = make_float4(acc[i][4], acc[i][5], acc[i][6], acc[i][7]);
    }
}

// ---------------------------------------------------------------------------
// RoPE (HF rotate_half) applied in place. X is [S, nh, HD] flattened.
// ---------------------------------------------------------------------------
__global__ void rope_kernel(float* __restrict__ X, int nh) {
    int idx = blockIdx.x * blockDim.x + threadIdx.x;
    int total = S_LEN * nh * (HD / 2);
    if (idx >= total) return;
    int j = idx % (HD / 2);
    int h = (idx / (HD / 2)) % nh;
    int s = idx / ((HD / 2) * nh);
    // inv_freq = 10000^(-2j/128)
    float invf = expf(-logf(10000.0f) * (float)(2 * j) / (float)HD);
    float ang = (float)s * invf;
    float c = cosf(ang), sn = sinf(ang);
    float* p = X + (size_t)s * nh * HD + (size_t)h * HD;
    float a = p[j], b = p[j + HD / 2];
    p[j]          = a * c - b * sn;
    p[j + HD / 2] = b * c + a * sn;
}

// ---------------------------------------------------------------------------
// Flash attention with sliding-window causal mask (analytic), online softmax.
// Tile: 64 queries x 64 keys, HD=128. 256 threads.
// smem: Qs[64][129], Ks[64][129], Vs[64][128], Ps[64][65], m/l/alpha[64]
// ---------------------------------------------------------------------------
#define BQ 64
#define BKK 64
#define QS_STRIDE 129
#define PS_STRIDE 65
#define FLASH_SMEM ((64*129*2 + 64*128 + 64*65 + 3*64) * sizeof(float))

__global__ __launch_bounds__(256) void flash_kernel(const float* __restrict__ Q,
                                                    const float* __restrict__ K,
                                                    const float* __restrict__ V,
                                                    float* __restrict__ O) {
    extern __shared__ float sm[];
    float* Qs = sm;                         // [64][129]
    float* Ks = Qs + 64 * QS_STRIDE;        // [64][129]
    float* Vs = Ks + 64 * QS_STRIDE;        // [64][128]
    float* Ps = Vs + 64 * 128;              // [64][65]
    float* mrow = Ps + 64 * PS_STRIDE;
    float* lrow = mrow + 64;
    float* arow = lrow + 64;

    int tid = threadIdx.x;
    int qt = blockIdx.x;
    int h = blockIdx.y;
    int q0 = qt * BQ;
    int kvh = h >> 2;
    const float sc = 0.08838834764831845f;  // 1/sqrt(128)

    // load Q tile [64][128]
    for (int i = tid; i < 64 * 32; i += 256) {
        int r = i >> 5, c4 = (i & 31) << 2;
        float4 v = *(const float4*)(Q + (size_t)(q0 + r) * NQD + h * HD + c4);
        float* d = Qs + r * QS_STRIDE + c4;
        d[0] = v.x; d[1] = v.y; d[2] = v.z; d[3] = v.w;
    }
    if (tid < 64) { mrow[tid] = -1e30f; lrow[tid] = 0.0f; }

    float acc[4][8] = {};
    int ty = tid >> 4, tx = tid & 15;
    int sRow = ty * 4, sCol = tx * 4;   // S-phase 4x4
    int oRow = ty * 4, oCol = tx * 8;   // O-phase 4x8

    int kt0 = q0 - (WIN - 1);
    kt0 = (kt0 < 0) ? 0 : (kt0 >> 6);

    for (int kt = kt0; kt <= qt; kt++) {
        int k0 = kt * BKK;
        // load K, V tiles
        for (int i = tid; i < 64 * 32; i += 256) {
            int r = i >> 5, c4 = (i & 31) << 2;
            const float* kp = K + (size_t)(k0 + r) * NKD + kvh * HD + c4;
            const float* vp = V + (size_t)(k0 + r) * NKD + kvh * HD + c4;
            float4 kv = *(const float4*)kp;
            float* d = Ks + r * QS_STRIDE + c4;
            d[0] = kv.x; d[1] = kv.y; d[2] = kv.z; d[3] = kv.w;
            *(float4*)(Vs + r * 128 + c4) = *(const float4*)vp;
        }
        __syncthreads();

        // S = Q K^T (4x4 per thread)
        float sacc[4][4] = {};
#pragma unroll 4
        for (int d = 0; d < HD; d++) {
            float rq[4], rk[4];
#pragma unroll
            for (int i = 0; i < 4; i++) rq[i] = Qs[(sRow + i) * QS_STRIDE + d];
#pragma unroll
            for (int j = 0; j < 4; j++) rk[j] = Ks[(sCol + j) * QS_STRIDE + d];
#pragma unroll
            for (int i = 0; i < 4; i++)
#pragma unroll
                for (int j = 0; j < 4; j++) sacc[i][j] += rq[i] * rk[j];
        }
        // mask + scale, write to Ps
#pragma unroll
        for (int i = 0; i < 4; i++) {
            int qi = q0 + sRow + i;
#pragma unroll
            for (int j = 0; j < 4; j++) {
                int kj = k0 + sCol + j;
                bool ok = (kj <= qi) && (qi - kj < WIN);
                Ps[(sRow + i) * PS_STRIDE + sCol + j] = ok ? sacc[i][j] * sc : -1e9f;
            }
        }
        __syncthreads();

        // online softmax: 4 threads per row
        {
            int r = tid >> 2, part = tid & 3;
            int cbase = part * 16;
            float mx = -1e30f;
#pragma unroll
            for (int c = 0; c < 16; c++) mx = fmaxf(mx, Ps[r * PS_STRIDE + cbase + c]);
            mx = fmaxf(mx, __shfl_xor_sync(0xffffffffu, mx, 1));
            mx = fmaxf(mx, __shfl_xor_sync(0xffffffffu, mx, 2));
            float mold = mrow[r];
            float mnew = fmaxf(mold, mx);
            float sum = 0.0f;
#pragma unroll
            for (int c = 0; c < 16; c++) {
                float p = expf(Ps[r * PS_STRIDE + cbase + c] - mnew);
                Ps[r * PS_STRIDE + cbase + c] = p;
                sum += p;
            }
            sum += __shfl_xor_sync(0xffffffffu, sum, 1);
            sum += __shfl_xor_sync(0xffffffffu, sum, 2);
            if (part == 0) {
                float al = expf(mold - mnew);
                arow[r] = al;
                lrow[r] = lrow[r] * al + sum;
                mrow[r] = mnew;
            }
        }
        __syncthreads();

        // rescale O and accumulate P @ V
        float al[4];
#pragma unroll
        for (int i = 0; i < 4; i++) al[i] = arow[oRow + i];
#pragma unroll
        for (int i = 0; i < 4; i++)
#pragma unroll
            for (int j = 0; j < 8; j++) acc[i][j] *= al[i];

#pragma unroll 4
        for (int kk = 0; kk < BKK; kk++) {
            float rp[4], rv[8];
#pragma unroll
            for (int i = 0; i < 4; i++) rp[i] = Ps[(oRow + i) * PS_STRIDE + kk];
#pragma unroll
            for (int j = 0; j < 8; j++) rv[j] = Vs[kk * 128 + oCol + j];
#pragma unroll
            for (int i = 0; i < 4; i++)
#pragma unroll
                for (int j = 0; j < 8; j++) acc[i][j] += rp[i] * rv[j];
        }
        __syncthreads();
    }

    // finalize + write out
#pragma unroll
    for (int i = 0; i < 4; i++) {
        float inv = 1.0f / lrow[oRow + i];
        float* op = O + (size_t)(q0 + oRow + i) * NQD + h * HD + oCol;
#pragma unroll
        for (int j = 0; j < 8; j++) op[j] = acc[i][j] * inv;
    }
}

// ---------------------------------------------------------------------------
extern "C" void kernel_launch(void* const* d_in, const int* in_sizes, int n_in,
                              void* d_out, int out_size) {
    const float* x  = (const float*)d_in[0];
    // d_in[1] = attention_mask (deterministic sliding-window; recomputed analytically)
    const float* wq = (const float*)d_in[2];
    const float* wk = (const float*)d_in[3];
    const float* wv = (const float*)d_in[4];
    const float* wo = (const float*)d_in[5];
    float* out = (float*)d_out;

    float *Qb, *Kb, *Vb, *Ab;
    cudaGetSymbolAddress((void**)&Qb, g_Q);
    cudaGetSymbolAddress((void**)&Kb, g_K);
    cudaGetSymbolAddress((void**)&Vb, g_V);
    cudaGetSymbolAddress((void**)&Ab, g_A);

    static bool attr_set = false;
    if (!attr_set) {
        cudaFuncSetAttribute(flash_kernel, cudaFuncAttributeMaxDynamicSharedMemorySize,
                             (int)FLASH_SMEM);
        attr_set = true;
    }

    // QKV projections
    {
        dim3 gq(NQD / BN, S_LEN / BM);
        gemm_nt<<<gq, 256>>>(x, wq, Qb, S_LEN, NQD, HIDDIM);
        dim3 gk(NKD / BN, S_LEN / BM);
        gemm_nt<<<gk, 256>>>(x, wk, Kb, S_LEN, NKD, HIDDIM);
        gemm_nt<<<gk, 256>>>(x, wv, Vb, S_LEN, NKD, HIDDIM);
    }
    // RoPE on Q and K
    {
        int totq = S_LEN * NH * (HD / 2);
        rope_kernel<<<(totq + 255) / 256, 256>>>(Qb, NH);
        int totk = S_LEN * NKV * (HD / 2);
        rope_kernel<<<(totk + 255) / 256, 256>>>(Kb, NKV);
    }
    // Flash attention
    {
        dim3 g(S_LEN / BQ, NH);
        flash_kernel<<<g, 256, FLASH_SMEM>>>(Qb, Kb, Vb, Ab);
    }
    // Output projection
    {
        dim3 go(HIDDIM / BN, S_LEN / BM);
        gemm_nt<<<go, 256>>>(Ab, wo, out, S_LEN, HIDDIM, NQD);
    }
}

// round 3
// speedup vs baseline: 1.2045x; 1.2045x over previous
#include <cuda_runtime.h>
#include <cuda_bf16.h>
#include <math.h>
#include <stdint.h>

#define S_LEN 2048
#define HIDDIM 2048
#define NH 16
#define NKV 4
#define HD 128
#define NQD (NH*HD)    // 2048
#define NKD (NKV*HD)   // 512
#define WIN 1024
#define KDIM 2048      // every GEMM in this layer has K = 2048

// ---------------- scratch (__device__ globals; no allocs allowed) ----------
__device__ float g_Q[S_LEN * NQD];
__device__ float g_K[S_LEN * NKD];
__device__ float g_V[S_LEN * NKD];
__device__ float g_A[S_LEN * NQD];

__device__ __nv_bfloat16 g_xh[S_LEN * HIDDIM], g_xl[S_LEN * HIDDIM];
__device__ __nv_bfloat16 g_wqh[NQD * HIDDIM],  g_wql[NQD * HIDDIM];
__device__ __nv_bfloat16 g_wkh[NKD * HIDDIM],  g_wkl[NKD * HIDDIM];
__device__ __nv_bfloat16 g_wvh[NKD * HIDDIM],  g_wvl[NKD * HIDDIM];
__device__ __nv_bfloat16 g_woh[HIDDIM * NQD],  g_wol[HIDDIM * NQD];
__device__ __nv_bfloat16 g_ah[S_LEN * NQD],    g_al[S_LEN * NQD];

// ---------------- helpers ---------------------------------------------------
__device__ __forceinline__ uint32_t smem_u32(const void* p) {
    uint32_t a;
    asm("{ .reg .u64 t; cvta.to.shared.u64 t, %1; cvt.u32.u64 %0, t; }"
        : "=r"(a) : "l"(p));
    return a;
}

__device__ __forceinline__ void cp16(uint32_t dst, const void* src) {
    asm volatile("cp.async.cg.shared.global [%0], [%1], 16;" :: "r"(dst), "l"(src));
}

__device__ __forceinline__ void mma16816(float* c, const uint32_t* a,
                                         uint32_t b0, uint32_t b1) {
    asm volatile(
        "mma.sync.aligned.m16n8k16.row.col.f32.bf16.bf16.f32 "
        "{%0,%1,%2,%3}, {%4,%5,%6,%7}, {%8,%9}, {%0,%1,%2,%3};"
        : "+f"(c[0]), "+f"(c[1]), "+f"(c[2]), "+f"(c[3])
        : "r"(a[0]), "r"(a[1]), "r"(a[2]), "r"(a[3]), "r"(b0), "r"(b1));
}

// ---------------------------------------------------------------------------
// fp32 -> (bf16 hi, bf16 lo) split, 4 floats per thread.
// ---------------------------------------------------------------------------
__global__ void split_kernel(const float* __restrict__ in,
                             __nv_bfloat16* __restrict__ hi,
                             __nv_bfloat16* __restrict__ lo, int n4) {
    int i = blockIdx.x * blockDim.x + threadIdx.x;
    if (i >= n4) return;
    float4 v = ((const float4*)in)[i];
    __nv_bfloat16 h0 = __float2bfloat16(v.x);
    __nv_bfloat16 h1 = __float2bfloat16(v.y);
    __nv_bfloat16 h2 = __float2bfloat16(v.z);
    __nv_bfloat16 h3 = __float2bfloat16(v.w);
    __nv_bfloat16 l0 = __float2bfloat16(v.x - __bfloat162float(h0));
    __nv_bfloat16 l1 = __float2bfloat16(v.y - __bfloat162float(h1));
    __nv_bfloat16 l2 = __float2bfloat16(v.z - __bfloat162float(h2));
    __nv_bfloat16 l3 = __float2bfloat16(v.w - __bfloat162float(h3));
    uint2 hv, lv;
    hv.x = (uint32_t)__bfloat16_as_ushort(h0) | ((uint32_t)__bfloat16_as_ushort(h1) << 16);
    hv.y = (uint32_t)__bfloat16_as_ushort(h2) | ((uint32_t)__bfloat16_as_ushort(h3) << 16);
    lv.x = (uint32_t)__bfloat16_as_ushort(l0) | ((uint32_t)__bfloat16_as_ushort(l1) << 16);
    lv.y = (uint32_t)__bfloat16_as_ushort(l2) | ((uint32_t)__bfloat16_as_ushort(l3) << 16);
    ((uint2*)hi)[i] = hv;
    ((uint2*)lo)[i] = lv;
}

// ---------------------------------------------------------------------------
// HMMA GEMM: C[M,N] = Ah*Bh^T + Ah*Bl^T + Al*Bh^T  (NT layout, K=2048, fp32 acc)
// BM=BN=128, BK=32, 256 threads (8 warps, 4x2), warp tile 32x64.
// cp.async 2-stage pipeline. Padded smem rows (40 halves) -> conflict-free lds.
// ---------------------------------------------------------------------------
#define BM 128
#define BN 128
#define BKG 32
#define ASTRIDE 40                         // halves per smem row (32 + 8 pad)
#define TILE_B (128 * ASTRIDE * 2)         // 10240 bytes per tile
#define STAGE_B (4 * TILE_B)               // Ah, Al, Bh, Bl
#define GEMM_SMEM (2 * STAGE_B)            // 81920 bytes
#define NST (KDIM / BKG)                   // 64 stages

__global__ __launch_bounds__(256) void gemm_hmma(const __nv_bfloat16* __restrict__ Ahg,
                                                 const __nv_bfloat16* __restrict__ Alg,
                                                 const __nv_bfloat16* __restrict__ Bhg,
                                                 const __nv_bfloat16* __restrict__ Blg,
                                                 float* __restrict__ C, int N) {
    extern __shared__ char smg[];
    const int t = threadIdx.x;
    const int wid = t >> 5, lane = t & 31;
    const int g = lane >> 2, tq = lane & 3;
    const int wm = wid & 3, wn = wid >> 2;
    const int mBase = blockIdx.y * BM;
    const int nBase = blockIdx.x * BN;

    float acc[2][8][4] = {};

    const int chunk = t & 3;   // 16B chunk within 64B row
    const int row0 = t >> 2;   // 0..63

    const __nv_bfloat16* srcs[4] = {Ahg, Alg, Bhg, Blg};
    const int tb[4] = {mBase, mBase, nBase, nBase};

    // ---- prologue: stage 0 ----
    {
        char* base = smg;
#pragma unroll
        for (int ti = 0; ti < 4; ti++)
#pragma unroll
            for (int rr = 0; rr < 2; rr++) {
                int r = row0 + rr * 64;
                uint32_t dst = smem_u32(base + ti * TILE_B + (r * ASTRIDE + chunk * 8) * 2);
                cp16(dst, srcs[ti] + (size_t)(tb[ti] + r) * KDIM + chunk * 8);
            }
        asm volatile("cp.async.commit_group;");
    }

    for (int s = 0; s < NST; s++) {
        if (s + 1 < NST) {
            char* base = smg + ((s + 1) & 1) * STAGE_B;
            int k0 = (s + 1) * BKG;
#pragma unroll
            for (int ti = 0; ti < 4; ti++)
#pragma unroll
                for (int rr = 0; rr < 2; rr++) {
                    int r = row0 + rr * 64;
                    uint32_t dst = smem_u32(base + ti * TILE_B + (r * ASTRIDE + chunk * 8) * 2);
                    cp16(dst, srcs[ti] + (size_t)(tb[ti] + r) * KDIM + k0 + chunk * 8);
                }
            asm volatile("cp.async.commit_group;");
            asm volatile("cp.async.wait_group 1;");
        } else {
            asm volatile("cp.async.wait_group 0;");
        }
        __syncthreads();

        // ---- compute on buffer s%2 ----
        const char* base = smg + (s & 1) * STAGE_B;
        const char* pAh = base;
        const char* pAl = base + TILE_B;
        const char* pBh = base + 2 * TILE_B;
        const char* pBl = base + 3 * TILE_B;

#pragma unroll
        for (int ks = 0; ks < 2; ks++) {
            const int kk = ks * 16;
            uint32_t ah[2][4], al[2][4];
#pragma unroll
            for (int mf = 0; mf < 2; mf++) {
                int r = wm * 32 + mf * 16 + g;
                int off = (r * ASTRIDE + kk + 2 * tq) * 2;
                ah[mf][0] = *(const uint32_t*)(pAh + off);
                ah[mf][1] = *(const uint32_t*)(pAh + off + 8 * ASTRIDE * 2);
                ah[mf][2] = *(const uint32_t*)(pAh + off + 16);
                ah[mf][3] = *(const uint32_t*)(pAh + off + 8 * ASTRIDE * 2 + 16);
                al[mf][0] = *(const uint32_t*)(pAl + off);
                al[mf][1] = *(const uint32_t*)(pAl + off + 8 * ASTRIDE * 2);
                al[mf][2] = *(const uint32_t*)(pAl + off + 16);
                al[mf][3] = *(const uint32_t*)(pAl + off + 8 * ASTRIDE * 2 + 16);
            }
#pragma unroll
            for (int nf = 0; nf < 8; nf++) {
                int rn = wn * 64 + nf * 8 + g;
                int off = (rn * ASTRIDE + kk + 2 * tq) * 2;
                uint32_t bh0 = *(const uint32_t*)(pBh + off);
                uint32_t bh1 = *(const uint32_t*)(pBh + off + 16);
                uint32_t bl0 = *(const uint32_t*)(pBl + off);
                uint32_t bl1 = *(const uint32_t*)(pBl + off + 16);
#pragma unroll
                for (int mf = 0; mf < 2; mf++) {
                    mma16816(acc[mf][nf], ah[mf], bh0, bh1);
                    mma16816(acc[mf][nf], ah[mf], bl0, bl1);
                    mma16816(acc[mf][nf], al[mf], bh0, bh1);
                }
            }
        }
        __syncthreads();
    }

    // ---- epilogue ----
#pragma unroll
    for (int mf = 0; mf < 2; mf++) {
        int row = mBase + wm * 32 + mf * 16 + g;
#pragma unroll
        for (int nf = 0; nf < 8; nf++) {
            int col = nBase + wn * 64 + nf * 8 + 2 * tq;
            *(float2*)(C + (size_t)row * N + col) =
                make_float2(acc[mf][nf][0], acc[mf][nf][1]);
            *(float2*)(C + (size_t)(row + 8) * N + col) =
                make_float2(acc[mf][nf][2], acc[mf][nf][3]);
        }
    }
}

// ---------------------------------------------------------------------------
// RoPE (HF rotate_half) in place. X is [S, nh, HD].
// ---------------------------------------------------------------------------
__global__ void rope_kernel(float* __restrict__ X, int nh) {
    int idx = blockIdx.x * blockDim.x + threadIdx.x;
    int total = S_LEN * nh * (HD / 2);
    if (idx >= total) return;
    int j = idx % (HD / 2);
    int h = (idx / (HD / 2)) % nh;
    int s = idx / ((HD / 2) * nh);
    float invf = expf(-logf(10000.0f) * (float)(2 * j) / (float)HD);
    float ang = (float)s * invf;
    float c = cosf(ang), sn = sinf(ang);
    float* p = X + (size_t)s * nh * HD + (size_t)h * HD;
    float a = p[j], b = p[j + HD / 2];
    p[j]          = a * c - b * sn;
    p[j + HD / 2] = b * c + a * sn;
}

// ---------------------------------------------------------------------------
// Flash attention, fp32 FFMA. 64q x 64k tiles, online softmax.
// ---------------------------------------------------------------------------
#define BQ 64
#define BKK 64
#define QS_STRIDE 129
#define PS_STRIDE 65
#define FLASH_SMEM ((64*129*2 + 64*128 + 64*65 + 3*64) * sizeof(float))

__global__ __launch_bounds__(256) void flash_kernel(const float* __restrict__ Q,
                                                    const float* __restrict__ K,
                                                    const float* __restrict__ V,
                                                    float* __restrict__ O) {
    extern __shared__ float sm[];
    float* Qs = sm;
    float* Ks = Qs + 64 * QS_STRIDE;
    float* Vs = Ks + 64 * QS_STRIDE;
    float* Ps = Vs + 64 * 128;
    float* mrow = Ps + 64 * PS_STRIDE;
    float* lrow = mrow + 64;
    float* arow = lrow + 64;

    int tid = threadIdx.x;
    int qt = blockIdx.x;
    int h = blockIdx.y;
    int q0 = qt * BQ;
    int kvh = h >> 2;
    const float sc = 0.08838834764831845f;

    for (int i = tid; i < 64 * 32; i += 256) {
        int r = i >> 5, c4 = (i & 31) << 2;
        float4 v = *(const float4*)(Q + (size_t)(q0 + r) * NQD + h * HD + c4);
        float* d = Qs + r * QS_STRIDE + c4;
        d[0] = v.x; d[1] = v.y; d[2] = v.z; d[3] = v.w;
    }
    if (tid < 64) { mrow[tid] = -1e30f; lrow[tid] = 0.0f; }

    float acc[4][8] = {};
    int ty = tid >> 4, tx = tid & 15;
    int sRow = ty * 4, sCol = tx * 4;
    int oRow = ty * 4, oCol = tx * 8;

    int kt0 = q0 - (WIN - 1);
    kt0 = (kt0 < 0) ? 0 : (kt0 >> 6);

    for (int kt = kt0; kt <= qt; kt++) {
        int k0 = kt * BKK;
        for (int i = tid; i < 64 * 32; i += 256) {
            int r = i >> 5, c4 = (i & 31) << 2;
            const float* kp = K + (size_t)(k0 + r) * NKD + kvh * HD + c4;
            const float* vp = V + (size_t)(k0 + r) * NKD + kvh * HD + c4;
            float4 kv = *(const float4*)kp;
            float* d = Ks + r * QS_STRIDE + c4;
            d[0] = kv.x; d[1] = kv.y; d[2] = kv.z; d[3] = kv.w;
            *(float4*)(Vs + r * 128 + c4) = *(const float4*)vp;
        }
        __syncthreads();

        float sacc[4][4] = {};
#pragma unroll 4
        for (int d = 0; d < HD; d++) {
            float rq[4], rk[4];
#pragma unroll
            for (int i = 0; i < 4; i++) rq[i] = Qs[(sRow + i) * QS_STRIDE + d];
#pragma unroll
            for (int j = 0; j < 4; j++) rk[j] = Ks[(sCol + j) * QS_STRIDE + d];
#pragma unroll
            for (int i = 0; i < 4; i++)
#pragma unroll
                for (int j = 0; j < 4; j++) sacc[i][j] += rq[i] * rk[j];
        }
#pragma unroll
        for (int i = 0; i < 4; i++) {
            int qi = q0 + sRow + i;
#pragma unroll
            for (int j = 0; j < 4; j++) {
                int kj = k0 + sCol + j;
                bool ok = (kj <= qi) && (qi - kj < WIN);
                Ps[(sRow + i) * PS_STRIDE + sCol + j] = ok ? sacc[i][j] * sc : -1e9f;
            }
        }
        __syncthreads();

        {
            int r = tid >> 2, part = tid & 3;
            int cbase = part * 16;
            float mx = -1e30f;
#pragma unroll
            for (int c = 0; c < 16; c++) mx = fmaxf(mx, Ps[r * PS_STRIDE + cbase + c]);
            mx = fmaxf(mx, __shfl_xor_sync(0xffffffffu, mx, 1));
            mx = fmaxf(mx, __shfl_xor_sync(0xffffffffu, mx, 2));
            float mold = mrow[r];
            float mnew = fmaxf(mold, mx);
            float sum = 0.0f;
#pragma unroll
            for (int c = 0; c < 16; c++) {
                float p = expf(Ps[r * PS_STRIDE + cbase + c] - mnew);
                Ps[r * PS_STRIDE + cbase + c] = p;
                sum += p;
            }
            sum += __shfl_xor_sync(0xffffffffu, sum, 1);
            sum += __shfl_xor_sync(0xffffffffu, sum, 2);
            if (part == 0) {
                float al = expf(mold - mnew);
                arow[r] = al;
                lrow[r] = lrow[r] * al + sum;
                mrow[r] = mnew;
            }
        }
        __syncthreads();

        float al[4];
#pragma unroll
        for (int i = 0; i < 4; i++) al[i] = arow[oRow + i];
#pragma unroll
        for (int i = 0; i < 4; i++)
#pragma unroll
            for (int j = 0; j < 8; j++) acc[i][j] *= al[i];

#pragma unroll 4
        for (int kk = 0; kk < BKK; kk++) {
            float rp[4], rv[8];
#pragma unroll
            for (int i = 0; i < 4; i++) rp[i] = Ps[(oRow + i) * PS_STRIDE + kk];
#pragma unroll
            for (int j = 0; j < 8; j++) rv[j] = Vs[kk * 128 + oCol + j];
#pragma unroll
            for (int i = 0; i < 4; i++)
#pragma unroll
                for (int j = 0; j < 8; j++) acc[i][j] += rp[i] * rv[j];
        }
        __syncthreads();
    }

#pragma unroll
    for (int i = 0; i < 4; i++) {
        float inv = 1.0f / lrow[oRow + i];
        float* op = O + (size_t)(q0 + oRow + i) * NQD + h * HD + oCol;
#pragma unroll
        for (int j = 0; j < 8; j++) op[j] = acc[i][j] * inv;
    }
}

// ---------------------------------------------------------------------------
extern "C" void kernel_launch(void* const* d_in, const int* in_sizes, int n_in,
                              void* d_out, int out_size) {
    const float* x  = (const float*)d_in[0];
    // d_in[1] = attention_mask (deterministic sliding-window; computed analytically)
    const float* wq = (const float*)d_in[2];
    const float* wk = (const float*)d_in[3];
    const float* wv = (const float*)d_in[4];
    const float* wo = (const float*)d_in[5];
    float* out = (float*)d_out;

    float *Qb, *Kb, *Vb, *Ab;
    cudaGetSymbolAddress((void**)&Qb, g_Q);
    cudaGetSymbolAddress((void**)&Kb, g_K);
    cudaGetSymbolAddress((void**)&Vb, g_V);
    cudaGetSymbolAddress((void**)&Ab, g_A);
    __nv_bfloat16 *xh, *xl, *wqh, *wql, *wkh, *wkl, *wvh, *wvl, *woh, *wol, *ah, *al;
    cudaGetSymbolAddress((void**)&xh, g_xh);   cudaGetSymbolAddress((void**)&xl, g_xl);
    cudaGetSymbolAddress((void**)&wqh, g_wqh); cudaGetSymbolAddress((void**)&wql, g_wql);
    cudaGetSymbolAddress((void**)&wkh, g_wkh); cudaGetSymbolAddress((void**)&wkl, g_wkl);
    cudaGetSymbolAddress((void**)&wvh, g_wvh); cudaGetSymbolAddress((void**)&wvl, g_wvl);
    cudaGetSymbolAddress((void**)&woh, g_woh); cudaGetSymbolAddress((void**)&wol, g_wol);
    cudaGetSymbolAddress((void**)&ah, g_ah);   cudaGetSymbolAddress((void**)&al, g_al);

    static bool attr_set = false;
    if (!attr_set) {
        cudaFuncSetAttribute(flash_kernel, cudaFuncAttributeMaxDynamicSharedMemorySize,
                             (int)FLASH_SMEM);
        cudaFuncSetAttribute(gemm_hmma, cudaFuncAttributeMaxDynamicSharedMemorySize,
                             (int)GEMM_SMEM);
        attr_set = true;
    }

    // split fp32 -> bf16 hi/lo
    {
        int n4;
        n4 = S_LEN * HIDDIM / 4;  split_kernel<<<(n4 + 255) / 256, 256>>>(x,  xh,  xl,  n4);
        n4 = NQD * HIDDIM / 4;    split_kernel<<<(n4 + 255) / 256, 256>>>(wq, wqh, wql, n4);
        n4 = NKD * HIDDIM / 4;    split_kernel<<<(n4 + 255) / 256, 256>>>(wk, wkh, wkl, n4);
        n4 = NKD * HIDDIM / 4;    split_kernel<<<(n4 + 255) / 256, 256>>>(wv, wvh, wvl, n4);
        n4 = HIDDIM * NQD / 4;    split_kernel<<<(n4 + 255) / 256, 256>>>(wo, woh, wol, n4);
    }

    // QKV projections on HMMA tensor cores
    {
        dim3 gq(NQD / BN, S_LEN / BM);
        gemm_hmma<<<gq, 256, GEMM_SMEM>>>(xh, xl, wqh, wql, Qb, NQD);
        dim3 gk(NKD / BN, S_LEN / BM);
        gemm_hmma<<<gk, 256, GEMM_SMEM>>>(xh, xl, wkh, wkl, Kb, NKD);
        gemm_hmma<<<gk, 256, GEMM_SMEM>>>(xh, xl, wvh, wvl, Vb, NKD);
    }
    // RoPE
    {
        int totq = S_LEN * NH * (HD / 2);
        rope_kernel<<<(totq + 255) / 256, 256>>>(Qb, NH);
        int totk = S_LEN * NKV * (HD / 2);
        rope_kernel<<<(totk + 255) / 256, 256>>>(Kb, NKV);
    }
    // Flash attention (fp32)
    {
        dim3 g(S_LEN / BQ, NH);
        flash_kernel<<<g, 256, FLASH_SMEM>>>(Qb, Kb, Vb, Ab);
    }
    // split attention output, then output projection on HMMA
    {
        int n4 = S_LEN * NQD / 4;
        split_kernel<<<(n4 + 255) / 256, 256>>>(Ab, ah, al, n4);
        dim3 go(HIDDIM / BN, S_LEN / BM);
        gemm_hmma<<<go, 256, GEMM_SMEM>>>(ah, al, woh, wol, out, HIDDIM);
    }
}

// round 5
// speedup vs baseline: 3.2993x; 2.7390x over previous
#include <cuda_runtime.h>
#include <cuda_bf16.h>
#include <math.h>
#include <stdint.h>

#define S_LEN 2048
#define HIDDIM 2048
#define NH 16
#define NKV 4
#define HD 128
#define NQD (NH*HD)    // 2048
#define NKD (NKV*HD)   // 512
#define WIN 1024
#define KDIM 2048

// ---------------- scratch ---------------------------------------------------
__device__ float g_Q[S_LEN * NQD];
__device__ float g_K[S_LEN * NKD];
__device__ float g_V[S_LEN * NKD];
__device__ float g_A[S_LEN * NQD];

__device__ __nv_bfloat16 g_xh[S_LEN * HIDDIM], g_xl[S_LEN * HIDDIM];
__device__ __nv_bfloat16 g_wqh[NQD * HIDDIM],  g_wql[NQD * HIDDIM];
__device__ __nv_bfloat16 g_wkh[NKD * HIDDIM],  g_wkl[NKD * HIDDIM];
__device__ __nv_bfloat16 g_wvh[NKD * HIDDIM],  g_wvl[NKD * HIDDIM];
__device__ __nv_bfloat16 g_woh[HIDDIM * NQD],  g_wol[HIDDIM * NQD];
__device__ __nv_bfloat16 g_ah[S_LEN * NQD],    g_al[S_LEN * NQD];

__device__ __nv_bfloat16 g_Qh[S_LEN * NQD], g_Ql[S_LEN * NQD];
__device__ __nv_bfloat16 g_Kh[S_LEN * NKD], g_Kl[S_LEN * NKD];
__device__ __nv_bfloat16 g_Vh[S_LEN * NKD], g_Vl[S_LEN * NKD];

// ---------------- helpers ---------------------------------------------------
__device__ __forceinline__ uint32_t smem_u32(const void* p) {
    uint32_t a;
    asm("{ .reg .u64 t; cvta.to.shared.u64 t, %1; cvt.u32.u64 %0, t; }"
        : "=r"(a) : "l"(p));
    return a;
}

__device__ __forceinline__ void cp16(uint32_t dst, const void* src) {
    asm volatile("cp.async.cg.shared.global [%0], [%1], 16;" :: "r"(dst), "l"(src));
}

__device__ __forceinline__ void mma16816(float* c, const uint32_t* a,
                                         uint32_t b0, uint32_t b1) {
    asm volatile(
        "mma.sync.aligned.m16n8k16.row.col.f32.bf16.bf16.f32 "
        "{%0,%1,%2,%3}, {%4,%5,%6,%7}, {%8,%9}, {%0,%1,%2,%3};"
        : "+f"(c[0]), "+f"(c[1]), "+f"(c[2]), "+f"(c[3])
        : "r"(a[0]), "r"(a[1]), "r"(a[2]), "r"(a[3]), "r"(b0), "r"(b1));
}

__device__ __forceinline__ void ldsm4t(uint32_t& r0, uint32_t& r1,
                                       uint32_t& r2, uint32_t& r3, uint32_t addr) {
    asm volatile("ldmatrix.sync.aligned.m8n8.x4.trans.shared.b16 {%0,%1,%2,%3}, [%4];"
                 : "=r"(r0), "=r"(r1), "=r"(r2), "=r"(r3) : "r"(addr));
}

__device__ __forceinline__ uint32_t pack_bf2(float x, float y) {
    __nv_bfloat16 hx = __float2bfloat16(x), hy = __float2bfloat16(y);
    return (uint32_t)__bfloat16_as_ushort(hx) |
           ((uint32_t)__bfloat16_as_ushort(hy) << 16);
}

// ---------------------------------------------------------------------------
// fused split: x, wq, wk, wv, wo -> bf16 hi/lo   (float4 granularity)
// ---------------------------------------------------------------------------
__device__ __forceinline__ void split4(const float* __restrict__ in,
                                       __nv_bfloat16* __restrict__ hi,
                                       __nv_bfloat16* __restrict__ lo, int i) {
    float4 v = ((const float4*)in)[i];
    __nv_bfloat16 h0 = __float2bfloat16(v.x);
    __nv_bfloat16 h1 = __float2bfloat16(v.y);
    __nv_bfloat16 h2 = __float2bfloat16(v.z);
    __nv_bfloat16 h3 = __float2bfloat16(v.w);
    __nv_bfloat16 l0 = __float2bfloat16(v.x - __bfloat162float(h0));
    __nv_bfloat16 l1 = __float2bfloat16(v.y - __bfloat162float(h1));
    __nv_bfloat16 l2 = __float2bfloat16(v.z - __bfloat162float(h2));
    __nv_bfloat16 l3 = __float2bfloat16(v.w - __bfloat162float(h3));
    uint2 hv, lv;
    hv.x = (uint32_t)__bfloat16_as_ushort(h0) | ((uint32_t)__bfloat16_as_ushort(h1) << 16);
    hv.y = (uint32_t)__bfloat16_as_ushort(h2) | ((uint32_t)__bfloat16_as_ushort(h3) << 16);
    lv.x = (uint32_t)__bfloat16_as_ushort(l0) | ((uint32_t)__bfloat16_as_ushort(l1) << 16);
    lv.y = (uint32_t)__bfloat16_as_ushort(l2) | ((uint32_t)__bfloat16_as_ushort(l3) << 16);
    ((uint2*)hi)[i] = hv;
    ((uint2*)lo)[i] = lv;
}

__global__ void split_kernel(const float* __restrict__ in,
                             __nv_bfloat16* __restrict__ hi,
                             __nv_bfloat16* __restrict__ lo, int n4) {
    int i = blockIdx.x * blockDim.x + threadIdx.x;
    if (i >= n4) return;
    split4(in, hi, lo, i);
}

#define C1 1048576   // x      (S*HID/4)
#define C2 2097152   // + wq
#define C3 2359296   // + wk
#define C4 2621440   // + wv
#define C5 3670016   // + wo

__global__ void splitAll_kernel(const float* __restrict__ x,
                                const float* __restrict__ wq,
                                const float* __restrict__ wk,
                                const float* __restrict__ wv,
                                const float* __restrict__ wo,
                                __nv_bfloat16* xh, __nv_bfloat16* xl,
                                __nv_bfloat16* wqh, __nv_bfloat16* wql,
                                __nv_bfloat16* wkh, __nv_bfloat16* wkl,
                                __nv_bfloat16* wvh, __nv_bfloat16* wvl,
                                __nv_bfloat16* woh, __nv_bfloat16* wol) {
    int i = blockIdx.x * blockDim.x + threadIdx.x;
    if (i < C1)      split4(x,  xh,  xl,  i);
    else if (i < C2) split4(wq, wqh, wql, i - C1);
    else if (i < C3) split4(wk, wkh, wkl, i - C2);
    else if (i < C4) split4(wv, wvh, wvl, i - C3);
    else if (i < C5) split4(wo, woh, wol, i - C4);
}

// ---------------------------------------------------------------------------
// HMMA GEMM core: C[M,N] = Ah*Bh^T + Ah*Bl^T + Al*Bh^T (NT, K=2048, fp32 acc)
// BM=BN=128, BK=32, 256 threads, warp tile 32x64, 2-stage cp.async.
// ---------------------------------------------------------------------------
#define BM 128
#define BN 128
#define BKG 32
#define ASTRIDE 40
#define TILE_B (128 * ASTRIDE * 2)
#define STAGE_B (4 * TILE_B)
#define GEMM_SMEM (2 * STAGE_B)
#define NST (KDIM / BKG)

__device__ __forceinline__ void gemm_body(const __nv_bfloat16* __restrict__ Ahg,
                                          const __nv_bfloat16* __restrict__ Alg,
                                          const __nv_bfloat16* __restrict__ Bhg,
                                          const __nv_bfloat16* __restrict__ Blg,
                                          float* __restrict__ C, int N,
                                          int mBase, int nBase, char* smg) {
    const int t = threadIdx.x;
    const int wid = t >> 5, lane = t & 31;
    const int g = lane >> 2, tq = lane & 3;
    const int wm = wid & 3, wn = wid >> 2;

    float acc[2][8][4] = {};

    const int chunk = t & 3;
    const int row0 = t >> 2;

    const __nv_bfloat16* srcs[4] = {Ahg, Alg, Bhg, Blg};
    const int tb[4] = {mBase, mBase, nBase, nBase};

    {
        char* base = smg;
#pragma unroll
        for (int ti = 0; ti < 4; ti++)
#pragma unroll
            for (int rr = 0; rr < 2; rr++) {
                int r = row0 + rr * 64;
                uint32_t dst = smem_u32(base + ti * TILE_B + (r * ASTRIDE + chunk * 8) * 2);
                cp16(dst, srcs[ti] + (size_t)(tb[ti] + r) * KDIM + chunk * 8);
            }
        asm volatile("cp.async.commit_group;");
    }

    for (int s = 0; s < NST; s++) {
        if (s + 1 < NST) {
            char* base = smg + ((s + 1) & 1) * STAGE_B;
            int k0 = (s + 1) * BKG;
#pragma unroll
            for (int ti = 0; ti < 4; ti++)
#pragma unroll
                for (int rr = 0; rr < 2; rr++) {
                    int r = row0 + rr * 64;
                    uint32_t dst = smem_u32(base + ti * TILE_B + (r * ASTRIDE + chunk * 8) * 2);
                    cp16(dst, srcs[ti] + (size_t)(tb[ti] + r) * KDIM + k0 + chunk * 8);
                }
            asm volatile("cp.async.commit_group;");
            asm volatile("cp.async.wait_group 1;");
        } else {
            asm volatile("cp.async.wait_group 0;");
        }
        __syncthreads();

        const char* base = smg + (s & 1) * STAGE_B;
        const char* pAh = base;
        const char* pAl = base + TILE_B;
        const char* pBh = base + 2 * TILE_B;
        const char* pBl = base + 3 * TILE_B;

#pragma unroll
        for (int ks = 0; ks < 2; ks++) {
            const int kk = ks * 16;
            uint32_t ah[2][4], al[2][4];
#pragma unroll
            for (int mf = 0; mf < 2; mf++) {
                int r = wm * 32 + mf * 16 + g;
                int off = (r * ASTRIDE + kk + 2 * tq) * 2;
                ah[mf][0] = *(const uint32_t*)(pAh + off);
                ah[mf][1] = *(const uint32_t*)(pAh + off + 8 * ASTRIDE * 2);
                ah[mf][2] = *(const uint32_t*)(pAh + off + 16);
                ah[mf][3] = *(const uint32_t*)(pAh + off + 8 * ASTRIDE * 2 + 16);
                al[mf][0] = *(const uint32_t*)(pAl + off);
                al[mf][1] = *(const uint32_t*)(pAl + off + 8 * ASTRIDE * 2);
                al[mf][2] = *(const uint32_t*)(pAl + off + 16);
                al[mf][3] = *(const uint32_t*)(pAl + off + 8 * ASTRIDE * 2 + 16);
            }
#pragma unroll
            for (int nf = 0; nf < 8; nf++) {
                int rn = wn * 64 + nf * 8 + g;
                int off = (rn * ASTRIDE + kk + 2 * tq) * 2;
                uint32_t bh0 = *(const uint32_t*)(pBh + off);
                uint32_t bh1 = *(const uint32_t*)(pBh + off + 16);
                uint32_t bl0 = *(const uint32_t*)(pBl + off);
                uint32_t bl1 = *(const uint32_t*)(pBl + off + 16);
#pragma unroll
                for (int mf = 0; mf < 2; mf++) {
                    mma16816(acc[mf][nf], ah[mf], bh0, bh1);
                    mma16816(acc[mf][nf], ah[mf], bl0, bl1);
                    mma16816(acc[mf][nf], al[mf], bh0, bh1);
                }
            }
        }
        __syncthreads();
    }

#pragma unroll
    for (int mf = 0; mf < 2; mf++) {
        int row = mBase + wm * 32 + mf * 16 + g;
#pragma unroll
        for (int nf = 0; nf < 8; nf++) {
            int col = nBase + wn * 64 + nf * 8 + 2 * tq;
            *(float2*)(C + (size_t)row * N + col) =
                make_float2(acc[mf][nf][0], acc[mf][nf][1]);
            *(float2*)(C + (size_t)(row + 8) * N + col) =
                make_float2(acc[mf][nf][2], acc[mf][nf][3]);
        }
    }
}

// fused QKV projection: grid.x = 24 column blocks (16 Q, 4 K, 4 V)
__global__ __launch_bounds__(256) void gemm_qkv(const __nv_bfloat16* __restrict__ xh,
                                                const __nv_bfloat16* __restrict__ xl,
                                                const __nv_bfloat16* __restrict__ wqh,
                                                const __nv_bfloat16* __restrict__ wql,
                                                const __nv_bfloat16* __restrict__ wkh,
                                                const __nv_bfloat16* __restrict__ wkl,
                                                const __nv_bfloat16* __restrict__ wvh,
                                                const __nv_bfloat16* __restrict__ wvl,
                                                float* __restrict__ Q,
                                                float* __restrict__ K,
                                                float* __restrict__ V) {
    extern __shared__ char smg[];
    int bx = blockIdx.x;
    int mBase = blockIdx.y * BM;
    const __nv_bfloat16 *Bh, *Bl;
    float* C;
    int N, nb;
    if (bx < 16)      { Bh = wqh; Bl = wql; C = Q; N = NQD; nb = bx; }
    else if (bx < 20) { Bh = wkh; Bl = wkl; C = K; N = NKD; nb = bx - 16; }
    else              { Bh = wvh; Bl = wvl; C = V; N = NKD; nb = bx - 20; }
    gemm_body(xh, xl, Bh, Bl, C, N, mBase, nb * BN, smg);
}

__global__ __launch_bounds__(256) void gemm_plain(const __nv_bfloat16* __restrict__ Ah,
                                                  const __nv_bfloat16* __restrict__ Al,
                                                  const __nv_bfloat16* __restrict__ Bh,
                                                  const __nv_bfloat16* __restrict__ Bl,
                                                  float* __restrict__ C, int N) {
    extern __shared__ char smg[];
    gemm_body(Ah, Al, Bh, Bl, C, N, blockIdx.y * BM, blockIdx.x * BN, smg);
}

// ---------------------------------------------------------------------------
// fused RoPE for Q and K: reads fp32, writes bf16 hi/lo
// hh in [0,16) -> Q head hh;  hh in [16,20) -> K head hh-16
// ---------------------------------------------------------------------------
__global__ void ropeQK_kernel(const float* __restrict__ Q, const float* __restrict__ K,
                              __nv_bfloat16* __restrict__ Qh, __nv_bfloat16* __restrict__ Ql,
                              __nv_bfloat16* __restrict__ Kh, __nv_bfloat16* __restrict__ Kl) {
    int idx = blockIdx.x * blockDim.x + threadIdx.x;
    int total = S_LEN * 20 * (HD / 2);
    if (idx >= total) return;
    int j = idx & 63;
    int rest = idx >> 6;
    int hh = rest % 20;
    int s = rest / 20;

    float invf = expf(-logf(10000.0f) * (float)(2 * j) / (float)HD);
    float ang = (float)s * invf;
    float c = cosf(ang), sn = sinf(ang);

    const float* src;
    __nv_bfloat16 *dh, *dl;
    size_t base;
    if (hh < 16) { src = Q; dh = Qh; dl = Ql; base = (size_t)s * NQD + hh * HD; }
    else         { src = K; dh = Kh; dl = Kl; base = (size_t)s * NKD + (hh - 16) * HD; }

    float a = src[base + j], b = src[base + j + 64];
    float ra = a * c - b * sn;
    float rb = b * c + a * sn;
    __nv_bfloat16 rah = __float2bfloat16(ra);
    __nv_bfloat16 rbh = __float2bfloat16(rb);
    dh[base + j]      = rah;
    dh[base + j + 64] = rbh;
    dl[base + j]      = __float2bfloat16(ra - __bfloat162float(rah));
    dl[base + j + 64] = __float2bfloat16(rb - __bfloat162float(rbh));
}

// ---------------------------------------------------------------------------
// HMMA flash attention. BQ=128 q-rows per CTA, 64 keys per iter, HD=128.
// 8 warps, warp w owns q rows [16w, 16w+16). bf16 3-term everywhere.
// smem (halves, stride 136/row): Qh, Ql [128][136]; 2 stages x {Kh,Kl,Vh,Vl}[64][136]
// ---------------------------------------------------------------------------
#define FQ 128
#define FKK 64
#define FSTR 136                         // halves per row
#define FROWB (FSTR * 2)                 // 272 bytes per row
#define QT_B (FQ * FROWB)                // 34816 per Q tile
#define KT_B (FKK * FROWB)               // 17408 per KV tile
#define FSTAGE_B (4 * KT_B)              // 69632
#define FSTAGE0 (2 * QT_B)               // 69632
#define FLASH_SMEM (FSTAGE0 + 2 * FSTAGE_B)   // 208896

__global__ __launch_bounds__(256, 1) void flash_hmma(
        const __nv_bfloat16* __restrict__ Qh, const __nv_bfloat16* __restrict__ Ql,
        const __nv_bfloat16* __restrict__ Kh, const __nv_bfloat16* __restrict__ Kl,
        const __nv_bfloat16* __restrict__ Vh, const __nv_bfloat16* __restrict__ Vl,
        float* __restrict__ O) {
    extern __shared__ char sm[];
    const int tid = threadIdx.x;
    const int wid = tid >> 5, lane = tid & 31;
    const int g = lane >> 2, tq = lane & 3;
    const int qt = blockIdx.x;
    const int h = blockIdx.y;
    const int kvh = h >> 2;
    const int q0 = qt * FQ;
    const int rw = wid * 16;
    const float sc = 0.08838834764831845f;

    // ---- issue Q load + first KV stage ----
    {
#pragma unroll
        for (int i = 0; i < 16; i++) {
            int id = tid + i * 256;               // 4096 chunks
            int tile = id >> 11;                  // 0=hi 1=lo
            int rem = id & 2047;
            int r = rem >> 4, c = rem & 15;
            uint32_t dst = smem_u32(sm + tile * QT_B + r * FROWB + c * 16);
            const __nv_bfloat16* src = (tile == 0 ? Qh : Ql) +
                (size_t)(q0 + r) * NQD + h * HD + c * 8;
            cp16(dst, src);
        }
    }
    int kt_begin = q0 - (WIN - 1);
    kt_begin = (kt_begin < 0) ? 0 : (kt_begin >> 6);
    const int kt_end = (q0 + FQ - 1) >> 6;

    const __nv_bfloat16* kvsrc[4] = {Kh, Kl, Vh, Vl};
    {
        int k0 = kt_begin * FKK;
#pragma unroll
        for (int i = 0; i < 16; i++) {
            int id = tid + i * 256;               // 4096 chunks
            int tile = id >> 10;
            int rem = id & 1023;
            int r = rem >> 4, c = rem & 15;
            uint32_t dst = smem_u32(sm + FSTAGE0 + tile * KT_B + r * FROWB + c * 16);
            cp16(dst, kvsrc[tile] + (size_t)(k0 + r) * NKD + kvh * HD + c * 8);
        }
        asm volatile("cp.async.commit_group;");
    }

    float oacc[16][4] = {};
    float m0 = -1e30f, m1 = -1e30f, l0 = 0.0f, l1 = 0.0f;

    for (int kt = kt_begin; kt <= kt_end; kt++) {
        const int buf = (kt - kt_begin) & 1;
        if (kt < kt_end) {
            int k0 = (kt + 1) * FKK;
            char* base = sm + FSTAGE0 + (buf ^ 1) * FSTAGE_B;
#pragma unroll
            for (int i = 0; i < 16; i++) {
                int id = tid + i * 256;
                int tile = id >> 10;
                int rem = id & 1023;
                int r = rem >> 4, c = rem & 15;
                uint32_t dst = smem_u32(base + tile * KT_B + r * FROWB + c * 16);
                cp16(dst, kvsrc[tile] + (size_t)(k0 + r) * NKD + kvh * HD + c * 8);
            }
            asm volatile("cp.async.commit_group;");
            asm volatile("cp.async.wait_group 1;");
        } else {
            asm volatile("cp.async.wait_group 0;");
        }
        __syncthreads();

        const char* stage = sm + FSTAGE0 + buf * FSTAGE_B;
        const char* pKh = stage;
        const char* pKl = stage + KT_B;
        const int k0 = kt * FKK;

        // ---- S = Q K^T (bf16 3-term) ----
        float sacc[8][4] = {};
#pragma unroll
        for (int ks = 0; ks < 8; ks++) {
            uint32_t qh[4], ql[4];
            int aoff = ((rw + g) * FSTR + ks * 16 + 2 * tq) * 2;
            qh[0] = *(const uint32_t*)(sm + aoff);
            qh[1] = *(const uint32_t*)(sm + aoff + 8 * FROWB);
            qh[2] = *(const uint32_t*)(sm + aoff + 16);
            qh[3] = *(const uint32_t*)(sm + aoff + 8 * FROWB + 16);
            ql[0] = *(const uint32_t*)(sm + QT_B + aoff);
            ql[1] = *(const uint32_t*)(sm + QT_B + aoff + 8 * FROWB);
            ql[2] = *(const uint32_t*)(sm + QT_B + aoff + 16);
            ql[3] = *(const uint32_t*)(sm + QT_B + aoff + 8 * FROWB + 16);
#pragma unroll
            for (int nf = 0; nf < 8; nf++) {
                int boff = ((nf * 8 + g) * FSTR + ks * 16 + 2 * tq) * 2;
                uint32_t bh0 = *(const uint32_t*)(pKh + boff);
                uint32_t bh1 = *(const uint32_t*)(pKh + boff + 16);
                uint32_t bl0 = *(const uint32_t*)(pKl + boff);
                uint32_t bl1 = *(const uint32_t*)(pKl + boff + 16);
                mma16816(sacc[nf], qh, bh0, bh1);
                mma16816(sacc[nf], qh, bl0, bl1);
                mma16816(sacc[nf], ql, bh0, bh1);
            }
        }

        // ---- scale + sliding-window causal mask ----
        const int row0 = q0 + rw + g, row1 = row0 + 8;
#pragma unroll
        for (int nf = 0; nf < 8; nf++) {
            int colb = k0 + nf * 8 + 2 * tq;
#pragma unroll
            for (int c = 0; c < 4; c++) {
                int col = colb + (c & 1);
                int row = (c < 2) ? row0 : row1;
                bool ok = (col <= row) && (row - col < WIN);
                sacc[nf][c] = ok ? sacc[nf][c] * sc : -1e9f;
            }
        }

        // ---- online softmax ----
        float mx0 = -1e30f, mx1 = -1e30f;
#pragma unroll
        for (int nf = 0; nf < 8; nf++) {
            mx0 = fmaxf(mx0, fmaxf(sacc[nf][0], sacc[nf][1]));
            mx1 = fmaxf(mx1, fmaxf(sacc[nf][2], sacc[nf][3]));
        }
        mx0 = fmaxf(mx0, __shfl_xor_sync(0xffffffffu, mx0, 1));
        mx0 = fmaxf(mx0, __shfl_xor_sync(0xffffffffu, mx0, 2));
        mx1 = fmaxf(mx1, __shfl_xor_sync(0xffffffffu, mx1, 1));
        mx1 = fmaxf(mx1, __shfl_xor_sync(0xffffffffu, mx1, 2));
        float mn0 = fmaxf(m0, mx0), mn1 = fmaxf(m1, mx1);
        float al0 = __expf(m0 - mn0), al1 = __expf(m1 - mn1);
        m0 = mn0; m1 = mn1;

        float sum0 = 0.0f, sum1 = 0.0f;
#pragma unroll
        for (int nf = 0; nf < 8; nf++) {
            sacc[nf][0] = __expf(sacc[nf][0] - mn0);
            sacc[nf][1] = __expf(sacc[nf][1] - mn0);
            sacc[nf][2] = __expf(sacc[nf][2] - mn1);
            sacc[nf][3] = __expf(sacc[nf][3] - mn1);
            sum0 += sacc[nf][0] + sacc[nf][1];
            sum1 += sacc[nf][2] + sacc[nf][3];
        }
        sum0 += __shfl_xor_sync(0xffffffffu, sum0, 1);
        sum0 += __shfl_xor_sync(0xffffffffu, sum0, 2);
        sum1 += __shfl_xor_sync(0xffffffffu, sum1, 1);
        sum1 += __shfl_xor_sync(0xffffffffu, sum1, 2);
        l0 = l0 * al0 + sum0;
        l1 = l1 * al1 + sum1;

        // ---- rescale O ----
#pragma unroll
        for (int on = 0; on < 16; on++) {
            oacc[on][0] *= al0; oacc[on][1] *= al0;
            oacc[on][2] *= al1; oacc[on][3] *= al1;
        }

        // ---- pack P (bf16 hi/lo) into A-operand frags ----
        uint32_t pah[4][4], pal[4][4];
#pragma unroll
        for (int j = 0; j < 4; j++) {
#pragma unroll
            for (int q = 0; q < 4; q++) {
                int nf = 2 * j + (q >> 1);
                float x = sacc[nf][(q & 1) * 2 + 0];   // wait: careful ordering below
                float y = sacc[nf][(q & 1) * 2 + 1];
                // q=0 -> nf=2j,(c0,c1); q=1 -> nf=2j,(c2,c3);
                // q=2 -> nf=2j+1,(c0,c1); q=3 -> nf=2j+1,(c2,c3)
                __nv_bfloat16 hx = __float2bfloat16(x);
                __nv_bfloat16 hy = __float2bfloat16(y);
                pah[j][q] = (uint32_t)__bfloat16_as_ushort(hx) |
                            ((uint32_t)__bfloat16_as_ushort(hy) << 16);
                pal[j][q] = pack_bf2(x - __bfloat162float(hx),
                                     y - __bfloat162float(hy));
            }
        }

        // ---- O += P V (bf16 3-term), V frags via ldmatrix.trans ----
        const char* pVh = stage + 2 * KT_B;
        const char* pVl = stage + 3 * KT_B;
#pragma unroll
        for (int j = 0; j < 4; j++) {
            int krow = j * 16 + (lane & 7) + ((lane >> 3) & 1) * 8;
#pragma unroll
            for (int vb = 0; vb < 8; vb++) {
                int ncol = vb * 16 + (lane >> 4) * 8;
                uint32_t vaddr = smem_u32(pVh + (krow * FSTR + ncol) * 2);
                uint32_t waddr = smem_u32(pVl + (krow * FSTR + ncol) * 2);
                uint32_t v0, v1, v2, v3, w0, w1, w2, w3;
                ldsm4t(v0, v1, v2, v3, vaddr);
                ldsm4t(w0, w1, w2, w3, waddr);
                mma16816(oacc[2 * vb],     pah[j], v0, v1);
                mma16816(oacc[2 * vb],     pal[j], v0, v1);
                mma16816(oacc[2 * vb],     pah[j], w0, w1);
                mma16816(oacc[2 * vb + 1], pah[j], v2, v3);
                mma16816(oacc[2 * vb + 1], pal[j], v2, v3);
                mma16816(oacc[2 * vb + 1], pah[j], w2, w3);
            }
        }
        __syncthreads();
    }

    // ---- finalize ----
    float inv0 = 1.0f / l0, inv1 = 1.0f / l1;
    const int row0 = q0 + rw + g, row1 = row0 + 8;
#pragma unroll
    for (int on = 0; on < 16; on++) {
        int col = h * HD + on * 8 + 2 * tq;
        *(float2*)(O + (size_t)row0 * NQD + col) =
            make_float2(oacc[on][0] * inv0, oacc[on][1] * inv0);
        *(float2*)(O + (size_t)row1 * NQD + col) =
            make_float2(oacc[on][2] * inv1, oacc[on][3] * inv1);
    }
}

// ---------------------------------------------------------------------------
extern "C" void kernel_launch(void* const* d_in, const int* in_sizes, int n_in,
                              void* d_out, int out_size) {
    const float* x  = (const float*)d_in[0];
    // d_in[1] = attention_mask (deterministic sliding-window; computed analytically)
    const float* wq = (const float*)d_in[2];
    const float* wk = (const float*)d_in[3];
    const float* wv = (const float*)d_in[4];
    const float* wo = (const float*)d_in[5];
    float* out = (float*)d_out;

    float *Qb, *Kb, *Vb, *Ab;
    cudaGetSymbolAddress((void**)&Qb, g_Q);
    cudaGetSymbolAddress((void**)&Kb, g_K);
    cudaGetSymbolAddress((void**)&Vb, g_V);
    cudaGetSymbolAddress((void**)&Ab, g_A);
    __nv_bfloat16 *xh, *xl, *wqh, *wql, *wkh, *wkl, *wvh, *wvl, *woh, *wol, *ah, *al;
    __nv_bfloat16 *qhh, *qll, *khh, *kll, *vhh, *vll;
    cudaGetSymbolAddress((void**)&xh, g_xh);   cudaGetSymbolAddress((void**)&xl, g_xl);
    cudaGetSymbolAddress((void**)&wqh, g_wqh); cudaGetSymbolAddress((void**)&wql, g_wql);
    cudaGetSymbolAddress((void**)&wkh, g_wkh); cudaGetSymbolAddress((void**)&wkl, g_wkl);
    cudaGetSymbolAddress((void**)&wvh, g_wvh); cudaGetSymbolAddress((void**)&wvl, g_wvl);
    cudaGetSymbolAddress((void**)&woh, g_woh); cudaGetSymbolAddress((void**)&wol, g_wol);
    cudaGetSymbolAddress((void**)&ah, g_ah);   cudaGetSymbolAddress((void**)&al, g_al);
    cudaGetSymbolAddress((void**)&qhh, g_Qh);  cudaGetSymbolAddress((void**)&qll, g_Ql);
    cudaGetSymbolAddress((void**)&khh, g_Kh);  cudaGetSymbolAddress((void**)&kll, g_Kl);
    cudaGetSymbolAddress((void**)&vhh, g_Vh);  cudaGetSymbolAddress((void**)&vll, g_Vl);

    static bool attr_set = false;
    if (!attr_set) {
        cudaFuncSetAttribute(gemm_qkv, cudaFuncAttributeMaxDynamicSharedMemorySize,
                             (int)GEMM_SMEM);
        cudaFuncSetAttribute(gemm_plain, cudaFuncAttributeMaxDynamicSharedMemorySize,
                             (int)GEMM_SMEM);
        cudaFuncSetAttribute(flash_hmma, cudaFuncAttributeMaxDynamicSharedMemorySize,
                             (int)FLASH_SMEM);
        attr_set = true;
    }

    // 1. fused split of x + all weights
    splitAll_kernel<<<C5 / 256, 256>>>(x, wq, wk, wv, wo,
                                       xh, xl, wqh, wql, wkh, wkl, wvh, wvl, woh, wol);
    // 2. fused QKV projection
    {
        dim3 gq(24, S_LEN / BM);
        gemm_qkv<<<gq, 256, GEMM_SMEM>>>(xh, xl, wqh, wql, wkh, wkl, wvh, wvl,
                                         Qb, Kb, Vb);
    }
    // 3. split V -> bf16 hi/lo
    split_kernel<<<(S_LEN * NKD / 4 + 255) / 256, 256>>>(Vb, vhh, vll, S_LEN * NKD / 4);
    // 4. fused RoPE Q+K -> bf16 hi/lo
    {
        int tot = S_LEN * 20 * (HD / 2);
        ropeQK_kernel<<<(tot + 255) / 256, 256>>>(Qb, Kb, qhh, qll, khh, kll);
    }
    // 5. HMMA flash attention
    {
        dim3 g(S_LEN / FQ, NH);
        flash_hmma<<<g, 256, FLASH_SMEM>>>(qhh, qll, khh, kll, vhh, vll, Ab);
    }
    // 6. split attention output
    split_kernel<<<(S_LEN * NQD / 4 + 255) / 256, 256>>>(Ab, ah, al, S_LEN * NQD / 4);
    // 7. output projection
    {
        dim3 go(HIDDIM / BN, S_LEN / BM);
        gemm_plain<<<go, 256, GEMM_SMEM>>>(ah, al, woh, wol, out, HIDDIM);
    }
}

// round 6
// speedup vs baseline: 3.4826x; 1.0556x over previous
#include <cuda_runtime.h>
#include <cuda_bf16.h>
#include <math.h>
#include <stdint.h>

#define S_LEN 2048
#define HIDDIM 2048
#define NH 16
#define NKV 4
#define HD 128
#define NQD (NH*HD)    // 2048
#define NKD (NKV*HD)   // 512
#define WIN 1024
#define KDIM 2048

// ---------------- scratch ---------------------------------------------------
__device__ float g_Q[S_LEN * NQD];
__device__ float g_K[S_LEN * NKD];
__device__ float g_V[S_LEN * NKD];

__device__ __nv_bfloat16 g_xh[S_LEN * HIDDIM], g_xl[S_LEN * HIDDIM];
__device__ __nv_bfloat16 g_wqh[NQD * HIDDIM],  g_wql[NQD * HIDDIM];
__device__ __nv_bfloat16 g_wkh[NKD * HIDDIM],  g_wkl[NKD * HIDDIM];
__device__ __nv_bfloat16 g_wvh[NKD * HIDDIM],  g_wvl[NKD * HIDDIM];
__device__ __nv_bfloat16 g_woh[HIDDIM * NQD],  g_wol[HIDDIM * NQD];
__device__ __nv_bfloat16 g_ah[S_LEN * NQD],    g_al[S_LEN * NQD];

__device__ __nv_bfloat16 g_Qh[S_LEN * NQD], g_Ql[S_LEN * NQD];
__device__ __nv_bfloat16 g_Kh[S_LEN * NKD], g_Kl[S_LEN * NKD];
__device__ __nv_bfloat16 g_Vh[S_LEN * NKD], g_Vl[S_LEN * NKD];

// ---------------- helpers ---------------------------------------------------
__device__ __forceinline__ uint32_t smem_u32(const void* p) {
    uint32_t a;
    asm("{ .reg .u64 t; cvta.to.shared.u64 t, %1; cvt.u32.u64 %0, t; }"
        : "=r"(a) : "l"(p));
    return a;
}

__device__ __forceinline__ void cp16(uint32_t dst, const void* src) {
    asm volatile("cp.async.cg.shared.global [%0], [%1], 16;" :: "r"(dst), "l"(src));
}

__device__ __forceinline__ void mma16816(float* c, const uint32_t* a,
                                         uint32_t b0, uint32_t b1) {
    asm volatile(
        "mma.sync.aligned.m16n8k16.row.col.f32.bf16.bf16.f32 "
        "{%0,%1,%2,%3}, {%4,%5,%6,%7}, {%8,%9}, {%0,%1,%2,%3};"
        : "+f"(c[0]), "+f"(c[1]), "+f"(c[2]), "+f"(c[3])
        : "r"(a[0]), "r"(a[1]), "r"(a[2]), "r"(a[3]), "r"(b0), "r"(b1));
}

__device__ __forceinline__ void ldsm4t(uint32_t& r0, uint32_t& r1,
                                       uint32_t& r2, uint32_t& r3, uint32_t addr) {
    asm volatile("ldmatrix.sync.aligned.m8n8.x4.trans.shared.b16 {%0,%1,%2,%3}, [%4];"
                 : "=r"(r0), "=r"(r1), "=r"(r2), "=r"(r3) : "r"(addr));
}

__device__ __forceinline__ uint32_t pack_bf2(float x, float y) {
    __nv_bfloat16 hx = __float2bfloat16(x), hy = __float2bfloat16(y);
    return (uint32_t)__bfloat16_as_ushort(hx) |
           ((uint32_t)__bfloat16_as_ushort(hy) << 16);
}

// ---------------------------------------------------------------------------
// fused split: x, wq, wk, wv, wo -> bf16 hi/lo   (float4 granularity)
// ---------------------------------------------------------------------------
__device__ __forceinline__ void split4(const float* __restrict__ in,
                                       __nv_bfloat16* __restrict__ hi,
                                       __nv_bfloat16* __restrict__ lo, int i) {
    float4 v = ((const float4*)in)[i];
    __nv_bfloat16 h0 = __float2bfloat16(v.x);
    __nv_bfloat16 h1 = __float2bfloat16(v.y);
    __nv_bfloat16 h2 = __float2bfloat16(v.z);
    __nv_bfloat16 h3 = __float2bfloat16(v.w);
    __nv_bfloat16 l0 = __float2bfloat16(v.x - __bfloat162float(h0));
    __nv_bfloat16 l1 = __float2bfloat16(v.y - __bfloat162float(h1));
    __nv_bfloat16 l2 = __float2bfloat16(v.z - __bfloat162float(h2));
    __nv_bfloat16 l3 = __float2bfloat16(v.w - __bfloat162float(h3));
    uint2 hv, lv;
    hv.x = (uint32_t)__bfloat16_as_ushort(h0) | ((uint32_t)__bfloat16_as_ushort(h1) << 16);
    hv.y = (uint32_t)__bfloat16_as_ushort(h2) | ((uint32_t)__bfloat16_as_ushort(h3) << 16);
    lv.x = (uint32_t)__bfloat16_as_ushort(l0) | ((uint32_t)__bfloat16_as_ushort(l1) << 16);
    lv.y = (uint32_t)__bfloat16_as_ushort(l2) | ((uint32_t)__bfloat16_as_ushort(l3) << 16);
    ((uint2*)hi)[i] = hv;
    ((uint2*)lo)[i] = lv;
}

__global__ void split_kernel(const float* __restrict__ in,
                             __nv_bfloat16* __restrict__ hi,
                             __nv_bfloat16* __restrict__ lo, int n4) {
    int i = blockIdx.x * blockDim.x + threadIdx.x;
    if (i >= n4) return;
    split4(in, hi, lo, i);
}

#define C1 1048576   // x      (S*HID/4)
#define C2 2097152   // + wq
#define C3 2359296   // + wk
#define C4 2621440   // + wv
#define C5 3670016   // + wo

__global__ void splitAll_kernel(const float* __restrict__ x,
                                const float* __restrict__ wq,
                                const float* __restrict__ wk,
                                const float* __restrict__ wv,
                                const float* __restrict__ wo,
                                __nv_bfloat16* xh, __nv_bfloat16* xl,
                                __nv_bfloat16* wqh, __nv_bfloat16* wql,
                                __nv_bfloat16* wkh, __nv_bfloat16* wkl,
                                __nv_bfloat16* wvh, __nv_bfloat16* wvl,
                                __nv_bfloat16* woh, __nv_bfloat16* wol) {
    int i = blockIdx.x * blockDim.x + threadIdx.x;
    if (i < C1)      split4(x,  xh,  xl,  i);
    else if (i < C2) split4(wq, wqh, wql, i - C1);
    else if (i < C3) split4(wk, wkh, wkl, i - C2);
    else if (i < C4) split4(wv, wvh, wvl, i - C3);
    else if (i < C5) split4(wo, woh, wol, i - C4);
}

// ---------------------------------------------------------------------------
// HMMA GEMM core: C[M,N] = Ah*Bh^T + Ah*Bl^T + Al*Bh^T (NT, K=2048, fp32 acc)
// BM=BN=128, BK=32, 256 threads, warp tile 32x64, 2-stage cp.async, 2 CTAs/SM.
// ---------------------------------------------------------------------------
#define BM 128
#define BN 128
#define BKG 32
#define ASTRIDE 40
#define TILE_B (128 * ASTRIDE * 2)
#define STAGE_B (4 * TILE_B)
#define GEMM_SMEM (2 * STAGE_B)
#define NST (KDIM / BKG)

__device__ __forceinline__ void gemm_body(const __nv_bfloat16* __restrict__ Ahg,
                                          const __nv_bfloat16* __restrict__ Alg,
                                          const __nv_bfloat16* __restrict__ Bhg,
                                          const __nv_bfloat16* __restrict__ Blg,
                                          float* __restrict__ C, int N,
                                          int mBase, int nBase, char* smg) {
    const int t = threadIdx.x;
    const int wid = t >> 5, lane = t & 31;
    const int g = lane >> 2, tq = lane & 3;
    const int wm = wid & 3, wn = wid >> 2;

    float acc[2][8][4] = {};

    const int chunk = t & 3;
    const int row0 = t >> 2;

    const __nv_bfloat16* srcs[4] = {Ahg, Alg, Bhg, Blg};
    const int tb[4] = {mBase, mBase, nBase, nBase};

    {
        char* base = smg;
#pragma unroll
        for (int ti = 0; ti < 4; ti++)
#pragma unroll
            for (int rr = 0; rr < 2; rr++) {
                int r = row0 + rr * 64;
                uint32_t dst = smem_u32(base + ti * TILE_B + (r * ASTRIDE + chunk * 8) * 2);
                cp16(dst, srcs[ti] + (size_t)(tb[ti] + r) * KDIM + chunk * 8);
            }
        asm volatile("cp.async.commit_group;");
    }

    for (int s = 0; s < NST; s++) {
        if (s + 1 < NST) {
            char* base = smg + ((s + 1) & 1) * STAGE_B;
            int k0 = (s + 1) * BKG;
#pragma unroll
            for (int ti = 0; ti < 4; ti++)
#pragma unroll
                for (int rr = 0; rr < 2; rr++) {
                    int r = row0 + rr * 64;
                    uint32_t dst = smem_u32(base + ti * TILE_B + (r * ASTRIDE + chunk * 8) * 2);
                    cp16(dst, srcs[ti] + (size_t)(tb[ti] + r) * KDIM + k0 + chunk * 8);
                }
            asm volatile("cp.async.commit_group;");
            asm volatile("cp.async.wait_group 1;");
        } else {
            asm volatile("cp.async.wait_group 0;");
        }
        __syncthreads();

        const char* base = smg + (s & 1) * STAGE_B;
        const char* pAh = base;
        const char* pAl = base + TILE_B;
        const char* pBh = base + 2 * TILE_B;
        const char* pBl = base + 3 * TILE_B;

#pragma unroll
        for (int ks = 0; ks < 2; ks++) {
            const int kk = ks * 16;
            uint32_t ah[2][4], al[2][4];
#pragma unroll
            for (int mf = 0; mf < 2; mf++) {
                int r = wm * 32 + mf * 16 + g;
                int off = (r * ASTRIDE + kk + 2 * tq) * 2;
                ah[mf][0] = *(const uint32_t*)(pAh + off);
                ah[mf][1] = *(const uint32_t*)(pAh + off + 8 * ASTRIDE * 2);
                ah[mf][2] = *(const uint32_t*)(pAh + off + 16);
                ah[mf][3] = *(const uint32_t*)(pAh + off + 8 * ASTRIDE * 2 + 16);
                al[mf][0] = *(const uint32_t*)(pAl + off);
                al[mf][1] = *(const uint32_t*)(pAl + off + 8 * ASTRIDE * 2);
                al[mf][2] = *(const uint32_t*)(pAl + off + 16);
                al[mf][3] = *(const uint32_t*)(pAl + off + 8 * ASTRIDE * 2 + 16);
            }
#pragma unroll
            for (int nf = 0; nf < 8; nf++) {
                int rn = wn * 64 + nf * 8 + g;
                int off = (rn * ASTRIDE + kk + 2 * tq) * 2;
                uint32_t bh0 = *(const uint32_t*)(pBh + off);
                uint32_t bh1 = *(const uint32_t*)(pBh + off + 16);
                uint32_t bl0 = *(const uint32_t*)(pBl + off);
                uint32_t bl1 = *(const uint32_t*)(pBl + off + 16);
#pragma unroll
                for (int mf = 0; mf < 2; mf++) {
                    mma16816(acc[mf][nf], ah[mf], bh0, bh1);
                    mma16816(acc[mf][nf], ah[mf], bl0, bl1);
                    mma16816(acc[mf][nf], al[mf], bh0, bh1);
                }
            }
        }
        __syncthreads();
    }

#pragma unroll
    for (int mf = 0; mf < 2; mf++) {
        int row = mBase + wm * 32 + mf * 16 + g;
#pragma unroll
        for (int nf = 0; nf < 8; nf++) {
            int col = nBase + wn * 64 + nf * 8 + 2 * tq;
            *(float2*)(C + (size_t)row * N + col) =
                make_float2(acc[mf][nf][0], acc[mf][nf][1]);
            *(float2*)(C + (size_t)(row + 8) * N + col) =
                make_float2(acc[mf][nf][2], acc[mf][nf][3]);
        }
    }
}

// fused QKV projection: grid.x = 24 column blocks (16 Q, 4 K, 4 V)
__global__ __launch_bounds__(256, 2) void gemm_qkv(const __nv_bfloat16* __restrict__ xh,
                                                   const __nv_bfloat16* __restrict__ xl,
                                                   const __nv_bfloat16* __restrict__ wqh,
                                                   const __nv_bfloat16* __restrict__ wql,
                                                   const __nv_bfloat16* __restrict__ wkh,
                                                   const __nv_bfloat16* __restrict__ wkl,
                                                   const __nv_bfloat16* __restrict__ wvh,
                                                   const __nv_bfloat16* __restrict__ wvl,
                                                   float* __restrict__ Q,
                                                   float* __restrict__ K,
                                                   float* __restrict__ V) {
    extern __shared__ char smg[];
    int bx = blockIdx.x;
    int mBase = blockIdx.y * BM;
    const __nv_bfloat16 *Bh, *Bl;
    float* C;
    int N, nb;
    if (bx < 16)      { Bh = wqh; Bl = wql; C = Q; N = NQD; nb = bx; }
    else if (bx < 20) { Bh = wkh; Bl = wkl; C = K; N = NKD; nb = bx - 16; }
    else              { Bh = wvh; Bl = wvl; C = V; N = NKD; nb = bx - 20; }
    gemm_body(xh, xl, Bh, Bl, C, N, mBase, nb * BN, smg);
}

__global__ __launch_bounds__(256, 2) void gemm_plain(const __nv_bfloat16* __restrict__ Ah,
                                                     const __nv_bfloat16* __restrict__ Al,
                                                     const __nv_bfloat16* __restrict__ Bh,
                                                     const __nv_bfloat16* __restrict__ Bl,
                                                     float* __restrict__ C, int N) {
    extern __shared__ char smg[];
    gemm_body(Ah, Al, Bh, Bl, C, N, blockIdx.y * BM, blockIdx.x * BN, smg);
}

// ---------------------------------------------------------------------------
// fused RoPE for Q and K: reads fp32, writes bf16 hi/lo
// ---------------------------------------------------------------------------
__global__ void ropeQK_kernel(const float* __restrict__ Q, const float* __restrict__ K,
                              __nv_bfloat16* __restrict__ Qh, __nv_bfloat16* __restrict__ Ql,
                              __nv_bfloat16* __restrict__ Kh, __nv_bfloat16* __restrict__ Kl) {
    int idx = blockIdx.x * blockDim.x + threadIdx.x;
    int total = S_LEN * 20 * (HD / 2);
    if (idx >= total) return;
    int j = idx & 63;
    int rest = idx >> 6;
    int hh = rest % 20;
    int s = rest / 20;

    float invf = expf(-logf(10000.0f) * (float)(2 * j) / (float)HD);
    float ang = (float)s * invf;
    float c = cosf(ang), sn = sinf(ang);

    const float* src;
    __nv_bfloat16 *dh, *dl;
    size_t base;
    if (hh < 16) { src = Q; dh = Qh; dl = Ql; base = (size_t)s * NQD + hh * HD; }
    else         { src = K; dh = Kh; dl = Kl; base = (size_t)s * NKD + (hh - 16) * HD; }

    float a = src[base + j], b = src[base + j + 64];
    float ra = a * c - b * sn;
    float rb = b * c + a * sn;
    __nv_bfloat16 rah = __float2bfloat16(ra);
    __nv_bfloat16 rbh = __float2bfloat16(rb);
    dh[base + j]      = rah;
    dh[base + j + 64] = rbh;
    dl[base + j]      = __float2bfloat16(ra - __bfloat162float(rah));
    dl[base + j + 64] = __float2bfloat16(rb - __bfloat162float(rbh));
}

// ---------------------------------------------------------------------------
// HMMA flash attention. BQ=128 q-rows per CTA, 64 keys per iter, HD=128.
// 8 warps, warp w owns q rows [16w, 16w+16). bf16 3-term everywhere.
// Writes attention output directly as bf16 hi/lo (feeds out-projection).
// Heavy q-tiles scheduled first (descending qt) to balance waves.
// ---------------------------------------------------------------------------
#define FQ 128
#define FKK 64
#define FSTR 136
#define FROWB (FSTR * 2)
#define QT_B (FQ * FROWB)
#define KT_B (FKK * FROWB)
#define FSTAGE_B (4 * KT_B)
#define FSTAGE0 (2 * QT_B)
#define FLASH_SMEM (FSTAGE0 + 2 * FSTAGE_B)   // 208896

__global__ __launch_bounds__(256, 1) void flash_hmma(
        const __nv_bfloat16* __restrict__ Qh, const __nv_bfloat16* __restrict__ Ql,
        const __nv_bfloat16* __restrict__ Kh, const __nv_bfloat16* __restrict__ Kl,
        const __nv_bfloat16* __restrict__ Vh, const __nv_bfloat16* __restrict__ Vl,
        __nv_bfloat16* __restrict__ Oh, __nv_bfloat16* __restrict__ Ol) {
    extern __shared__ char sm[];
    const int tid = threadIdx.x;
    const int wid = tid >> 5, lane = tid & 31;
    const int g = lane >> 2, tq = lane & 3;
    const int qt = gridDim.x - 1 - blockIdx.x;   // heavy tiles first
    const int h = blockIdx.y;
    const int kvh = h >> 2;
    const int q0 = qt * FQ;
    const int rw = wid * 16;
    const float sc = 0.08838834764831845f;

    {
#pragma unroll
        for (int i = 0; i < 16; i++) {
            int id = tid + i * 256;
            int tile = id >> 11;
            int rem = id & 2047;
            int r = rem >> 4, c = rem & 15;
            uint32_t dst = smem_u32(sm + tile * QT_B + r * FROWB + c * 16);
            const __nv_bfloat16* src = (tile == 0 ? Qh : Ql) +
                (size_t)(q0 + r) * NQD + h * HD + c * 8;
            cp16(dst, src);
        }
    }
    int kt_begin = q0 - (WIN - 1);
    kt_begin = (kt_begin < 0) ? 0 : (kt_begin >> 6);
    const int kt_end = (q0 + FQ - 1) >> 6;

    const __nv_bfloat16* kvsrc[4] = {Kh, Kl, Vh, Vl};
    {
        int k0 = kt_begin * FKK;
#pragma unroll
        for (int i = 0; i < 16; i++) {
            int id = tid + i * 256;
            int tile = id >> 10;
            int rem = id & 1023;
            int r = rem >> 4, c = rem & 15;
            uint32_t dst = smem_u32(sm + FSTAGE0 + tile * KT_B + r * FROWB + c * 16);
            cp16(dst, kvsrc[tile] + (size_t)(k0 + r) * NKD + kvh * HD + c * 8);
        }
        asm volatile("cp.async.commit_group;");
    }

    float oacc[16][4] = {};
    float m0 = -1e30f, m1 = -1e30f, l0 = 0.0f, l1 = 0.0f;

    for (int kt = kt_begin; kt <= kt_end; kt++) {
        const int buf = (kt - kt_begin) & 1;
        if (kt < kt_end) {
            int k0 = (kt + 1) * FKK;
            char* base = sm + FSTAGE0 + (buf ^ 1) * FSTAGE_B;
#pragma unroll
            for (int i = 0; i < 16; i++) {
                int id = tid + i * 256;
                int tile = id >> 10;
                int rem = id & 1023;
                int r = rem >> 4, c = rem & 15;
                uint32_t dst = smem_u32(base + tile * KT_B + r * FROWB + c * 16);
                cp16(dst, kvsrc[tile] + (size_t)(k0 + r) * NKD + kvh * HD + c * 8);
            }
            asm volatile("cp.async.commit_group;");
            asm volatile("cp.async.wait_group 1;");
        } else {
            asm volatile("cp.async.wait_group 0;");
        }
        __syncthreads();

        const char* stage = sm + FSTAGE0 + buf * FSTAGE_B;
        const char* pKh = stage;
        const char* pKl = stage + KT_B;
        const int k0 = kt * FKK;

        // ---- S = Q K^T (bf16 3-term) ----
        float sacc[8][4] = {};
#pragma unroll
        for (int ks = 0; ks < 8; ks++) {
            uint32_t qh[4], ql[4];
            int aoff = ((rw + g) * FSTR + ks * 16 + 2 * tq) * 2;
            qh[0] = *(const uint32_t*)(sm + aoff);
            qh[1] = *(const uint32_t*)(sm + aoff + 8 * FROWB);
            qh[2] = *(const uint32_t*)(sm + aoff + 16);
            qh[3] = *(const uint32_t*)(sm + aoff + 8 * FROWB + 16);
            ql[0] = *(const uint32_t*)(sm + QT_B + aoff);
            ql[1] = *(const uint32_t*)(sm + QT_B + aoff + 8 * FROWB);
            ql[2] = *(const uint32_t*)(sm + QT_B + aoff + 16);
            ql[3] = *(const uint32_t*)(sm + QT_B + aoff + 8 * FROWB + 16);
#pragma unroll
            for (int nf = 0; nf < 8; nf++) {
                int boff = ((nf * 8 + g) * FSTR + ks * 16 + 2 * tq) * 2;
                uint32_t bh0 = *(const uint32_t*)(pKh + boff);
                uint32_t bh1 = *(const uint32_t*)(pKh + boff + 16);
                uint32_t bl0 = *(const uint32_t*)(pKl + boff);
                uint32_t bl1 = *(const uint32_t*)(pKl + boff + 16);
                mma16816(sacc[nf], qh, bh0, bh1);
                mma16816(sacc[nf], qh, bl0, bl1);
                mma16816(sacc[nf], ql, bh0, bh1);
            }
        }

        // ---- scale + sliding-window causal mask ----
        const int row0 = q0 + rw + g, row1 = row0 + 8;
#pragma unroll
        for (int nf = 0; nf < 8; nf++) {
            int colb = k0 + nf * 8 + 2 * tq;
#pragma unroll
            for (int c = 0; c < 4; c++) {
                int col = colb + (c & 1);
                int row = (c < 2) ? row0 : row1;
                bool ok = (col <= row) && (row - col < WIN);
                sacc[nf][c] = ok ? sacc[nf][c] * sc : -1e9f;
            }
        }

        // ---- online softmax ----
        float mx0 = -1e30f, mx1 = -1e30f;
#pragma unroll
        for (int nf = 0; nf < 8; nf++) {
            mx0 = fmaxf(mx0, fmaxf(sacc[nf][0], sacc[nf][1]));
            mx1 = fmaxf(mx1, fmaxf(sacc[nf][2], sacc[nf][3]));
        }
        mx0 = fmaxf(mx0, __shfl_xor_sync(0xffffffffu, mx0, 1));
        mx0 = fmaxf(mx0, __shfl_xor_sync(0xffffffffu, mx0, 2));
        mx1 = fmaxf(mx1, __shfl_xor_sync(0xffffffffu, mx1, 1));
        mx1 = fmaxf(mx1, __shfl_xor_sync(0xffffffffu, mx1, 2));
        float mn0 = fmaxf(m0, mx0), mn1 = fmaxf(m1, mx1);
        float al0 = __expf(m0 - mn0), al1 = __expf(m1 - mn1);
        m0 = mn0; m1 = mn1;

        float sum0 = 0.0f, sum1 = 0.0f;
#pragma unroll
        for (int nf = 0; nf < 8; nf++) {
            sacc[nf][0] = __expf(sacc[nf][0] - mn0);
            sacc[nf][1] = __expf(sacc[nf][1] - mn0);
            sacc[nf][2] = __expf(sacc[nf][2] - mn1);
            sacc[nf][3] = __expf(sacc[nf][3] - mn1);
            sum0 += sacc[nf][0] + sacc[nf][1];
            sum1 += sacc[nf][2] + sacc[nf][3];
        }
        sum0 += __shfl_xor_sync(0xffffffffu, sum0, 1);
        sum0 += __shfl_xor_sync(0xffffffffu, sum0, 2);
        sum1 += __shfl_xor_sync(0xffffffffu, sum1, 1);
        sum1 += __shfl_xor_sync(0xffffffffu, sum1, 2);
        l0 = l0 * al0 + sum0;
        l1 = l1 * al1 + sum1;

#pragma unroll
        for (int on = 0; on < 16; on++) {
            oacc[on][0] *= al0; oacc[on][1] *= al0;
            oacc[on][2] *= al1; oacc[on][3] *= al1;
        }

        // ---- pack P (bf16 hi/lo) into A-operand frags ----
        uint32_t pah[4][4], pal[4][4];
#pragma unroll
        for (int j = 0; j < 4; j++) {
#pragma unroll
            for (int q = 0; q < 4; q++) {
                int nf = 2 * j + (q >> 1);
                float x = sacc[nf][(q & 1) * 2 + 0];
                float y = sacc[nf][(q & 1) * 2 + 1];
                __nv_bfloat16 hx = __float2bfloat16(x);
                __nv_bfloat16 hy = __float2bfloat16(y);
                pah[j][q] = (uint32_t)__bfloat16_as_ushort(hx) |
                            ((uint32_t)__bfloat16_as_ushort(hy) << 16);
                pal[j][q] = pack_bf2(x - __bfloat162float(hx),
                                     y - __bfloat162float(hy));
            }
        }

        // ---- O += P V (bf16 3-term) ----
        const char* pVh = stage + 2 * KT_B;
        const char* pVl = stage + 3 * KT_B;
#pragma unroll
        for (int j = 0; j < 4; j++) {
            int krow = j * 16 + (lane & 7) + ((lane >> 3) & 1) * 8;
#pragma unroll
            for (int vb = 0; vb < 8; vb++) {
                int ncol = vb * 16 + (lane >> 4) * 8;
                uint32_t vaddr = smem_u32(pVh + (krow * FSTR + ncol) * 2);
                uint32_t waddr = smem_u32(pVl + (krow * FSTR + ncol) * 2);
                uint32_t v0, v1, v2, v3, w0, w1, w2, w3;
                ldsm4t(v0, v1, v2, v3, vaddr);
                ldsm4t(w0, w1, w2, w3, waddr);
                mma16816(oacc[2 * vb],     pah[j], v0, v1);
                mma16816(oacc[2 * vb],     pal[j], v0, v1);
                mma16816(oacc[2 * vb],     pah[j], w0, w1);
                mma16816(oacc[2 * vb + 1], pah[j], v2, v3);
                mma16816(oacc[2 * vb + 1], pal[j], v2, v3);
                mma16816(oacc[2 * vb + 1], pah[j], w2, w3);
            }
        }
        __syncthreads();
    }

    // ---- finalize: write bf16 hi/lo directly ----
    float inv0 = 1.0f / l0, inv1 = 1.0f / l1;
    const int row0 = q0 + rw + g, row1 = row0 + 8;
#pragma unroll
    for (int on = 0; on < 16; on++) {
        int col = h * HD + on * 8 + 2 * tq;
        float x0 = oacc[on][0] * inv0, y0 = oacc[on][1] * inv0;
        float x1 = oacc[on][2] * inv1, y1 = oacc[on][3] * inv1;
        __nv_bfloat16 hx0 = __float2bfloat16(x0), hy0 = __float2bfloat16(y0);
        __nv_bfloat16 hx1 = __float2bfloat16(x1), hy1 = __float2bfloat16(y1);
        *(uint32_t*)(Oh + (size_t)row0 * NQD + col) =
            (uint32_t)__bfloat16_as_ushort(hx0) | ((uint32_t)__bfloat16_as_ushort(hy0) << 16);
        *(uint32_t*)(Oh + (size_t)row1 * NQD + col) =
            (uint32_t)__bfloat16_as_ushort(hx1) | ((uint32_t)__bfloat16_as_ushort(hy1) << 16);
        *(uint32_t*)(Ol + (size_t)row0 * NQD + col) =
            pack_bf2(x0 - __bfloat162float(hx0), y0 - __bfloat162float(hy0));
        *(uint32_t*)(Ol + (size_t)row1 * NQD + col) =
            pack_bf2(x1 - __bfloat162float(hx1), y1 - __bfloat162float(hy1));
    }
}

// ---------------------------------------------------------------------------
extern "C" void kernel_launch(void* const* d_in, const int* in_sizes, int n_in,
                              void* d_out, int out_size) {
    const float* x  = (const float*)d_in[0];
    // d_in[1] = attention_mask (deterministic sliding-window; computed analytically)
    const float* wq = (const float*)d_in[2];
    const float* wk = (const float*)d_in[3];
    const float* wv = (const float*)d_in[4];
    const float* wo = (const float*)d_in[5];
    float* out = (float*)d_out;

    float *Qb, *Kb, *Vb;
    cudaGetSymbolAddress((void**)&Qb, g_Q);
    cudaGetSymbolAddress((void**)&Kb, g_K);
    cudaGetSymbolAddress((void**)&Vb, g_V);
    __nv_bfloat16 *xh, *xl, *wqh, *wql, *wkh, *wkl, *wvh, *wvl, *woh, *wol, *ah, *al;
    __nv_bfloat16 *qhh, *qll, *khh, *kll, *vhh, *vll;
    cudaGetSymbolAddress((void**)&xh, g_xh);   cudaGetSymbolAddress((void**)&xl, g_xl);
    cudaGetSymbolAddress((void**)&wqh, g_wqh); cudaGetSymbolAddress((void**)&wql, g_wql);
    cudaGetSymbolAddress((void**)&wkh, g_wkh); cudaGetSymbolAddress((void**)&wkl, g_wkl);
    cudaGetSymbolAddress((void**)&wvh, g_wvh); cudaGetSymbolAddress((void**)&wvl, g_wvl);
    cudaGetSymbolAddress((void**)&woh, g_woh); cudaGetSymbolAddress((void**)&wol, g_wol);
    cudaGetSymbolAddress((void**)&ah, g_ah);   cudaGetSymbolAddress((void**)&al, g_al);
    cudaGetSymbolAddress((void**)&qhh, g_Qh);  cudaGetSymbolAddress((void**)&qll, g_Ql);
    cudaGetSymbolAddress((void**)&khh, g_Kh);  cudaGetSymbolAddress((void**)&kll, g_Kl);
    cudaGetSymbolAddress((void**)&vhh, g_Vh);  cudaGetSymbolAddress((void**)&vll, g_Vl);

    static bool attr_set = false;
    if (!attr_set) {
        cudaFuncSetAttribute(gemm_qkv, cudaFuncAttributeMaxDynamicSharedMemorySize,
                             (int)GEMM_SMEM);
        cudaFuncSetAttribute(gemm_plain, cudaFuncAttributeMaxDynamicSharedMemorySize,
                             (int)GEMM_SMEM);
        cudaFuncSetAttribute(flash_hmma, cudaFuncAttributeMaxDynamicSharedMemorySize,
                             (int)FLASH_SMEM);
        attr_set = true;
    }

    // 1. fused split of x + all weights
    splitAll_kernel<<<C5 / 256, 256>>>(x, wq, wk, wv, wo,
                                       xh, xl, wqh, wql, wkh, wkl, wvh, wvl, woh, wol);
    // 2. fused QKV projection
    {
        dim3 gq(24, S_LEN / BM);
        gemm_qkv<<<gq, 256, GEMM_SMEM>>>(xh, xl, wqh, wql, wkh, wkl, wvh, wvl,
                                         Qb, Kb, Vb);
    }
    // 3. split V -> bf16 hi/lo
    split_kernel<<<(S_LEN * NKD / 4 + 255) / 256, 256>>>(Vb, vhh, vll, S_LEN * NKD / 4);
    // 4. fused RoPE Q+K -> bf16 hi/lo
    {
        int tot = S_LEN * 20 * (HD / 2);
        ropeQK_kernel<<<(tot + 255) / 256, 256>>>(Qb, Kb, qhh, qll, khh, kll);
    }
    // 5. HMMA flash attention (writes bf16 hi/lo attention output)
    {
        dim3 g(S_LEN / FQ, NH);
        flash_hmma<<<g, 256, FLASH_SMEM>>>(qhh, qll, khh, kll, vhh, vll, ah, al);
    }
    // 6. output projection
    {
        dim3 go(HIDDIM / BN, S_LEN / BM);
        gemm_plain<<<go, 256, GEMM_SMEM>>>(ah, al, woh, wol, out, HIDDIM);
    }
}

// round 7
// speedup vs baseline: 3.7058x; 1.0641x over previous
#include <cuda_runtime.h>
#include <cuda_bf16.h>
#include <math.h>
#include <stdint.h>

#define S_LEN 2048
#define HIDDIM 2048
#define NH 16
#define NKV 4
#define HD 128
#define NQD (NH*HD)    // 2048
#define NKD (NKV*HD)   // 512
#define WIN 1024
#define KDIM 2048

// ---------------- scratch ---------------------------------------------------
__device__ float g_Q[S_LEN * NQD];
__device__ float g_K[S_LEN * NKD];

__device__ __nv_bfloat16 g_xh[S_LEN * HIDDIM], g_xl[S_LEN * HIDDIM];
__device__ __nv_bfloat16 g_wqh[NQD * HIDDIM],  g_wql[NQD * HIDDIM];
__device__ __nv_bfloat16 g_wkh[NKD * HIDDIM],  g_wkl[NKD * HIDDIM];
__device__ __nv_bfloat16 g_wvh[NKD * HIDDIM],  g_wvl[NKD * HIDDIM];
__device__ __nv_bfloat16 g_woh[HIDDIM * NQD],  g_wol[HIDDIM * NQD];
__device__ __nv_bfloat16 g_ah[S_LEN * NQD],    g_al[S_LEN * NQD];

__device__ __nv_bfloat16 g_Qh[S_LEN * NQD], g_Ql[S_LEN * NQD];
__device__ __nv_bfloat16 g_Kh[S_LEN * NKD], g_Kl[S_LEN * NKD];
__device__ __nv_bfloat16 g_Vh[S_LEN * NKD], g_Vl[S_LEN * NKD];

// ---------------- helpers ---------------------------------------------------
__device__ __forceinline__ uint32_t smem_u32(const void* p) {
    uint32_t a;
    asm("{ .reg .u64 t; cvta.to.shared.u64 t, %1; cvt.u32.u64 %0, t; }"
        : "=r"(a) : "l"(p));
    return a;
}

__device__ __forceinline__ void cp16(uint32_t dst, const void* src) {
    asm volatile("cp.async.cg.shared.global [%0], [%1], 16;" :: "r"(dst), "l"(src));
}

__device__ __forceinline__ void mma16816(float* c, const uint32_t* a,
                                         uint32_t b0, uint32_t b1) {
    asm volatile(
        "mma.sync.aligned.m16n8k16.row.col.f32.bf16.bf16.f32 "
        "{%0,%1,%2,%3}, {%4,%5,%6,%7}, {%8,%9}, {%0,%1,%2,%3};"
        : "+f"(c[0]), "+f"(c[1]), "+f"(c[2]), "+f"(c[3])
        : "r"(a[0]), "r"(a[1]), "r"(a[2]), "r"(a[3]), "r"(b0), "r"(b1));
}

__device__ __forceinline__ void ldsm4(uint32_t* r, uint32_t addr) {
    asm volatile("ldmatrix.sync.aligned.m8n8.x4.shared.b16 {%0,%1,%2,%3}, [%4];"
                 : "=r"(r[0]), "=r"(r[1]), "=r"(r[2]), "=r"(r[3]) : "r"(addr));
}

__device__ __forceinline__ void ldsm4t(uint32_t& r0, uint32_t& r1,
                                       uint32_t& r2, uint32_t& r3, uint32_t addr) {
    asm volatile("ldmatrix.sync.aligned.m8n8.x4.trans.shared.b16 {%0,%1,%2,%3}, [%4];"
                 : "=r"(r0), "=r"(r1), "=r"(r2), "=r"(r3) : "r"(addr));
}

__device__ __forceinline__ uint32_t pack_bf2(float x, float y) {
    __nv_bfloat16 hx = __float2bfloat16(x), hy = __float2bfloat16(y);
    return (uint32_t)__bfloat16_as_ushort(hx) |
           ((uint32_t)__bfloat16_as_ushort(hy) << 16);
}

// ---------------------------------------------------------------------------
// fused split: x, wq, wk, wv, wo -> bf16 hi/lo
// ---------------------------------------------------------------------------
__device__ __forceinline__ void split4(const float* __restrict__ in,
                                       __nv_bfloat16* __restrict__ hi,
                                       __nv_bfloat16* __restrict__ lo, int i) {
    float4 v = ((const float4*)in)[i];
    __nv_bfloat16 h0 = __float2bfloat16(v.x);
    __nv_bfloat16 h1 = __float2bfloat16(v.y);
    __nv_bfloat16 h2 = __float2bfloat16(v.z);
    __nv_bfloat16 h3 = __float2bfloat16(v.w);
    __nv_bfloat16 l0 = __float2bfloat16(v.x - __bfloat162float(h0));
    __nv_bfloat16 l1 = __float2bfloat16(v.y - __bfloat162float(h1));
    __nv_bfloat16 l2 = __float2bfloat16(v.z - __bfloat162float(h2));
    __nv_bfloat16 l3 = __float2bfloat16(v.w - __bfloat162float(h3));
    uint2 hv, lv;
    hv.x = (uint32_t)__bfloat16_as_ushort(h0) | ((uint32_t)__bfloat16_as_ushort(h1) << 16);
    hv.y = (uint32_t)__bfloat16_as_ushort(h2) | ((uint32_t)__bfloat16_as_ushort(h3) << 16);
    lv.x = (uint32_t)__bfloat16_as_ushort(l0) | ((uint32_t)__bfloat16_as_ushort(l1) << 16);
    lv.y = (uint32_t)__bfloat16_as_ushort(l2) | ((uint32_t)__bfloat16_as_ushort(l3) << 16);
    ((uint2*)hi)[i] = hv;
    ((uint2*)lo)[i] = lv;
}

#define C1 1048576
#define C2 2097152
#define C3 2359296
#define C4 2621440
#define C5 3670016

__global__ void splitAll_kernel(const float* __restrict__ x,
                                const float* __restrict__ wq,
                                const float* __restrict__ wk,
                                const float* __restrict__ wv,
                                const float* __restrict__ wo,
                                __nv_bfloat16* xh, __nv_bfloat16* xl,
                                __nv_bfloat16* wqh, __nv_bfloat16* wql,
                                __nv_bfloat16* wkh, __nv_bfloat16* wkl,
                                __nv_bfloat16* wvh, __nv_bfloat16* wvl,
                                __nv_bfloat16* woh, __nv_bfloat16* wol) {
    int i = blockIdx.x * blockDim.x + threadIdx.x;
    if (i < C1)      split4(x,  xh,  xl,  i);
    else if (i < C2) split4(wq, wqh, wql, i - C1);
    else if (i < C3) split4(wk, wkh, wkl, i - C2);
    else if (i < C4) split4(wv, wvh, wvl, i - C3);
    else if (i < C5) split4(wo, woh, wol, i - C4);
}

// ---------------------------------------------------------------------------
// HMMA GEMM core: C[M,N] = Ah*Bh^T + Ah*Bl^T + Al*Bh^T (NT, K=2048, fp32 acc)
// BM=BN=128, BK=32, 256 threads, warp tile 32x64, 2-stage cp.async.
// Fragment loads via ldmatrix.x4. Optional bf16 hi/lo epilogue (for V).
// ---------------------------------------------------------------------------
#define BM 128
#define BN 128
#define BKG 32
#define ASTRIDE 40
#define TILE_B (128 * ASTRIDE * 2)
#define STAGE_B (4 * TILE_B)
#define GEMM_SMEM (2 * STAGE_B)
#define NST (KDIM / BKG)

__device__ __forceinline__ void gemm_body(const __nv_bfloat16* __restrict__ Ahg,
                                          const __nv_bfloat16* __restrict__ Alg,
                                          const __nv_bfloat16* __restrict__ Bhg,
                                          const __nv_bfloat16* __restrict__ Blg,
                                          float* __restrict__ C,
                                          __nv_bfloat16* __restrict__ Ch,
                                          __nv_bfloat16* __restrict__ Cl,
                                          int N, int mBase, int nBase, char* smg) {
    const int t = threadIdx.x;
    const int wid = t >> 5, lane = t & 31;
    const int g = lane >> 2, tq = lane & 3;
    const int wm = wid & 3, wn = wid >> 2;

    float acc[2][8][4] = {};

    const int chunk = t & 3;
    const int row0 = t >> 2;

    // ldmatrix lane offsets (bytes)
    const int sub16 = lane & 15;
    const int hi8 = (lane >> 4) << 3;
    const int q2 = lane >> 3, sub8 = lane & 7;
    const int loffA0 = ((wm * 32 + sub16) * ASTRIDE + hi8) * 2;
    const int loffA1 = ((wm * 32 + 16 + sub16) * ASTRIDE + hi8) * 2;
    const int loffB  = ((wn * 64 + ((q2 >> 1) << 3) + sub8) * ASTRIDE + ((q2 & 1) << 3)) * 2;

    const __nv_bfloat16* srcs[4] = {Ahg, Alg, Bhg, Blg};
    const int tb[4] = {mBase, mBase, nBase, nBase};

    {
        char* base = smg;
#pragma unroll
        for (int ti = 0; ti < 4; ti++)
#pragma unroll
            for (int rr = 0; rr < 2; rr++) {
                int r = row0 + rr * 64;
                uint32_t dst = smem_u32(base + ti * TILE_B + (r * ASTRIDE + chunk * 8) * 2);
                cp16(dst, srcs[ti] + (size_t)(tb[ti] + r) * KDIM + chunk * 8);
            }
        asm volatile("cp.async.commit_group;");
    }

    for (int s = 0; s < NST; s++) {
        if (s + 1 < NST) {
            char* base = smg + ((s + 1) & 1) * STAGE_B;
            int k0 = (s + 1) * BKG;
#pragma unroll
            for (int ti = 0; ti < 4; ti++)
#pragma unroll
                for (int rr = 0; rr < 2; rr++) {
                    int r = row0 + rr * 64;
                    uint32_t dst = smem_u32(base + ti * TILE_B + (r * ASTRIDE + chunk * 8) * 2);
                    cp16(dst, srcs[ti] + (size_t)(tb[ti] + r) * KDIM + k0 + chunk * 8);
                }
            asm volatile("cp.async.commit_group;");
            asm volatile("cp.async.wait_group 1;");
        } else {
            asm volatile("cp.async.wait_group 0;");
        }
        __syncthreads();

        uint32_t bAh = smem_u32(smg + (s & 1) * STAGE_B);
        uint32_t bAl = bAh + TILE_B;
        uint32_t bBh = bAh + 2 * TILE_B;
        uint32_t bBl = bAh + 3 * TILE_B;

#pragma unroll
        for (int ks = 0; ks < 2; ks++) {
            const int kk2 = ks * 32;   // 16 halves = 32 bytes
            uint32_t ah[2][4], al[2][4];
            ldsm4(ah[0], bAh + loffA0 + kk2);
            ldsm4(ah[1], bAh + loffA1 + kk2);
            ldsm4(al[0], bAl + loffA0 + kk2);
            ldsm4(al[1], bAl + loffA1 + kk2);
#pragma unroll
            for (int p = 0; p < 4; p++) {
                uint32_t bh4[4], bl4[4];
                ldsm4(bh4, bBh + loffB + p * (16 * ASTRIDE * 2) + kk2);
                ldsm4(bl4, bBl + loffB + p * (16 * ASTRIDE * 2) + kk2);
#pragma unroll
                for (int mf = 0; mf < 2; mf++) {
                    mma16816(acc[mf][2 * p],     ah[mf], bh4[0], bh4[1]);
                    mma16816(acc[mf][2 * p],     ah[mf], bl4[0], bl4[1]);
                    mma16816(acc[mf][2 * p],     al[mf], bh4[0], bh4[1]);
                    mma16816(acc[mf][2 * p + 1], ah[mf], bh4[2], bh4[3]);
                    mma16816(acc[mf][2 * p + 1], ah[mf], bl4[2], bl4[3]);
                    mma16816(acc[mf][2 * p + 1], al[mf], bh4[2], bh4[3]);
                }
            }
        }
        __syncthreads();
    }

    if (Ch) {
        // bf16 hi/lo epilogue (V path)
#pragma unroll
        for (int mf = 0; mf < 2; mf++) {
            int row = mBase + wm * 32 + mf * 16 + g;
#pragma unroll
            for (int nf = 0; nf < 8; nf++) {
                int col = nBase + wn * 64 + nf * 8 + 2 * tq;
                float a0 = acc[mf][nf][0], a1 = acc[mf][nf][1];
                float a2 = acc[mf][nf][2], a3 = acc[mf][nf][3];
                __nv_bfloat16 h0 = __float2bfloat16(a0), h1 = __float2bfloat16(a1);
                __nv_bfloat16 h2 = __float2bfloat16(a2), h3 = __float2bfloat16(a3);
                *(uint32_t*)(Ch + (size_t)row * N + col) =
                    (uint32_t)__bfloat16_as_ushort(h0) | ((uint32_t)__bfloat16_as_ushort(h1) << 16);
                *(uint32_t*)(Ch + (size_t)(row + 8) * N + col) =
                    (uint32_t)__bfloat16_as_ushort(h2) | ((uint32_t)__bfloat16_as_ushort(h3) << 16);
                *(uint32_t*)(Cl + (size_t)row * N + col) =
                    pack_bf2(a0 - __bfloat162float(h0), a1 - __bfloat162float(h1));
                *(uint32_t*)(Cl + (size_t)(row + 8) * N + col) =
                    pack_bf2(a2 - __bfloat162float(h2), a3 - __bfloat162float(h3));
            }
        }
    } else {
#pragma unroll
        for (int mf = 0; mf < 2; mf++) {
            int row = mBase + wm * 32 + mf * 16 + g;
#pragma unroll
            for (int nf = 0; nf < 8; nf++) {
                int col = nBase + wn * 64 + nf * 8 + 2 * tq;
                *(float2*)(C + (size_t)row * N + col) =
                    make_float2(acc[mf][nf][0], acc[mf][nf][1]);
                *(float2*)(C + (size_t)(row + 8) * N + col) =
                    make_float2(acc[mf][nf][2], acc[mf][nf][3]);
            }
        }
    }
}

// fused QKV projection: grid.x = 24 column blocks (16 Q, 4 K, 4 V)
// V is emitted directly as bf16 hi/lo (no RoPE needed on V).
__global__ __launch_bounds__(256, 2) void gemm_qkv(const __nv_bfloat16* __restrict__ xh,
                                                   const __nv_bfloat16* __restrict__ xl,
                                                   const __nv_bfloat16* __restrict__ wqh,
                                                   const __nv_bfloat16* __restrict__ wql,
                                                   const __nv_bfloat16* __restrict__ wkh,
                                                   const __nv_bfloat16* __restrict__ wkl,
                                                   const __nv_bfloat16* __restrict__ wvh,
                                                   const __nv_bfloat16* __restrict__ wvl,
                                                   float* __restrict__ Q,
                                                   float* __restrict__ K,
                                                   __nv_bfloat16* __restrict__ Vh,
                                                   __nv_bfloat16* __restrict__ Vl) {
    extern __shared__ char smg[];
    int bx = blockIdx.x;
    int mBase = blockIdx.y * BM;
    if (bx < 16) {
        gemm_body(xh, xl, wqh, wql, Q, nullptr, nullptr, NQD, mBase, bx * BN, smg);
    } else if (bx < 20) {
        gemm_body(xh, xl, wkh, wkl, K, nullptr, nullptr, NKD, mBase, (bx - 16) * BN, smg);
    } else {
        gemm_body(xh, xl, wvh, wvl, nullptr, Vh, Vl, NKD, mBase, (bx - 20) * BN, smg);
    }
}

__global__ __launch_bounds__(256, 2) void gemm_plain(const __nv_bfloat16* __restrict__ Ah,
                                                     const __nv_bfloat16* __restrict__ Al,
                                                     const __nv_bfloat16* __restrict__ Bh,
                                                     const __nv_bfloat16* __restrict__ Bl,
                                                     float* __restrict__ C, int N) {
    extern __shared__ char smg[];
    gemm_body(Ah, Al, Bh, Bl, C, nullptr, nullptr, N, blockIdx.y * BM, blockIdx.x * BN, smg);
}

// ---------------------------------------------------------------------------
// fused RoPE for Q and K: reads fp32, writes bf16 hi/lo
// ---------------------------------------------------------------------------
__global__ void ropeQK_kernel(const float* __restrict__ Q, const float* __restrict__ K,
                              __nv_bfloat16* __restrict__ Qh, __nv_bfloat16* __restrict__ Ql,
                              __nv_bfloat16* __restrict__ Kh, __nv_bfloat16* __restrict__ Kl) {
    int idx = blockIdx.x * blockDim.x + threadIdx.x;
    int total = S_LEN * 20 * (HD / 2);
    if (idx >= total) return;
    int j = idx & 63;
    int rest = idx >> 6;
    int hh = rest % 20;
    int s = rest / 20;

    float invf = expf(-logf(10000.0f) * (float)(2 * j) / (float)HD);
    float ang = (float)s * invf;
    float c = cosf(ang), sn = sinf(ang);

    const float* src;
    __nv_bfloat16 *dh, *dl;
    size_t base;
    if (hh < 16) { src = Q; dh = Qh; dl = Ql; base = (size_t)s * NQD + hh * HD; }
    else         { src = K; dh = Kh; dl = Kl; base = (size_t)s * NKD + (hh - 16) * HD; }

    float a = src[base + j], b = src[base + j + 64];
    float ra = a * c - b * sn;
    float rb = b * c + a * sn;
    __nv_bfloat16 rah = __float2bfloat16(ra);
    __nv_bfloat16 rbh = __float2bfloat16(rb);
    dh[base + j]      = rah;
    dh[base + j + 64] = rbh;
    dl[base + j]      = __float2bfloat16(ra - __bfloat162float(rah));
    dl[base + j + 64] = __float2bfloat16(rb - __bfloat162float(rbh));
}

// ---------------------------------------------------------------------------
// HMMA flash attention. 128 q-rows per CTA, 64 keys per iter, HD=128.
// ldmatrix fragment loads in the S-phase. Heavy q-tiles first.
// ---------------------------------------------------------------------------
#define FQ 128
#define FKK 64
#define FSTR 136
#define FROWB (FSTR * 2)
#define QT_B (FQ * FROWB)
#define KT_B (FKK * FROWB)
#define FSTAGE_B (4 * KT_B)
#define FSTAGE0 (2 * QT_B)
#define FLASH_SMEM (FSTAGE0 + 2 * FSTAGE_B)   // 208896

__global__ __launch_bounds__(256, 1) void flash_hmma(
        const __nv_bfloat16* __restrict__ Qh, const __nv_bfloat16* __restrict__ Ql,
        const __nv_bfloat16* __restrict__ Kh, const __nv_bfloat16* __restrict__ Kl,
        const __nv_bfloat16* __restrict__ Vh, const __nv_bfloat16* __restrict__ Vl,
        __nv_bfloat16* __restrict__ Oh, __nv_bfloat16* __restrict__ Ol) {
    extern __shared__ char sm[];
    const int tid = threadIdx.x;
    const int wid = tid >> 5, lane = tid & 31;
    const int g = lane >> 2, tq = lane & 3;
    const int qt = gridDim.x - 1 - blockIdx.x;   // heavy tiles first
    const int h = blockIdx.y;
    const int kvh = h >> 2;
    const int q0 = qt * FQ;
    const int rw = wid * 16;
    const float sc = 0.08838834764831845f;

    // ldmatrix lane offsets
    const int sub16 = lane & 15;
    const int hi8 = (lane >> 4) << 3;
    const int q2 = lane >> 3, sub8 = lane & 7;
    const int loffQ = ((rw + sub16) * FSTR + hi8) * 2;
    const int loffK = ((((q2 >> 1) << 3) + sub8) * FSTR + ((q2 & 1) << 3)) * 2;

    {
#pragma unroll
        for (int i = 0; i < 16; i++) {
            int id = tid + i * 256;
            int tile = id >> 11;
            int rem = id & 2047;
            int r = rem >> 4, c = rem & 15;
            uint32_t dst = smem_u32(sm + tile * QT_B + r * FROWB + c * 16);
            const __nv_bfloat16* src = (tile == 0 ? Qh : Ql) +
                (size_t)(q0 + r) * NQD + h * HD + c * 8;
            cp16(dst, src);
        }
    }
    int kt_begin = q0 - (WIN - 1);
    kt_begin = (kt_begin < 0) ? 0 : (kt_begin >> 6);
    const int kt_end = (q0 + FQ - 1) >> 6;

    const __nv_bfloat16* kvsrc[4] = {Kh, Kl, Vh, Vl};
    {
        int k0 = kt_begin * FKK;
#pragma unroll
        for (int i = 0; i < 16; i++) {
            int id = tid + i * 256;
            int tile = id >> 10;
            int rem = id & 1023;
            int r = rem >> 4, c = rem & 15;
            uint32_t dst = smem_u32(sm + FSTAGE0 + tile * KT_B + r * FROWB + c * 16);
            cp16(dst, kvsrc[tile] + (size_t)(k0 + r) * NKD + kvh * HD + c * 8);
        }
        asm volatile("cp.async.commit_group;");
    }

    float oacc[16][4] = {};
    float m0 = -1e30f, m1 = -1e30f, l0 = 0.0f, l1 = 0.0f;

    for (int kt = kt_begin; kt <= kt_end; kt++) {
        const int buf = (kt - kt_begin) & 1;
        if (kt < kt_end) {
            int k0 = (kt + 1) * FKK;
            char* base = sm + FSTAGE0 + (buf ^ 1) * FSTAGE_B;
#pragma unroll
            for (int i = 0; i < 16; i++) {
                int id = tid + i * 256;
                int tile = id >> 10;
                int rem = id & 1023;
                int r = rem >> 4, c = rem & 15;
                uint32_t dst = smem_u32(base + tile * KT_B + r * FROWB + c * 16);
                cp16(dst, kvsrc[tile] + (size_t)(k0 + r) * NKD + kvh * HD + c * 8);
            }
            asm volatile("cp.async.commit_group;");
            asm volatile("cp.async.wait_group 1;");
        } else {
            asm volatile("cp.async.wait_group 0;");
        }
        __syncthreads();

        uint32_t bQh = smem_u32(sm);
        uint32_t bQl = bQh + QT_B;
        uint32_t bKh = smem_u32(sm + FSTAGE0 + buf * FSTAGE_B);
        uint32_t bKl = bKh + KT_B;
        const int k0 = kt * FKK;

        // ---- S = Q K^T (bf16 3-term, ldmatrix frags) ----
        float sacc[8][4] = {};
#pragma unroll
        for (int ks = 0; ks < 8; ks++) {
            const int kk2 = ks * 32;
            uint32_t qh[4], ql[4];
            ldsm4(qh, bQh + loffQ + kk2);
            ldsm4(ql, bQl + loffQ + kk2);
#pragma unroll
            for (int p = 0; p < 4; p++) {
                uint32_t kh4[4], kl4[4];
                ldsm4(kh4, bKh + loffK + p * (16 * FROWB) + kk2);
                ldsm4(kl4, bKl + loffK + p * (16 * FROWB) + kk2);
                mma16816(sacc[2 * p],     qh, kh4[0], kh4[1]);
                mma16816(sacc[2 * p],     qh, kl4[0], kl4[1]);
                mma16816(sacc[2 * p],     ql, kh4[0], kh4[1]);
                mma16816(sacc[2 * p + 1], qh, kh4[2], kh4[3]);
                mma16816(sacc[2 * p + 1], qh, kl4[2], kl4[3]);
                mma16816(sacc[2 * p + 1], ql, kh4[2], kh4[3]);
            }
        }

        // ---- scale + sliding-window causal mask ----
        const int row0 = q0 + rw + g, row1 = row0 + 8;
#pragma unroll
        for (int nf = 0; nf < 8; nf++) {
            int colb = k0 + nf * 8 + 2 * tq;
#pragma unroll
            for (int c = 0; c < 4; c++) {
                int col = colb + (c & 1);
                int row = (c < 2) ? row0 : row1;
                bool ok = (col <= row) && (row - col < WIN);
                sacc[nf][c] = ok ? sacc[nf][c] * sc : -1e9f;
            }
        }

        // ---- online softmax ----
        float mx0 = -1e30f, mx1 = -1e30f;
#pragma unroll
        for (int nf = 0; nf < 8; nf++) {
            mx0 = fmaxf(mx0, fmaxf(sacc[nf][0], sacc[nf][1]));
            mx1 = fmaxf(mx1, fmaxf(sacc[nf][2], sacc[nf][3]));
        }
        mx0 = fmaxf(mx0, __shfl_xor_sync(0xffffffffu, mx0, 1));
        mx0 = fmaxf(mx0, __shfl_xor_sync(0xffffffffu, mx0, 2));
        mx1 = fmaxf(mx1, __shfl_xor_sync(0xffffffffu, mx1, 1));
        mx1 = fmaxf(mx1, __shfl_xor_sync(0xffffffffu, mx1, 2));
        float mn0 = fmaxf(m0, mx0), mn1 = fmaxf(m1, mx1);
        float al0 = __expf(m0 - mn0), al1 = __expf(m1 - mn1);
        m0 = mn0; m1 = mn1;

        float sum0 = 0.0f, sum1 = 0.0f;
#pragma unroll
        for (int nf = 0; nf < 8; nf++) {
            sacc[nf][0] = __expf(sacc[nf][0] - mn0);
            sacc[nf][1] = __expf(sacc[nf][1] - mn0);
            sacc[nf][2] = __expf(sacc[nf][2] - mn1);
            sacc[nf][3] = __expf(sacc[nf][3] - mn1);
            sum0 += sacc[nf][0] + sacc[nf][1];
            sum1 += sacc[nf][2] + sacc[nf][3];
        }
        sum0 += __shfl_xor_sync(0xffffffffu, sum0, 1);
        sum0 += __shfl_xor_sync(0xffffffffu, sum0, 2);
        sum1 += __shfl_xor_sync(0xffffffffu, sum1, 1);
        sum1 += __shfl_xor_sync(0xffffffffu, sum1, 2);
        l0 = l0 * al0 + sum0;
        l1 = l1 * al1 + sum1;

#pragma unroll
        for (int on = 0; on < 16; on++) {
            oacc[on][0] *= al0; oacc[on][1] *= al0;
            oacc[on][2] *= al1; oacc[on][3] *= al1;
        }

        // ---- pack P (bf16 hi/lo) into A-operand frags ----
        uint32_t pah[4][4], pal[4][4];
#pragma unroll
        for (int j = 0; j < 4; j++) {
#pragma unroll
            for (int q = 0; q < 4; q++) {
                int nf = 2 * j + (q >> 1);
                float x = sacc[nf][(q & 1) * 2 + 0];
                float y = sacc[nf][(q & 1) * 2 + 1];
                __nv_bfloat16 hx = __float2bfloat16(x);
                __nv_bfloat16 hy = __float2bfloat16(y);
                pah[j][q] = (uint32_t)__bfloat16_as_ushort(hx) |
                            ((uint32_t)__bfloat16_as_ushort(hy) << 16);
                pal[j][q] = pack_bf2(x - __bfloat162float(hx),
                                     y - __bfloat162float(hy));
            }
        }

        // ---- O += P V (bf16 3-term) ----
        const char* stage = sm + FSTAGE0 + buf * FSTAGE_B;
        const char* pVh = stage + 2 * KT_B;
        const char* pVl = stage + 3 * KT_B;
#pragma unroll
        for (int j = 0; j < 4; j++) {
            int krow = j * 16 + (lane & 7) + ((lane >> 3) & 1) * 8;
#pragma unroll
            for (int vb = 0; vb < 8; vb++) {
                int ncol = vb * 16 + (lane >> 4) * 8;
                uint32_t vaddr = smem_u32(pVh + (krow * FSTR + ncol) * 2);
                uint32_t waddr = smem_u32(pVl + (krow * FSTR + ncol) * 2);
                uint32_t v0, v1, v2, v3, w0, w1, w2, w3;
                ldsm4t(v0, v1, v2, v3, vaddr);
                ldsm4t(w0, w1, w2, w3, waddr);
                mma16816(oacc[2 * vb],     pah[j], v0, v1);
                mma16816(oacc[2 * vb],     pal[j], v0, v1);
                mma16816(oacc[2 * vb],     pah[j], w0, w1);
                mma16816(oacc[2 * vb + 1], pah[j], v2, v3);
                mma16816(oacc[2 * vb + 1], pal[j], v2, v3);
                mma16816(oacc[2 * vb + 1], pah[j], w2, w3);
            }
        }
        __syncthreads();
    }

    // ---- finalize: write bf16 hi/lo directly ----
    float inv0 = 1.0f / l0, inv1 = 1.0f / l1;
    const int row0 = q0 + rw + g, row1 = row0 + 8;
#pragma unroll
    for (int on = 0; on < 16; on++) {
        int col = h * HD + on * 8 + 2 * tq;
        float x0 = oacc[on][0] * inv0, y0 = oacc[on][1] * inv0;
        float x1 = oacc[on][2] * inv1, y1 = oacc[on][3] * inv1;
        __nv_bfloat16 hx0 = __float2bfloat16(x0), hy0 = __float2bfloat16(y0);
        __nv_bfloat16 hx1 = __float2bfloat16(x1), hy1 = __float2bfloat16(y1);
        *(uint32_t*)(Oh + (size_t)row0 * NQD + col) =
            (uint32_t)__bfloat16_as_ushort(hx0) | ((uint32_t)__bfloat16_as_ushort(hy0) << 16);
        *(uint32_t*)(Oh + (size_t)row1 * NQD + col) =
            (uint32_t)__bfloat16_as_ushort(hx1) | ((uint32_t)__bfloat16_as_ushort(hy1) << 16);
        *(uint32_t*)(Ol + (size_t)row0 * NQD + col) =
            pack_bf2(x0 - __bfloat162float(hx0), y0 - __bfloat162float(hy0));
        *(uint32_t*)(Ol + (size_t)row1 * NQD + col) =
            pack_bf2(x1 - __bfloat162float(hx1), y1 - __bfloat162float(hy1));
    }
}

// ---------------------------------------------------------------------------
extern "C" void kernel_launch(void* const* d_in, const int* in_sizes, int n_in,
                              void* d_out, int out_size) {
    const float* x  = (const float*)d_in[0];
    // d_in[1] = attention_mask (deterministic sliding-window; computed analytically)
    const float* wq = (const float*)d_in[2];
    const float* wk = (const float*)d_in[3];
    const float* wv = (const float*)d_in[4];
    const float* wo = (const float*)d_in[5];
    float* out = (float*)d_out;

    float *Qb, *Kb;
    cudaGetSymbolAddress((void**)&Qb, g_Q);
    cudaGetSymbolAddress((void**)&Kb, g_K);
    __nv_bfloat16 *xh, *xl, *wqh, *wql, *wkh, *wkl, *wvh, *wvl, *woh, *wol, *ah, *al;
    __nv_bfloat16 *qhh, *qll, *khh, *kll, *vhh, *vll;
    cudaGetSymbolAddress((void**)&xh, g_xh);   cudaGetSymbolAddress((void**)&xl, g_xl);
    cudaGetSymbolAddress((void**)&wqh, g_wqh); cudaGetSymbolAddress((void**)&wql, g_wql);
    cudaGetSymbolAddress((void**)&wkh, g_wkh); cudaGetSymbolAddress((void**)&wkl, g_wkl);
    cudaGetSymbolAddress((void**)&wvh, g_wvh); cudaGetSymbolAddress((void**)&wvl, g_wvl);
    cudaGetSymbolAddress((void**)&woh, g_woh); cudaGetSymbolAddress((void**)&wol, g_wol);
    cudaGetSymbolAddress((void**)&ah, g_ah);   cudaGetSymbolAddress((void**)&al, g_al);
    cudaGetSymbolAddress((void**)&qhh, g_Qh);  cudaGetSymbolAddress((void**)&qll, g_Ql);
    cudaGetSymbolAddress((void**)&khh, g_Kh);  cudaGetSymbolAddress((void**)&kll, g_Kl);
    cudaGetSymbolAddress((void**)&vhh, g_Vh);  cudaGetSymbolAddress((void**)&vll, g_Vl);

    static bool attr_set = false;
    if (!attr_set) {
        cudaFuncSetAttribute(gemm_qkv, cudaFuncAttributeMaxDynamicSharedMemorySize,
                             (int)GEMM_SMEM);
        cudaFuncSetAttribute(gemm_plain, cudaFuncAttributeMaxDynamicSharedMemorySize,
                             (int)GEMM_SMEM);
        cudaFuncSetAttribute(flash_hmma, cudaFuncAttributeMaxDynamicSharedMemorySize,
                             (int)FLASH_SMEM);
        attr_set = true;
    }

    // 1. fused split of x + all weights
    splitAll_kernel<<<C5 / 256, 256>>>(x, wq, wk, wv, wo,
                                       xh, xl, wqh, wql, wkh, wkl, wvh, wvl, woh, wol);
    // 2. fused QKV projection (V written directly as bf16 hi/lo)
    {
        dim3 gq(24, S_LEN / BM);
        gemm_qkv<<<gq, 256, GEMM_SMEM>>>(xh, xl, wqh, wql, wkh, wkl, wvh, wvl,
                                         Qb, Kb, vhh, vll);
    }
    // 3. fused RoPE Q+K -> bf16 hi/lo
    {
        int tot = S_LEN * 20 * (HD / 2);
        ropeQK_kernel<<<(tot + 255) / 256, 256>>>(Qb, Kb, qhh, qll, khh, kll);
    }
    // 4. HMMA flash attention (writes bf16 hi/lo attention output)
    {
        dim3 g(S_LEN / FQ, NH);
        flash_hmma<<<g, 256, FLASH_SMEM>>>(qhh, qll, khh, kll, vhh, vll, ah, al);
    }
    // 5. output projection
    {
        dim3 go(HIDDIM / BN, S_LEN / BM);
        gemm_plain<<<go, 256, GEMM_SMEM>>>(ah, al, woh, wol, out, HIDDIM);
    }
}

// round 9
// speedup vs baseline: 3.7210x; 1.0041x over previous
#include <cuda_runtime.h>
#include <cuda_bf16.h>
#include <math.h>
#include <stdint.h>

#define S_LEN 2048
#define HIDDIM 2048
#define NH 16
#define NKV 4
#define HD 128
#define NQD (NH*HD)    // 2048
#define NKD (NKV*HD)   // 512
#define WIN 1024
#define KDIM 2048

// ---------------- scratch ---------------------------------------------------
__device__ float g_Q[S_LEN * NQD];
__device__ float g_K[S_LEN * NKD];

__device__ __nv_bfloat16 g_xh[S_LEN * HIDDIM], g_xl[S_LEN * HIDDIM];
__device__ __nv_bfloat16 g_wqh[NQD * HIDDIM],  g_wql[NQD * HIDDIM];
__device__ __nv_bfloat16 g_wkh[NKD * HIDDIM],  g_wkl[NKD * HIDDIM];
__device__ __nv_bfloat16 g_wvh[NKD * HIDDIM],  g_wvl[NKD * HIDDIM];
__device__ __nv_bfloat16 g_woh[HIDDIM * NQD],  g_wol[HIDDIM * NQD];
__device__ __nv_bfloat16 g_ah[S_LEN * NQD],    g_al[S_LEN * NQD];

__device__ __nv_bfloat16 g_Qh[S_LEN * NQD], g_Ql[S_LEN * NQD];
__device__ __nv_bfloat16 g_Kh[S_LEN * NKD], g_Kl[S_LEN * NKD];
__device__ __nv_bfloat16 g_Vh[S_LEN * NKD], g_Vl[S_LEN * NKD];

// ---------------- helpers ---------------------------------------------------
__device__ __forceinline__ uint32_t smem_u32(const void* p) {
    uint32_t a;
    asm("{ .reg .u64 t; cvta.to.shared.u64 t, %1; cvt.u32.u64 %0, t; }"
        : "=r"(a) : "l"(p));
    return a;
}

__device__ __forceinline__ void cp16(uint32_t dst, const void* src) {
    asm volatile("cp.async.cg.shared.global [%0], [%1], 16;" :: "r"(dst), "l"(src));
}

__device__ __forceinline__ void mma16816(float* c, const uint32_t* a,
                                         uint32_t b0, uint32_t b1) {
    asm volatile(
        "mma.sync.aligned.m16n8k16.row.col.f32.bf16.bf16.f32 "
        "{%0,%1,%2,%3}, {%4,%5,%6,%7}, {%8,%9}, {%0,%1,%2,%3};"
        : "+f"(c[0]), "+f"(c[1]), "+f"(c[2]), "+f"(c[3])
        : "r"(a[0]), "r"(a[1]), "r"(a[2]), "r"(a[3]), "r"(b0), "r"(b1));
}

__device__ __forceinline__ void ldsm4(uint32_t* r, uint32_t addr) {
    asm volatile("ldmatrix.sync.aligned.m8n8.x4.shared.b16 {%0,%1,%2,%3}, [%4];"
                 : "=r"(r[0]), "=r"(r[1]), "=r"(r[2]), "=r"(r[3]) : "r"(addr));
}

__device__ __forceinline__ void ldsm4t(uint32_t& r0, uint32_t& r1,
                                       uint32_t& r2, uint32_t& r3, uint32_t addr) {
    asm volatile("ldmatrix.sync.aligned.m8n8.x4.trans.shared.b16 {%0,%1,%2,%3}, [%4];"
                 : "=r"(r0), "=r"(r1), "=r"(r2), "=r"(r3) : "r"(addr));
}

__device__ __forceinline__ uint32_t pack_bf2(float x, float y) {
    __nv_bfloat16 hx = __float2bfloat16(x), hy = __float2bfloat16(y);
    return (uint32_t)__bfloat16_as_ushort(hx) |
           ((uint32_t)__bfloat16_as_ushort(hy) << 16);
}

// ---------------------------------------------------------------------------
// fused split: x, wq, wk, wv, wo -> bf16 hi/lo. 4 float4 per thread (MLP=4).
// ---------------------------------------------------------------------------
__device__ __forceinline__ void split_store(float4 v,
                                            __nv_bfloat16* __restrict__ hi,
                                            __nv_bfloat16* __restrict__ lo, int i) {
    __nv_bfloat16 h0 = __float2bfloat16(v.x);
    __nv_bfloat16 h1 = __float2bfloat16(v.y);
    __nv_bfloat16 h2 = __float2bfloat16(v.z);
    __nv_bfloat16 h3 = __float2bfloat16(v.w);
    __nv_bfloat16 l0 = __float2bfloat16(v.x - __bfloat162float(h0));
    __nv_bfloat16 l1 = __float2bfloat16(v.y - __bfloat162float(h1));
    __nv_bfloat16 l2 = __float2bfloat16(v.z - __bfloat162float(h2));
    __nv_bfloat16 l3 = __float2bfloat16(v.w - __bfloat162float(h3));
    uint2 hv, lv;
    hv.x = (uint32_t)__bfloat16_as_ushort(h0) | ((uint32_t)__bfloat16_as_ushort(h1) << 16);
    hv.y = (uint32_t)__bfloat16_as_ushort(h2) | ((uint32_t)__bfloat16_as_ushort(h3) << 16);
    lv.x = (uint32_t)__bfloat16_as_ushort(l0) | ((uint32_t)__bfloat16_as_ushort(l1) << 16);
    lv.y = (uint32_t)__bfloat16_as_ushort(l2) | ((uint32_t)__bfloat16_as_ushort(l3) << 16);
    ((uint2*)hi)[i] = hv;
    ((uint2*)lo)[i] = lv;
}

// quarter sizes (in float4) per array
#define XQ4  262144
#define WQQ4 262144
#define WKQ4 65536
#define WVQ4 65536
#define WOQ4 262144
#define SPLIT_THREADS (XQ4 + WQQ4 + WKQ4 + WVQ4 + WOQ4)   // 917504

__global__ void splitAll_kernel(const float* __restrict__ x,
                                const float* __restrict__ wq,
                                const float* __restrict__ wk,
                                const float* __restrict__ wv,
                                const float* __restrict__ wo,
                                __nv_bfloat16* xh, __nv_bfloat16* xl,
                                __nv_bfloat16* wqh, __nv_bfloat16* wql,
                                __nv_bfloat16* wkh, __nv_bfloat16* wkl,
                                __nv_bfloat16* wvh, __nv_bfloat16* wvl,
                                __nv_bfloat16* woh, __nv_bfloat16* wol) {
    int i = blockIdx.x * blockDim.x + threadIdx.x;
    const float* in; __nv_bfloat16 *hi, *lo; int base, qtr;
    if (i < XQ4)                       { in = x;  hi = xh;  lo = xl;  base = i;                      qtr = XQ4;  }
    else if (i < XQ4+WQQ4)             { in = wq; hi = wqh; lo = wql; base = i - XQ4;                qtr = WQQ4; }
    else if (i < XQ4+WQQ4+WKQ4)        { in = wk; hi = wkh; lo = wkl; base = i - XQ4-WQQ4;           qtr = WKQ4; }
    else if (i < XQ4+WQQ4+WKQ4+WVQ4)   { in = wv; hi = wvh; lo = wvl; base = i - XQ4-WQQ4-WKQ4;      qtr = WVQ4; }
    else                               { in = wo; hi = woh; lo = wol; base = i - XQ4-WQQ4-WKQ4-WVQ4; qtr = WOQ4; }
    const float4* in4 = (const float4*)in;
    float4 v0 = in4[base];
    float4 v1 = in4[base + qtr];
    float4 v2 = in4[base + 2 * qtr];
    float4 v3 = in4[base + 3 * qtr];
    split_store(v0, hi, lo, base);
    split_store(v1, hi, lo, base + qtr);
    split_store(v2, hi, lo, base + 2 * qtr);
    split_store(v3, hi, lo, base + 3 * qtr);
}

// ---------------------------------------------------------------------------
// HMMA GEMM core (unchanged from R7): 3-term bf16 split, ldmatrix frags.
// ---------------------------------------------------------------------------
#define BM 128
#define BN 128
#define BKG 32
#define ASTRIDE 40
#define TILE_B (128 * ASTRIDE * 2)
#define STAGE_B (4 * TILE_B)
#define GEMM_SMEM (2 * STAGE_B)
#define NST (KDIM / BKG)

__device__ __forceinline__ void gemm_body(const __nv_bfloat16* __restrict__ Ahg,
                                          const __nv_bfloat16* __restrict__ Alg,
                                          const __nv_bfloat16* __restrict__ Bhg,
                                          const __nv_bfloat16* __restrict__ Blg,
                                          float* __restrict__ C,
                                          __nv_bfloat16* __restrict__ Ch,
                                          __nv_bfloat16* __restrict__ Cl,
                                          int N, int mBase, int nBase, char* smg) {
    const int t = threadIdx.x;
    const int wid = t >> 5, lane = t & 31;
    const int g = lane >> 2, tq = lane & 3;
    const int wm = wid & 3, wn = wid >> 2;

    float acc[2][8][4] = {};

    const int chunk = t & 3;
    const int row0 = t >> 2;

    const int sub16 = lane & 15;
    const int hi8 = (lane >> 4) << 3;
    const int q2 = lane >> 3, sub8 = lane & 7;
    const int loffA0 = ((wm * 32 + sub16) * ASTRIDE + hi8) * 2;
    const int loffA1 = ((wm * 32 + 16 + sub16) * ASTRIDE + hi8) * 2;
    const int loffB  = ((wn * 64 + ((q2 >> 1) << 3) + sub8) * ASTRIDE + ((q2 & 1) << 3)) * 2;

    const __nv_bfloat16* srcs[4] = {Ahg, Alg, Bhg, Blg};
    const int tb[4] = {mBase, mBase, nBase, nBase};

    {
        char* base = smg;
#pragma unroll
        for (int ti = 0; ti < 4; ti++)
#pragma unroll
            for (int rr = 0; rr < 2; rr++) {
                int r = row0 + rr * 64;
                uint32_t dst = smem_u32(base + ti * TILE_B + (r * ASTRIDE + chunk * 8) * 2);
                cp16(dst, srcs[ti] + (size_t)(tb[ti] + r) * KDIM + chunk * 8);
            }
        asm volatile("cp.async.commit_group;");
    }

    for (int s = 0; s < NST; s++) {
        if (s + 1 < NST) {
            char* base = smg + ((s + 1) & 1) * STAGE_B;
            int k0 = (s + 1) * BKG;
#pragma unroll
            for (int ti = 0; ti < 4; ti++)
#pragma unroll
                for (int rr = 0; rr < 2; rr++) {
                    int r = row0 + rr * 64;
                    uint32_t dst = smem_u32(base + ti * TILE_B + (r * ASTRIDE + chunk * 8) * 2);
                    cp16(dst, srcs[ti] + (size_t)(tb[ti] + r) * KDIM + k0 + chunk * 8);
                }
            asm volatile("cp.async.commit_group;");
            asm volatile("cp.async.wait_group 1;");
        } else {
            asm volatile("cp.async.wait_group 0;");
        }
        __syncthreads();

        uint32_t bAh = smem_u32(smg + (s & 1) * STAGE_B);
        uint32_t bAl = bAh + TILE_B;
        uint32_t bBh = bAh + 2 * TILE_B;
        uint32_t bBl = bAh + 3 * TILE_B;

#pragma unroll
        for (int ks = 0; ks < 2; ks++) {
            const int kk2 = ks * 32;
            uint32_t ah[2][4], al[2][4];
            ldsm4(ah[0], bAh + loffA0 + kk2);
            ldsm4(ah[1], bAh + loffA1 + kk2);
            ldsm4(al[0], bAl + loffA0 + kk2);
            ldsm4(al[1], bAl + loffA1 + kk2);
#pragma unroll
            for (int p = 0; p < 4; p++) {
                uint32_t bh4[4], bl4[4];
                ldsm4(bh4, bBh + loffB + p * (16 * ASTRIDE * 2) + kk2);
                ldsm4(bl4, bBl + loffB + p * (16 * ASTRIDE * 2) + kk2);
#pragma unroll
                for (int mf = 0; mf < 2; mf++) {
                    mma16816(acc[mf][2 * p],     ah[mf], bh4[0], bh4[1]);
                    mma16816(acc[mf][2 * p],     ah[mf], bl4[0], bl4[1]);
                    mma16816(acc[mf][2 * p],     al[mf], bh4[0], bh4[1]);
                    mma16816(acc[mf][2 * p + 1], ah[mf], bh4[2], bh4[3]);
                    mma16816(acc[mf][2 * p + 1], ah[mf], bl4[2], bl4[3]);
                    mma16816(acc[mf][2 * p + 1], al[mf], bh4[2], bh4[3]);
                }
            }
        }
        __syncthreads();
    }

    if (Ch) {
#pragma unroll
        for (int mf = 0; mf < 2; mf++) {
            int row = mBase + wm * 32 + mf * 16 + g;
#pragma unroll
            for (int nf = 0; nf < 8; nf++) {
                int col = nBase + wn * 64 + nf * 8 + 2 * tq;
                float a0 = acc[mf][nf][0], a1 = acc[mf][nf][1];
                float a2 = acc[mf][nf][2], a3 = acc[mf][nf][3];
                __nv_bfloat16 h0 = __float2bfloat16(a0), h1 = __float2bfloat16(a1);
                __nv_bfloat16 h2 = __float2bfloat16(a2), h3 = __float2bfloat16(a3);
                *(uint32_t*)(Ch + (size_t)row * N + col) =
                    (uint32_t)__bfloat16_as_ushort(h0) | ((uint32_t)__bfloat16_as_ushort(h1) << 16);
                *(uint32_t*)(Ch + (size_t)(row + 8) * N + col) =
                    (uint32_t)__bfloat16_as_ushort(h2) | ((uint32_t)__bfloat16_as_ushort(h3) << 16);
                *(uint32_t*)(Cl + (size_t)row * N + col) =
                    pack_bf2(a0 - __bfloat162float(h0), a1 - __bfloat162float(h1));
                *(uint32_t*)(Cl + (size_t)(row + 8) * N + col) =
                    pack_bf2(a2 - __bfloat162float(h2), a3 - __bfloat162float(h3));
            }
        }
    } else {
#pragma unroll
        for (int mf = 0; mf < 2; mf++) {
            int row = mBase + wm * 32 + mf * 16 + g;
#pragma unroll
            for (int nf = 0; nf < 8; nf++) {
                int col = nBase + wn * 64 + nf * 8 + 2 * tq;
                *(float2*)(C + (size_t)row * N + col) =
                    make_float2(acc[mf][nf][0], acc[mf][nf][1]);
                *(float2*)(C + (size_t)(row + 8) * N + col) =
                    make_float2(acc[mf][nf][2], acc[mf][nf][3]);
            }
        }
    }
}

__global__ __launch_bounds__(256, 2) void gemm_qkv(const __nv_bfloat16* __restrict__ xh,
                                                   const __nv_bfloat16* __restrict__ xl,
                                                   const __nv_bfloat16* __restrict__ wqh,
                                                   const __nv_bfloat16* __restrict__ wql,
                                                   const __nv_bfloat16* __restrict__ wkh,
                                                   const __nv_bfloat16* __restrict__ wkl,
                                                   const __nv_bfloat16* __restrict__ wvh,
                                                   const __nv_bfloat16* __restrict__ wvl,
                                                   float* __restrict__ Q,
                                                   float* __restrict__ K,
                                                   __nv_bfloat16* __restrict__ Vh,
                                                   __nv_bfloat16* __restrict__ Vl) {
    extern __shared__ char smg[];
    int bx = blockIdx.x;
    int mBase = blockIdx.y * BM;
    if (bx < 16) {
        gemm_body(xh, xl, wqh, wql, Q, nullptr, nullptr, NQD, mBase, bx * BN, smg);
    } else if (bx < 20) {
        gemm_body(xh, xl, wkh, wkl, K, nullptr, nullptr, NKD, mBase, (bx - 16) * BN, smg);
    } else {
        gemm_body(xh, xl, wvh, wvl, nullptr, Vh, Vl, NKD, mBase, (bx - 20) * BN, smg);
    }
}

__global__ __launch_bounds__(256, 2) void gemm_plain(const __nv_bfloat16* __restrict__ Ah,
                                                     const __nv_bfloat16* __restrict__ Al,
                                                     const __nv_bfloat16* __restrict__ Bh,
                                                     const __nv_bfloat16* __restrict__ Bl,
                                                     float* __restrict__ C, int N) {
    extern __shared__ char smg[];
    gemm_body(Ah, Al, Bh, Bl, C, nullptr, nullptr, N, blockIdx.y * BM, blockIdx.x * BN, smg);
}

// ---------------------------------------------------------------------------
// RoPE: one thread per (s, j); trig computed once, applied to all 20 heads.
// ---------------------------------------------------------------------------
__global__ void ropeQK_kernel(const float* __restrict__ Q, const float* __restrict__ K,
                              __nv_bfloat16* __restrict__ Qh, __nv_bfloat16* __restrict__ Ql,
                              __nv_bfloat16* __restrict__ Kh, __nv_bfloat16* __restrict__ Kl) {
    int idx = blockIdx.x * blockDim.x + threadIdx.x;
    if (idx >= S_LEN * 64) return;
    int j = idx & 63;
    int s = idx >> 6;

    float invf = expf(-logf(10000.0f) * (float)(2 * j) / (float)HD);
    float ang = (float)s * invf;
    float c, sn;
    sincosf(ang, &sn, &c);

#pragma unroll 4
    for (int hh = 0; hh < NH; hh++) {
        size_t base = (size_t)s * NQD + hh * HD;
        float a = Q[base + j], b = Q[base + j + 64];
        float ra = a * c - b * sn;
        float rb = b * c + a * sn;
        __nv_bfloat16 rah = __float2bfloat16(ra);
        __nv_bfloat16 rbh = __float2bfloat16(rb);
        Qh[base + j]      = rah;
        Qh[base + j + 64] = rbh;
        Ql[base + j]      = __float2bfloat16(ra - __bfloat162float(rah));
        Ql[base + j + 64] = __float2bfloat16(rb - __bfloat162float(rbh));
    }
#pragma unroll
    for (int hh = 0; hh < NKV; hh++) {
        size_t base = (size_t)s * NKD + hh * HD;
        float a = K[base + j], b = K[base + j + 64];
        float ra = a * c - b * sn;
        float rb = b * c + a * sn;
        __nv_bfloat16 rah = __float2bfloat16(ra);
        __nv_bfloat16 rbh = __float2bfloat16(rb);
        Kh[base + j]      = rah;
        Kh[base + j + 64] = rbh;
        Kl[base + j]      = __float2bfloat16(ra - __bfloat162float(rah));
        Kl[base + j + 64] = __float2bfloat16(rb - __bfloat162float(rbh));
    }
}

// ---------------------------------------------------------------------------
// HMMA flash attention. 128 q-rows per CTA, 64 keys per iter split into two
// 32-key chunks (S of chunk B overlaps softmax of chunk A). Per-warp chunk
// skipping outside the sliding window. Const-folded prefetch pointers.
// ---------------------------------------------------------------------------
#define FQ 128
#define FKK 64
#define FSTR 136
#define FROWB (FSTR * 2)
#define QT_B (FQ * FROWB)
#define KT_B (FKK * FROWB)
#define FSTAGE_B (4 * KT_B)
#define FSTAGE0 (2 * QT_B)
#define FLASH_SMEM (FSTAGE0 + 2 * FSTAGE_B)   // 208896

__global__ __launch_bounds__(256, 1) void flash_hmma(
        const __nv_bfloat16* __restrict__ Qh, const __nv_bfloat16* __restrict__ Ql,
        const __nv_bfloat16* __restrict__ Kh, const __nv_bfloat16* __restrict__ Kl,
        const __nv_bfloat16* __restrict__ Vh, const __nv_bfloat16* __restrict__ Vl,
        __nv_bfloat16* __restrict__ Oh, __nv_bfloat16* __restrict__ Ol) {
    extern __shared__ char sm[];
    const int tid = threadIdx.x;
    const int wid = tid >> 5, lane = tid & 31;
    const int g = lane >> 2, tq = lane & 3;
    const int qt = gridDim.x - 1 - blockIdx.x;   // heavy tiles first
    const int h = blockIdx.y;
    const int kvh = h >> 2;
    const int q0 = qt * FQ;
    const int rw = wid * 16;
    const float sc = 0.08838834764831845f;

    const int sub16 = lane & 15;
    const int hi8 = (lane >> 4) << 3;
    const int q2 = lane >> 3, sub8 = lane & 7;
    const int loffQ = ((rw + sub16) * FSTR + hi8) * 2;
    const int loffK = ((((q2 >> 1) << 3) + sub8) * FSTR + ((q2 & 1) << 3)) * 2;

    const int rmin = q0 + rw;        // warp's q-row range [rmin, rmin+15]
    const int rmax = rmin + 15;

    // ---- Q load (compile-time tile pointer) ----
#pragma unroll
    for (int t = 0; t < 2; t++) {
        const __nv_bfloat16* src0 = (t == 0) ? Qh : Ql;
#pragma unroll
        for (int ii = 0; ii < 8; ii++) {
            int rem = tid + ii * 256;                 // 0..2047
            int r = rem >> 4, c = rem & 15;
            uint32_t dst = smem_u32(sm + t * QT_B + r * FROWB + c * 16);
            cp16(dst, src0 + (size_t)(q0 + r) * NQD + h * HD + c * 8);
        }
    }

    int kt_begin = q0 - (WIN - 1);
    kt_begin = (kt_begin < 0) ? 0 : (kt_begin >> 6);
    const int kt_end = (q0 + FQ - 1) >> 6;

    // ---- first KV stage ----
    {
        int k0 = kt_begin * FKK;
        char* base = sm + FSTAGE0;
#pragma unroll
        for (int t = 0; t < 4; t++) {
            const __nv_bfloat16* s0 = (t == 0) ? Kh : (t == 1) ? Kl : (t == 2) ? Vh : Vl;
#pragma unroll
            for (int ii = 0; ii < 4; ii++) {
                int rem = tid + ii * 256;             // 0..1023
                int r = rem >> 4, c = rem & 15;
                uint32_t dst = smem_u32(base + t * KT_B + r * FROWB + c * 16);
                cp16(dst, s0 + (size_t)(k0 + r) * NKD + kvh * HD + c * 8);
            }
        }
        asm volatile("cp.async.commit_group;");
    }

    float oacc[16][4] = {};
    float m0 = -1e30f, m1 = -1e30f, l0 = 0.0f, l1 = 0.0f;

    for (int kt = kt_begin; kt <= kt_end; kt++) {
        const int buf = (kt - kt_begin) & 1;
        if (kt < kt_end) {
            int k0n = (kt + 1) * FKK;
            char* base = sm + FSTAGE0 + (buf ^ 1) * FSTAGE_B;
#pragma unroll
            for (int t = 0; t < 4; t++) {
                const __nv_bfloat16* s0 = (t == 0) ? Kh : (t == 1) ? Kl : (t == 2) ? Vh : Vl;
#pragma unroll
                for (int ii = 0; ii < 4; ii++) {
                    int rem = tid + ii * 256;
                    int r = rem >> 4, c = rem & 15;
                    uint32_t dst = smem_u32(base + t * KT_B + r * FROWB + c * 16);
                    cp16(dst, s0 + (size_t)(k0n + r) * NKD + kvh * HD + c * 8);
                }
            }
            asm volatile("cp.async.commit_group;");
            asm volatile("cp.async.wait_group 1;");
        } else {
            asm volatile("cp.async.wait_group 0;");
        }
        __syncthreads();

        uint32_t bQh = smem_u32(sm);
        uint32_t bQl = bQh + QT_B;
        uint32_t bKh = smem_u32(sm + FSTAGE0 + buf * FSTAGE_B);
        uint32_t bKl = bKh + KT_B;
        uint32_t bVh = bKh + 2 * KT_B;
        uint32_t bVl = bKh + 3 * KT_B;
        const int k0 = kt * FKK;

        // per-warp chunk activity (uniform branch)
        const bool actA = (k0 + 31 >= rmin - (WIN - 1)) && (k0 <= rmax);
        const bool actB = (k0 + 63 >= rmin - (WIN - 1)) && (k0 + 32 <= rmax);

        float sacc[8][4] = {};

        // ---- S chunk A: keys [k0, k0+31] ----
        if (actA) {
#pragma unroll
            for (int ks = 0; ks < 8; ks++) {
                const int kk2 = ks * 32;
                uint32_t qh[4], ql[4];
                ldsm4(qh, bQh + loffQ + kk2);
                ldsm4(ql, bQl + loffQ + kk2);
#pragma unroll
                for (int p = 0; p < 2; p++) {
                    uint32_t kh4[4], kl4[4];
                    ldsm4(kh4, bKh + loffK + p * (16 * FROWB) + kk2);
                    ldsm4(kl4, bKl + loffK + p * (16 * FROWB) + kk2);
                    mma16816(sacc[2 * p],     qh, kh4[0], kh4[1]);
                    mma16816(sacc[2 * p],     qh, kl4[0], kl4[1]);
                    mma16816(sacc[2 * p],     ql, kh4[0], kh4[1]);
                    mma16816(sacc[2 * p + 1], qh, kh4[2], kh4[3]);
                    mma16816(sacc[2 * p + 1], qh, kl4[2], kl4[3]);
                    mma16816(sacc[2 * p + 1], ql, kh4[2], kh4[3]);
                }
            }
        }
        // ---- S chunk B: keys [k0+32, k0+63] ----
        if (actB) {
#pragma unroll
            for (int ks = 0; ks < 8; ks++) {
                const int kk2 = ks * 32;
                uint32_t qh[4], ql[4];
                ldsm4(qh, bQh + loffQ + kk2);
                ldsm4(ql, bQl + loffQ + kk2);
#pragma unroll
                for (int p = 2; p < 4; p++) {
                    uint32_t kh4[4], kl4[4];
                    ldsm4(kh4, bKh + loffK + p * (16 * FROWB) + kk2);
                    ldsm4(kl4, bKl + loffK + p * (16 * FROWB) + kk2);
                    mma16816(sacc[2 * p],     qh, kh4[0], kh4[1]);
                    mma16816(sacc[2 * p],     qh, kl4[0], kl4[1]);
                    mma16816(sacc[2 * p],     ql, kh4[0], kh4[1]);
                    mma16816(sacc[2 * p + 1], qh, kh4[2], kh4[3]);
                    mma16816(sacc[2 * p + 1], qh, kl4[2], kl4[3]);
                    mma16816(sacc[2 * p + 1], ql, kh4[2], kh4[3]);
                }
            }
        }

        const int row0 = q0 + rw + g, row1 = row0 + 8;

        // ================= chunk A tail =================
        if (actA) {
            // mask + scale (nf 0..3)
#pragma unroll
            for (int nf = 0; nf < 4; nf++) {
                int colb = k0 + nf * 8 + 2 * tq;
#pragma unroll
                for (int c = 0; c < 4; c++) {
                    int col = colb + (c & 1);
                    int row = (c < 2) ? row0 : row1;
                    bool ok = (col <= row) && (row - col < WIN);
                    sacc[nf][c] = ok ? sacc[nf][c] * sc : -1e9f;
                }
            }
            float mx0 = -1e30f, mx1 = -1e30f;
#pragma unroll
            for (int nf = 0; nf < 4; nf++) {
                mx0 = fmaxf(mx0, fmaxf(sacc[nf][0], sacc[nf][1]));
                mx1 = fmaxf(mx1, fmaxf(sacc[nf][2], sacc[nf][3]));
            }
            mx0 = fmaxf(mx0, __shfl_xor_sync(0xffffffffu, mx0, 1));
            mx0 = fmaxf(mx0, __shfl_xor_sync(0xffffffffu, mx0, 2));
            mx1 = fmaxf(mx1, __shfl_xor_sync(0xffffffffu, mx1, 1));
            mx1 = fmaxf(mx1, __shfl_xor_sync(0xffffffffu, mx1, 2));
            float mn0 = fmaxf(m0, mx0), mn1 = fmaxf(m1, mx1);
            float al0 = __expf(m0 - mn0), al1 = __expf(m1 - mn1);
            m0 = mn0; m1 = mn1;
            float sum0 = 0.0f, sum1 = 0.0f;
#pragma unroll
            for (int nf = 0; nf < 4; nf++) {
                sacc[nf][0] = __expf(sacc[nf][0] - mn0);
                sacc[nf][1] = __expf(sacc[nf][1] - mn0);
                sacc[nf][2] = __expf(sacc[nf][2] - mn1);
                sacc[nf][3] = __expf(sacc[nf][3] - mn1);
                sum0 += sacc[nf][0] + sacc[nf][1];
                sum1 += sacc[nf][2] + sacc[nf][3];
            }
            sum0 += __shfl_xor_sync(0xffffffffu, sum0, 1);
            sum0 += __shfl_xor_sync(0xffffffffu, sum0, 2);
            sum1 += __shfl_xor_sync(0xffffffffu, sum1, 1);
            sum1 += __shfl_xor_sync(0xffffffffu, sum1, 2);
            l0 = l0 * al0 + sum0;
            l1 = l1 * al1 + sum1;
#pragma unroll
            for (int on = 0; on < 16; on++) {
                oacc[on][0] *= al0; oacc[on][1] *= al0;
                oacc[on][2] *= al1; oacc[on][3] *= al1;
            }
            // pack P_A (j = 0,1)
            uint32_t pah[2][4], pal[2][4];
#pragma unroll
            for (int j = 0; j < 2; j++) {
#pragma unroll
                for (int q = 0; q < 4; q++) {
                    int nf = 2 * j + (q >> 1);
                    float x = sacc[nf][(q & 1) * 2 + 0];
                    float y = sacc[nf][(q & 1) * 2 + 1];
                    __nv_bfloat16 hx = __float2bfloat16(x);
                    __nv_bfloat16 hy = __float2bfloat16(y);
                    pah[j][q] = (uint32_t)__bfloat16_as_ushort(hx) |
                                ((uint32_t)__bfloat16_as_ushort(hy) << 16);
                    pal[j][q] = pack_bf2(x - __bfloat162float(hx),
                                         y - __bfloat162float(hy));
                }
            }
            // PV_A (V rows 0..31)
#pragma unroll
            for (int j = 0; j < 2; j++) {
                int krow = j * 16 + (lane & 7) + ((lane >> 3) & 1) * 8;
#pragma unroll
                for (int vb = 0; vb < 8; vb++) {
                    int ncol = vb * 16 + (lane >> 4) * 8;
                    uint32_t vaddr = bVh + (krow * FSTR + ncol) * 2;
                    uint32_t waddr = bVl + (krow * FSTR + ncol) * 2;
                    uint32_t v0, v1, v2, v3, w0, w1, w2, w3;
                    ldsm4t(v0, v1, v2, v3, vaddr);
                    ldsm4t(w0, w1, w2, w3, waddr);
                    mma16816(oacc[2 * vb],     pah[j], v0, v1);
                    mma16816(oacc[2 * vb],     pal[j], v0, v1);
                    mma16816(oacc[2 * vb],     pah[j], w0, w1);
                    mma16816(oacc[2 * vb + 1], pah[j], v2, v3);
                    mma16816(oacc[2 * vb + 1], pal[j], v2, v3);
                    mma16816(oacc[2 * vb + 1], pah[j], w2, w3);
                }
            }
        }

        // ================= chunk B tail =================
        if (actB) {
#pragma unroll
            for (int nf = 4; nf < 8; nf++) {
                int colb = k0 + nf * 8 + 2 * tq;
#pragma unroll
                for (int c = 0; c < 4; c++) {
                    int col = colb + (c & 1);
                    int row = (c < 2) ? row0 : row1;
                    bool ok = (col <= row) && (row - col < WIN);
                    sacc[nf][c] = ok ? sacc[nf][c] * sc : -1e9f;
                }
            }
            float mx0 = -1e30f, mx1 = -1e30f;
#pragma unroll
            for (int nf = 4; nf < 8; nf++) {
                mx0 = fmaxf(mx0, fmaxf(sacc[nf][0], sacc[nf][1]));
                mx1 = fmaxf(mx1, fmaxf(sacc[nf][2], sacc[nf][3]));
            }
            mx0 = fmaxf(mx0, __shfl_xor_sync(0xffffffffu, mx0, 1));
            mx0 = fmaxf(mx0, __shfl_xor_sync(0xffffffffu, mx0, 2));
            mx1 = fmaxf(mx1, __shfl_xor_sync(0xffffffffu, mx1, 1));
            mx1 = fmaxf(mx1, __shfl_xor_sync(0xffffffffu, mx1, 2));
            float mn0 = fmaxf(m0, mx0), mn1 = fmaxf(m1, mx1);
            float al0 = __expf(m0 - mn0), al1 = __expf(m1 - mn1);
            m0 = mn0; m1 = mn1;
            float sum0 = 0.0f, sum1 = 0.0f;
#pragma unroll
            for (int nf = 4; nf < 8; nf++) {
                sacc[nf][0] = __expf(sacc[nf][0] - mn0);
                sacc[nf][1] = __expf(sacc[nf][1] - mn0);
                sacc[nf][2] = __expf(sacc[nf][2] - mn1);
                sacc[nf][3] = __expf(sacc[nf][3] - mn1);
                sum0 += sacc[nf][0] + sacc[nf][1];
                sum1 += sacc[nf][2] + sacc[nf][3];
            }
            sum0 += __shfl_xor_sync(0xffffffffu, sum0, 1);
            sum0 += __shfl_xor_sync(0xffffffffu, sum0, 2);
            sum1 += __shfl_xor_sync(0xffffffffu, sum1, 1);
            sum1 += __shfl_xor_sync(0xffffffffu, sum1, 2);
            l0 = l0 * al0 + sum0;
            l1 = l1 * al1 + sum1;
#pragma unroll
            for (int on = 0; on < 16; on++) {
                oacc[on][0] *= al0; oacc[on][1] *= al0;
                oacc[on][2] *= al1; oacc[on][3] *= al1;
            }
            uint32_t pah[2][4], pal[2][4];
#pragma unroll
            for (int j = 0; j < 2; j++) {
#pragma unroll
                for (int q = 0; q < 4; q++) {
                    int nf = 4 + 2 * j + (q >> 1);
                    float x = sacc[nf][(q & 1) * 2 + 0];
                    float y = sacc[nf][(q & 1) * 2 + 1];
                    __nv_bfloat16 hx = __float2bfloat16(x);
                    __nv_bfloat16 hy = __float2bfloat16(y);
                    pah[j][q] = (uint32_t)__bfloat16_as_ushort(hx) |
                                ((uint32_t)__bfloat16_as_ushort(hy) << 16);
                    pal[j][q] = pack_bf2(x - __bfloat162float(hx),
                                         y - __bfloat162float(hy));
                }
            }
            // PV_B (V rows 32..63)
#pragma unroll
            for (int j = 0; j < 2; j++) {
                int krow = (j + 2) * 16 + (lane & 7) + ((lane >> 3) & 1) * 8;
#pragma unroll
                for (int vb = 0; vb < 8; vb++) {
                    int ncol = vb * 16 + (lane >> 4) * 8;
                    uint32_t vaddr = bVh + (krow * FSTR + ncol) * 2;
                    uint32_t waddr = bVl + (krow * FSTR + ncol) * 2;
                    uint32_t v0, v1, v2, v3, w0, w1, w2, w3;
                    ldsm4t(v0, v1, v2, v3, vaddr);
                    ldsm4t(w0, w1, w2, w3, waddr);
                    mma16816(oacc[2 * vb],     pah[j], v0, v1);
                    mma16816(oacc[2 * vb],     pal[j], v0, v1);
                    mma16816(oacc[2 * vb],     pah[j], w0, w1);
                    mma16816(oacc[2 * vb + 1], pah[j], v2, v3);
                    mma16816(oacc[2 * vb + 1], pal[j], v2, v3);
                    mma16816(oacc[2 * vb + 1], pah[j], w2, w3);
                }
            }
        }
        __syncthreads();
    }

    // ---- finalize: write bf16 hi/lo directly ----
    float inv0 = 1.0f / l0, inv1 = 1.0f / l1;
    const int row0 = q0 + rw + g, row1 = row0 + 8;
#pragma unroll
    for (int on = 0; on < 16; on++) {
        int col = h * HD + on * 8 + 2 * tq;
        float x0 = oacc[on][0] * inv0, y0 = oacc[on][1] * inv0;
        float x1 = oacc[on][2] * inv1, y1 = oacc[on][3] * inv1;
        __nv_bfloat16 hx0 = __float2bfloat16(x0), hy0 = __float2bfloat16(y0);
        __nv_bfloat16 hx1 = __float2bfloat16(x1), hy1 = __float2bfloat16(y1);
        *(uint32_t*)(Oh + (size_t)row0 * NQD + col) =
            (uint32_t)__bfloat16_as_ushort(hx0) | ((uint32_t)__bfloat16_as_ushort(hy0) << 16);
        *(uint32_t*)(Oh + (size_t)row1 * NQD + col) =
            (uint32_t)__bfloat16_as_ushort(hx1) | ((uint32_t)__bfloat16_as_ushort(hy1) << 16);
        *(uint32_t*)(Ol + (size_t)row0 * NQD + col) =
            pack_bf2(x0 - __bfloat162float(hx0), y0 - __bfloat162float(hy0));
        *(uint32_t*)(Ol + (size_t)row1 * NQD + col) =
            pack_bf2(x1 - __bfloat162float(hx1), y1 - __bfloat162float(hy1));
    }
}

// ---------------------------------------------------------------------------
extern "C" void kernel_launch(void* const* d_in, const int* in_sizes, int n_in,
                              void* d_out, int out_size) {
    const float* x  = (const float*)d_in[0];
    // d_in[1] = attention_mask (deterministic sliding-window; computed analytically)
    const float* wq = (const float*)d_in[2];
    const float* wk = (const float*)d_in[3];
    const float* wv = (const float*)d_in[4];
    const float* wo = (const float*)d_in[5];
    float* out = (float*)d_out;

    float *Qb, *Kb;
    cudaGetSymbolAddress((void**)&Qb, g_Q);
    cudaGetSymbolAddress((void**)&Kb, g_K);
    __nv_bfloat16 *xh, *xl, *wqh, *wql, *wkh, *wkl, *wvh, *wvl, *woh, *wol, *ah, *al;
    __nv_bfloat16 *qhh, *qll, *khh, *kll, *vhh, *vll;
    cudaGetSymbolAddress((void**)&xh, g_xh);   cudaGetSymbolAddress((void**)&xl, g_xl);
    cudaGetSymbolAddress((void**)&wqh, g_wqh); cudaGetSymbolAddress((void**)&wql, g_wql);
    cudaGetSymbolAddress((void**)&wkh, g_wkh); cudaGetSymbolAddress((void**)&wkl, g_wkl);
    cudaGetSymbolAddress((void**)&wvh, g_wvh); cudaGetSymbolAddress((void**)&wvl, g_wvl);
    cudaGetSymbolAddress((void**)&woh, g_woh); cudaGetSymbolAddress((void**)&wol, g_wol);
    cudaGetSymbolAddress((void**)&ah, g_ah);   cudaGetSymbolAddress((void**)&al, g_al);
    cudaGetSymbolAddress((void**)&qhh, g_Qh);  cudaGetSymbolAddress((void**)&qll, g_Ql);
    cudaGetSymbolAddress((void**)&khh, g_Kh);  cudaGetSymbolAddress((void**)&kll, g_Kl);
    cudaGetSymbolAddress((void**)&vhh, g_Vh);  cudaGetSymbolAddress((void**)&vll, g_Vl);

    static bool attr_set = false;
    if (!attr_set) {
        cudaFuncSetAttribute(gemm_qkv, cudaFuncAttributeMaxDynamicSharedMemorySize,
                             (int)GEMM_SMEM);
        cudaFuncSetAttribute(gemm_plain, cudaFuncAttributeMaxDynamicSharedMemorySize,
                             (int)GEMM_SMEM);
        cudaFuncSetAttribute(flash_hmma, cudaFuncAttributeMaxDynamicSharedMemorySize,
                             (int)FLASH_SMEM);
        attr_set = true;
    }

    // 1. fused split of x + all weights (4 float4 per thread)
    splitAll_kernel<<<SPLIT_THREADS / 256, 256>>>(x, wq, wk, wv, wo,
                                                  xh, xl, wqh, wql, wkh, wkl,
                                                  wvh, wvl, woh, wol);
    // 2. fused QKV projection (V written directly as bf16 hi/lo)
    {
        dim3 gq(24, S_LEN / BM);
        gemm_qkv<<<gq, 256, GEMM_SMEM>>>(xh, xl, wqh, wql, wkh, wkl, wvh, wvl,
                                         Qb, Kb, vhh, vll);
    }
    // 3. fused RoPE Q+K -> bf16 hi/lo (trig shared across heads)
    {
        int tot = S_LEN * 64;
        ropeQK_kernel<<<(tot + 255) / 256, 256>>>(Qb, Kb, qhh, qll, khh, kll);
    }
    // 4. HMMA flash attention (chunk-pipelined)
    {
        dim3 g(S_LEN / FQ, NH);
        flash_hmma<<<g, 256, FLASH_SMEM>>>(qhh, qll, khh, kll, vhh, vll, ah, al);
    }
    // 5. output projection
    {
        dim3 go(HIDDIM / BN, S_LEN / BM);
        gemm_plain<<<go, 256, GEMM_SMEM>>>(ah, al, woh, wol, out, HIDDIM);
    }
}

// round 11
// speedup vs baseline: 3.7456x; 1.0066x over previous
#include <cuda_runtime.h>
#include <cuda_bf16.h>
#include <math.h>
#include <stdint.h>

#define S_LEN 2048
#define HIDDIM 2048
#define NH 16
#define NKV 4
#define HD 128
#define NQD (NH*HD)    // 2048
#define NKD (NKV*HD)   // 512
#define WIN 1024
#define KDIM 2048

// ---------------- scratch ---------------------------------------------------
__device__ float g_Q[S_LEN * NQD];
__device__ float g_K[S_LEN * NKD];

__device__ __nv_bfloat16 g_xh[S_LEN * HIDDIM], g_xl[S_LEN * HIDDIM];
__device__ __nv_bfloat16 g_wqh[NQD * HIDDIM],  g_wql[NQD * HIDDIM];
__device__ __nv_bfloat16 g_wkh[NKD * HIDDIM],  g_wkl[NKD * HIDDIM];
__device__ __nv_bfloat16 g_wvh[NKD * HIDDIM],  g_wvl[NKD * HIDDIM];
__device__ __nv_bfloat16 g_woh[HIDDIM * NQD],  g_wol[HIDDIM * NQD];
__device__ __nv_bfloat16 g_ah[S_LEN * NQD],    g_al[S_LEN * NQD];

__device__ __nv_bfloat16 g_Qh[S_LEN * NQD], g_Ql[S_LEN * NQD];
__device__ __nv_bfloat16 g_Kh[S_LEN * NKD], g_Kl[S_LEN * NKD];
__device__ __nv_bfloat16 g_Vh[S_LEN * NKD], g_Vl[S_LEN * NKD];

// ---------------- helpers ---------------------------------------------------
__device__ __forceinline__ uint32_t smem_u32(const void* p) {
    uint32_t a;
    asm("{ .reg .u64 t; cvta.to.shared.u64 t, %1; cvt.u32.u64 %0, t; }"
        : "=r"(a) : "l"(p));
    return a;
}

__device__ __forceinline__ void cp16(uint32_t dst, const void* src) {
    asm volatile("cp.async.cg.shared.global [%0], [%1], 16;" :: "r"(dst), "l"(src));
}

__device__ __forceinline__ void mma16816(float* c, const uint32_t* a,
                                         uint32_t b0, uint32_t b1) {
    asm volatile(
        "mma.sync.aligned.m16n8k16.row.col.f32.bf16.bf16.f32 "
        "{%0,%1,%2,%3}, {%4,%5,%6,%7}, {%8,%9}, {%0,%1,%2,%3};"
        : "+f"(c[0]), "+f"(c[1]), "+f"(c[2]), "+f"(c[3])
        : "r"(a[0]), "r"(a[1]), "r"(a[2]), "r"(a[3]), "r"(b0), "r"(b1));
}

__device__ __forceinline__ void ldsm4(uint32_t* r, uint32_t addr) {
    asm volatile("ldmatrix.sync.aligned.m8n8.x4.shared.b16 {%0,%1,%2,%3}, [%4];"
                 : "=r"(r[0]), "=r"(r[1]), "=r"(r[2]), "=r"(r[3]) : "r"(addr));
}

__device__ __forceinline__ void ldsm4t(uint32_t& r0, uint32_t& r1,
                                       uint32_t& r2, uint32_t& r3, uint32_t addr) {
    asm volatile("ldmatrix.sync.aligned.m8n8.x4.trans.shared.b16 {%0,%1,%2,%3}, [%4];"
                 : "=r"(r0), "=r"(r1), "=r"(r2), "=r"(r3) : "r"(addr));
}

__device__ __forceinline__ uint32_t pack_bf2(float x, float y) {
    __nv_bfloat16 hx = __float2bfloat16(x), hy = __float2bfloat16(y);
    return (uint32_t)__bfloat16_as_ushort(hx) |
           ((uint32_t)__bfloat16_as_ushort(hy) << 16);
}

// ---------------------------------------------------------------------------
// fused split: x, wq, wk, wv, wo -> bf16 hi/lo. 4 float4 per thread (MLP=4).
// ---------------------------------------------------------------------------
__device__ __forceinline__ void split_store(float4 v,
                                            __nv_bfloat16* __restrict__ hi,
                                            __nv_bfloat16* __restrict__ lo, int i) {
    __nv_bfloat16 h0 = __float2bfloat16(v.x);
    __nv_bfloat16 h1 = __float2bfloat16(v.y);
    __nv_bfloat16 h2 = __float2bfloat16(v.z);
    __nv_bfloat16 h3 = __float2bfloat16(v.w);
    __nv_bfloat16 l0 = __float2bfloat16(v.x - __bfloat162float(h0));
    __nv_bfloat16 l1 = __float2bfloat16(v.y - __bfloat162float(h1));
    __nv_bfloat16 l2 = __float2bfloat16(v.z - __bfloat162float(h2));
    __nv_bfloat16 l3 = __float2bfloat16(v.w - __bfloat162float(h3));
    uint2 hv, lv;
    hv.x = (uint32_t)__bfloat16_as_ushort(h0) | ((uint32_t)__bfloat16_as_ushort(h1) << 16);
    hv.y = (uint32_t)__bfloat16_as_ushort(h2) | ((uint32_t)__bfloat16_as_ushort(h3) << 16);
    lv.x = (uint32_t)__bfloat16_as_ushort(l0) | ((uint32_t)__bfloat16_as_ushort(l1) << 16);
    lv.y = (uint32_t)__bfloat16_as_ushort(l2) | ((uint32_t)__bfloat16_as_ushort(l3) << 16);
    ((uint2*)hi)[i] = hv;
    ((uint2*)lo)[i] = lv;
}

#define XQ4  262144
#define WQQ4 262144
#define WKQ4 65536
#define WVQ4 65536
#define WOQ4 262144
#define SPLIT_THREADS (XQ4 + WQQ4 + WKQ4 + WVQ4 + WOQ4)

__global__ void splitAll_kernel(const float* __restrict__ x,
                                const float* __restrict__ wq,
                                const float* __restrict__ wk,
                                const float* __restrict__ wv,
                                const float* __restrict__ wo,
                                __nv_bfloat16* xh, __nv_bfloat16* xl,
                                __nv_bfloat16* wqh, __nv_bfloat16* wql,
                                __nv_bfloat16* wkh, __nv_bfloat16* wkl,
                                __nv_bfloat16* wvh, __nv_bfloat16* wvl,
                                __nv_bfloat16* woh, __nv_bfloat16* wol) {
    int i = blockIdx.x * blockDim.x + threadIdx.x;
    const float* in; __nv_bfloat16 *hi, *lo; int base, qtr;
    if (i < XQ4)                       { in = x;  hi = xh;  lo = xl;  base = i;                      qtr = XQ4;  }
    else if (i < XQ4+WQQ4)             { in = wq; hi = wqh; lo = wql; base = i - XQ4;                qtr = WQQ4; }
    else if (i < XQ4+WQQ4+WKQ4)        { in = wk; hi = wkh; lo = wkl; base = i - XQ4-WQQ4;           qtr = WKQ4; }
    else if (i < XQ4+WQQ4+WKQ4+WVQ4)   { in = wv; hi = wvh; lo = wvl; base = i - XQ4-WQQ4-WKQ4;      qtr = WVQ4; }
    else                               { in = wo; hi = woh; lo = wol; base = i - XQ4-WQQ4-WKQ4-WVQ4; qtr = WOQ4; }
    const float4* in4 = (const float4*)in;
    float4 v0 = in4[base];
    float4 v1 = in4[base + qtr];
    float4 v2 = in4[base + 2 * qtr];
    float4 v3 = in4[base + 3 * qtr];
    split_store(v0, hi, lo, base);
    split_store(v1, hi, lo, base + qtr);
    split_store(v2, hi, lo, base + 2 * qtr);
    split_store(v3, hi, lo, base + 3 * qtr);
}

// ---------------------------------------------------------------------------
// HMMA GEMM core (proven R9 config): 3-term bf16 split, ldmatrix frags,
// ASTRIDE=40 (80B rows, 16B-aligned), 2-stage cp.async, 2 CTAs/SM.
// ---------------------------------------------------------------------------
#define BM 128
#define BN 128
#define BKG 32
#define ASTRIDE 40
#define TILE_B (128 * ASTRIDE * 2)
#define STAGE_B (4 * TILE_B)
#define GEMM_SMEM (2 * STAGE_B)          // 81920
#define NST (KDIM / BKG)

__device__ __forceinline__ void gemm_body(const __nv_bfloat16* __restrict__ Ahg,
                                          const __nv_bfloat16* __restrict__ Alg,
                                          const __nv_bfloat16* __restrict__ Bhg,
                                          const __nv_bfloat16* __restrict__ Blg,
                                          float* __restrict__ C,
                                          __nv_bfloat16* __restrict__ Ch,
                                          __nv_bfloat16* __restrict__ Cl,
                                          int N, int mBase, int nBase, char* smg) {
    const int t = threadIdx.x;
    const int wid = t >> 5, lane = t & 31;
    const int g = lane >> 2, tq = lane & 3;
    const int wm = wid & 3, wn = wid >> 2;

    float acc[2][8][4] = {};

    const int chunk = t & 3;
    const int row0 = t >> 2;

    const int sub16 = lane & 15;
    const int hi8 = (lane >> 4) << 3;
    const int q2 = lane >> 3, sub8 = lane & 7;
    const int loffA0 = ((wm * 32 + sub16) * ASTRIDE + hi8) * 2;
    const int loffA1 = ((wm * 32 + 16 + sub16) * ASTRIDE + hi8) * 2;
    const int loffB  = ((wn * 64 + ((q2 >> 1) << 3) + sub8) * ASTRIDE + ((q2 & 1) << 3)) * 2;

    const __nv_bfloat16* srcs[4] = {Ahg, Alg, Bhg, Blg};
    const int tb[4] = {mBase, mBase, nBase, nBase};

    {
        char* base = smg;
#pragma unroll
        for (int ti = 0; ti < 4; ti++)
#pragma unroll
            for (int rr = 0; rr < 2; rr++) {
                int r = row0 + rr * 64;
                uint32_t dst = smem_u32(base + ti * TILE_B + (r * ASTRIDE + chunk * 8) * 2);
                cp16(dst, srcs[ti] + (size_t)(tb[ti] + r) * KDIM + chunk * 8);
            }
        asm volatile("cp.async.commit_group;");
    }

    for (int s = 0; s < NST; s++) {
        if (s + 1 < NST) {
            char* base = smg + ((s + 1) & 1) * STAGE_B;
            int k0 = (s + 1) * BKG;
#pragma unroll
            for (int ti = 0; ti < 4; ti++)
#pragma unroll
                for (int rr = 0; rr < 2; rr++) {
                    int r = row0 + rr * 64;
                    uint32_t dst = smem_u32(base + ti * TILE_B + (r * ASTRIDE + chunk * 8) * 2);
                    cp16(dst, srcs[ti] + (size_t)(tb[ti] + r) * KDIM + k0 + chunk * 8);
                }
            asm volatile("cp.async.commit_group;");
            asm volatile("cp.async.wait_group 1;");
        } else {
            asm volatile("cp.async.wait_group 0;");
        }
        __syncthreads();

        uint32_t bAh = smem_u32(smg + (s & 1) * STAGE_B);
        uint32_t bAl = bAh + TILE_B;
        uint32_t bBh = bAh + 2 * TILE_B;
        uint32_t bBl = bAh + 3 * TILE_B;

#pragma unroll
        for (int ks = 0; ks < 2; ks++) {
            const int kk2 = ks * 32;
            uint32_t ah[2][4], al[2][4];
            ldsm4(ah[0], bAh + loffA0 + kk2);
            ldsm4(ah[1], bAh + loffA1 + kk2);
            ldsm4(al[0], bAl + loffA0 + kk2);
            ldsm4(al[1], bAl + loffA1 + kk2);
#pragma unroll
            for (int p = 0; p < 4; p++) {
                uint32_t bh4[4], bl4[4];
                ldsm4(bh4, bBh + loffB + p * (16 * ASTRIDE * 2) + kk2);
                ldsm4(bl4, bBl + loffB + p * (16 * ASTRIDE * 2) + kk2);
#pragma unroll
                for (int mf = 0; mf < 2; mf++) {
                    mma16816(acc[mf][2 * p],     ah[mf], bh4[0], bh4[1]);
                    mma16816(acc[mf][2 * p],     ah[mf], bl4[0], bl4[1]);
                    mma16816(acc[mf][2 * p],     al[mf], bh4[0], bh4[1]);
                    mma16816(acc[mf][2 * p + 1], ah[mf], bh4[2], bh4[3]);
                    mma16816(acc[mf][2 * p + 1], ah[mf], bl4[2], bl4[3]);
                    mma16816(acc[mf][2 * p + 1], al[mf], bh4[2], bh4[3]);
                }
            }
        }
        __syncthreads();
    }

    if (Ch) {
#pragma unroll
        for (int mf = 0; mf < 2; mf++) {
            int row = mBase + wm * 32 + mf * 16 + g;
#pragma unroll
            for (int nf = 0; nf < 8; nf++) {
                int col = nBase + wn * 64 + nf * 8 + 2 * tq;
                float a0 = acc[mf][nf][0], a1 = acc[mf][nf][1];
                float a2 = acc[mf][nf][2], a3 = acc[mf][nf][3];
                __nv_bfloat16 h0 = __float2bfloat16(a0), h1 = __float2bfloat16(a1);
                __nv_bfloat16 h2 = __float2bfloat16(a2), h3 = __float2bfloat16(a3);
                *(uint32_t*)(Ch + (size_t)row * N + col) =
                    (uint32_t)__bfloat16_as_ushort(h0) | ((uint32_t)__bfloat16_as_ushort(h1) << 16);
                *(uint32_t*)(Ch + (size_t)(row + 8) * N + col) =
                    (uint32_t)__bfloat16_as_ushort(h2) | ((uint32_t)__bfloat16_as_ushort(h3) << 16);
                *(uint32_t*)(Cl + (size_t)row * N + col) =
                    pack_bf2(a0 - __bfloat162float(h0), a1 - __bfloat162float(h1));
                *(uint32_t*)(Cl + (size_t)(row + 8) * N + col) =
                    pack_bf2(a2 - __bfloat162float(h2), a3 - __bfloat162float(h3));
            }
        }
    } else {
#pragma unroll
        for (int mf = 0; mf < 2; mf++) {
            int row = mBase + wm * 32 + mf * 16 + g;
#pragma unroll
            for (int nf = 0; nf < 8; nf++) {
                int col = nBase + wn * 64 + nf * 8 + 2 * tq;
                *(float2*)(C + (size_t)row * N + col) =
                    make_float2(acc[mf][nf][0], acc[mf][nf][1]);
                *(float2*)(C + (size_t)(row + 8) * N + col) =
                    make_float2(acc[mf][nf][2], acc[mf][nf][3]);
            }
        }
    }
}

__global__ __launch_bounds__(256, 2) void gemm_qkv(const __nv_bfloat16* __restrict__ xh,
                                                   const __nv_bfloat16* __restrict__ xl,
                                                   const __nv_bfloat16* __restrict__ wqh,
                                                   const __nv_bfloat16* __restrict__ wql,
                                                   const __nv_bfloat16* __restrict__ wkh,
                                                   const __nv_bfloat16* __restrict__ wkl,
                                                   const __nv_bfloat16* __restrict__ wvh,
                                                   const __nv_bfloat16* __restrict__ wvl,
                                                   float* __restrict__ Q,
                                                   float* __restrict__ K,
                                                   __nv_bfloat16* __restrict__ Vh,
                                                   __nv_bfloat16* __restrict__ Vl) {
    extern __shared__ char smg[];
    int bx = blockIdx.x;
    int mBase = blockIdx.y * BM;
    if (bx < 16) {
        gemm_body(xh, xl, wqh, wql, Q, nullptr, nullptr, NQD, mBase, bx * BN, smg);
    } else if (bx < 20) {
        gemm_body(xh, xl, wkh, wkl, K, nullptr, nullptr, NKD, mBase, (bx - 16) * BN, smg);
    } else {
        gemm_body(xh, xl, wvh, wvl, nullptr, Vh, Vl, NKD, mBase, (bx - 20) * BN, smg);
    }
}

__global__ __launch_bounds__(256, 2) void gemm_plain(const __nv_bfloat16* __restrict__ Ah,
                                                     const __nv_bfloat16* __restrict__ Al,
                                                     const __nv_bfloat16* __restrict__ Bh,
                                                     const __nv_bfloat16* __restrict__ Bl,
                                                     float* __restrict__ C, int N) {
    extern __shared__ char smg[];
    gemm_body(Ah, Al, Bh, Bl, C, nullptr, nullptr, N, blockIdx.y * BM, blockIdx.x * BN, smg);
}

// ---------------------------------------------------------------------------
// RoPE: one thread per (s, j); trig computed once, applied to all 20 heads.
// ---------------------------------------------------------------------------
__global__ void ropeQK_kernel(const float* __restrict__ Q, const float* __restrict__ K,
                              __nv_bfloat16* __restrict__ Qh, __nv_bfloat16* __restrict__ Ql,
                              __nv_bfloat16* __restrict__ Kh, __nv_bfloat16* __restrict__ Kl) {
    int idx = blockIdx.x * blockDim.x + threadIdx.x;
    if (idx >= S_LEN * 64) return;
    int j = idx & 63;
    int s = idx >> 6;

    float invf = expf(-logf(10000.0f) * (float)(2 * j) / (float)HD);
    float ang = (float)s * invf;
    float c, sn;
    sincosf(ang, &sn, &c);

#pragma unroll 4
    for (int hh = 0; hh < NH; hh++) {
        size_t base = (size_t)s * NQD + hh * HD;
        float a = Q[base + j], b = Q[base + j + 64];
        float ra = a * c - b * sn;
        float rb = b * c + a * sn;
        __nv_bfloat16 rah = __float2bfloat16(ra);
        __nv_bfloat16 rbh = __float2bfloat16(rb);
        Qh[base + j]      = rah;
        Qh[base + j + 64] = rbh;
        Ql[base + j]      = __float2bfloat16(ra - __bfloat162float(rah));
        Ql[base + j + 64] = __float2bfloat16(rb - __bfloat162float(rbh));
    }
#pragma unroll
    for (int hh = 0; hh < NKV; hh++) {
        size_t base = (size_t)s * NKD + hh * HD;
        float a = K[base + j], b = K[base + j + 64];
        float ra = a * c - b * sn;
        float rb = b * c + a * sn;
        __nv_bfloat16 rah = __float2bfloat16(ra);
        __nv_bfloat16 rbh = __float2bfloat16(rb);
        Kh[base + j]      = rah;
        Kh[base + j + 64] = rbh;
        Kl[base + j]      = __float2bfloat16(ra - __bfloat162float(rah));
        Kl[base + j + 64] = __float2bfloat16(rb - __bfloat162float(rbh));
    }
}

// ---------------------------------------------------------------------------
// HMMA flash attention, 2 CTAs/SM. 128 q-rows per CTA, 16-key KV chunks,
// 2-stage cp.async, rescale-skip. smem = 104448 (Q 69632 + 2 x 17408).
// All smem rows are 272 bytes (16B-aligned).
// ---------------------------------------------------------------------------
#define FQ 128
#define FCH 16
#define FSTR 136
#define FROWB (FSTR * 2)                 // 272
#define QT_B (FQ * FROWB)                // 34816
#define CH_TILE (FCH * FROWB)            // 4352
#define FCH_B (4 * CH_TILE)              // 17408
#define FSTAGE0 (2 * QT_B)               // 69632
#define FLASH_SMEM (FSTAGE0 + 2 * FCH_B) // 104448

__device__ __forceinline__ void flash_load_chunk(const __nv_bfloat16* __restrict__ Kh,
                                                 const __nv_bfloat16* __restrict__ Kl,
                                                 const __nv_bfloat16* __restrict__ Vh,
                                                 const __nv_bfloat16* __restrict__ Vl,
                                                 int k0, int kvh, char* base, int tid) {
    int r = tid >> 4, c = tid & 15;
#pragma unroll
    for (int ti = 0; ti < 4; ti++) {
        const __nv_bfloat16* s0 = (ti == 0) ? Kh : (ti == 1) ? Kl : (ti == 2) ? Vh : Vl;
        uint32_t dst = smem_u32(base + ti * CH_TILE + r * FROWB + c * 16);
        cp16(dst, s0 + (size_t)(k0 + r) * NKD + kvh * HD + c * 8);
    }
}

__global__ __launch_bounds__(256, 2) void flash_hmma(
        const __nv_bfloat16* __restrict__ Qh, const __nv_bfloat16* __restrict__ Ql,
        const __nv_bfloat16* __restrict__ Kh, const __nv_bfloat16* __restrict__ Kl,
        const __nv_bfloat16* __restrict__ Vh, const __nv_bfloat16* __restrict__ Vl,
        __nv_bfloat16* __restrict__ Oh, __nv_bfloat16* __restrict__ Ol) {
    extern __shared__ char sm[];
    const int tid = threadIdx.x;
    const int wid = tid >> 5, lane = tid & 31;
    const int g = lane >> 2, tq = lane & 3;
    const int qt = gridDim.x - 1 - blockIdx.x;   // heavy tiles first
    const int h = blockIdx.y;
    const int kvh = h >> 2;
    const int q0 = qt * FQ;
    const int rw = wid * 16;
    const float sc = 0.08838834764831845f;

    const int sub16 = lane & 15;
    const int hi8 = (lane >> 4) << 3;
    const int q2 = lane >> 3, sub8 = lane & 7;
    const int loffQ = ((rw + sub16) * FSTR + hi8) * 2;
    const int loffK = ((((q2 >> 1) << 3) + sub8) * FSTR + ((q2 & 1) << 3)) * 2;

    const int rmin = q0 + rw;
    const int rmax = rmin + 15;

    // ---- Q load ----
#pragma unroll
    for (int ti = 0; ti < 2; ti++) {
        const __nv_bfloat16* src0 = (ti == 0) ? Qh : Ql;
#pragma unroll
        for (int ii = 0; ii < 8; ii++) {
            int rem = tid + ii * 256;
            int r = rem >> 4, c = rem & 15;
            uint32_t dst = smem_u32(sm + ti * QT_B + r * FROWB + c * 16);
            cp16(dst, src0 + (size_t)(q0 + r) * NQD + h * HD + c * 8);
        }
    }

    int lo_key = q0 - (WIN - 1);
    if (lo_key < 0) lo_key = 0;
    const int kc_begin = lo_key >> 4;
    const int kc_end = (q0 + FQ - 1) >> 4;

    flash_load_chunk(Kh, Kl, Vh, Vl, kc_begin * FCH, kvh, sm + FSTAGE0, tid);
    asm volatile("cp.async.commit_group;");

    float oacc[16][4] = {};
    float m0 = -1e30f, m1 = -1e30f, l0 = 0.0f, l1 = 0.0f;

    for (int kc = kc_begin; kc <= kc_end; kc++) {
        const int buf = (kc - kc_begin) & 1;
        if (kc < kc_end) {
            flash_load_chunk(Kh, Kl, Vh, Vl, (kc + 1) * FCH, kvh,
                             sm + FSTAGE0 + (buf ^ 1) * FCH_B, tid);
            asm volatile("cp.async.commit_group;");
            asm volatile("cp.async.wait_group 1;");
        } else {
            asm volatile("cp.async.wait_group 0;");
        }
        __syncthreads();

        const int k0 = kc * FCH;
        const bool act = (k0 + FCH - 1 >= rmin - (WIN - 1)) && (k0 <= rmax);

        if (act) {
            uint32_t bQh = smem_u32(sm);
            uint32_t bQl = bQh + QT_B;
            uint32_t bKh = smem_u32(sm + FSTAGE0 + buf * FCH_B);
            uint32_t bKl = bKh + CH_TILE;
            uint32_t bVh = bKh + 2 * CH_TILE;
            uint32_t bVl = bKh + 3 * CH_TILE;

            // ---- S = Q K^T for this 16-key chunk ----
            float sacc[2][4] = {};
#pragma unroll
            for (int ks = 0; ks < 8; ks++) {
                const int kk2 = ks * 32;
                uint32_t qh[4], ql[4], kh4[4], kl4[4];
                ldsm4(qh, bQh + loffQ + kk2);
                ldsm4(ql, bQl + loffQ + kk2);
                ldsm4(kh4, bKh + loffK + kk2);
                ldsm4(kl4, bKl + loffK + kk2);
                mma16816(sacc[0], qh, kh4[0], kh4[1]);
                mma16816(sacc[0], qh, kl4[0], kl4[1]);
                mma16816(sacc[0], ql, kh4[0], kh4[1]);
                mma16816(sacc[1], qh, kh4[2], kh4[3]);
                mma16816(sacc[1], qh, kl4[2], kl4[3]);
                mma16816(sacc[1], ql, kh4[2], kh4[3]);
            }

            // ---- mask + scale ----
            const int row0 = q0 + rw + g, row1 = row0 + 8;
#pragma unroll
            for (int nf = 0; nf < 2; nf++) {
                int colb = k0 + nf * 8 + 2 * tq;
#pragma unroll
                for (int c = 0; c < 4; c++) {
                    int col = colb + (c & 1);
                    int row = (c < 2) ? row0 : row1;
                    bool ok = (col <= row) && (row - col < WIN);
                    sacc[nf][c] = ok ? sacc[nf][c] * sc : -1e9f;
                }
            }

            // ---- online softmax ----
            float mx0 = fmaxf(fmaxf(sacc[0][0], sacc[0][1]), fmaxf(sacc[1][0], sacc[1][1]));
            float mx1 = fmaxf(fmaxf(sacc[0][2], sacc[0][3]), fmaxf(sacc[1][2], sacc[1][3]));
            mx0 = fmaxf(mx0, __shfl_xor_sync(0xffffffffu, mx0, 1));
            mx0 = fmaxf(mx0, __shfl_xor_sync(0xffffffffu, mx0, 2));
            mx1 = fmaxf(mx1, __shfl_xor_sync(0xffffffffu, mx1, 1));
            mx1 = fmaxf(mx1, __shfl_xor_sync(0xffffffffu, mx1, 2));
            bool upd = (mx0 > m0) || (mx1 > m1);
            float mn0 = fmaxf(m0, mx0), mn1 = fmaxf(m1, mx1);
            float al0 = __expf(m0 - mn0), al1 = __expf(m1 - mn1);
            m0 = mn0; m1 = mn1;

            float sum0 = 0.0f, sum1 = 0.0f;
#pragma unroll
            for (int nf = 0; nf < 2; nf++) {
                sacc[nf][0] = __expf(sacc[nf][0] - mn0);
                sacc[nf][1] = __expf(sacc[nf][1] - mn0);
                sacc[nf][2] = __expf(sacc[nf][2] - mn1);
                sacc[nf][3] = __expf(sacc[nf][3] - mn1);
                sum0 += sacc[nf][0] + sacc[nf][1];
                sum1 += sacc[nf][2] + sacc[nf][3];
            }
            sum0 += __shfl_xor_sync(0xffffffffu, sum0, 1);
            sum0 += __shfl_xor_sync(0xffffffffu, sum0, 2);
            sum1 += __shfl_xor_sync(0xffffffffu, sum1, 1);
            sum1 += __shfl_xor_sync(0xffffffffu, sum1, 2);
            l0 = l0 * al0 + sum0;
            l1 = l1 * al1 + sum1;

            // ---- rescale O only when max changed anywhere in warp ----
            if (__any_sync(0xffffffffu, upd)) {
#pragma unroll
                for (int on = 0; on < 16; on++) {
                    oacc[on][0] *= al0; oacc[on][1] *= al0;
                    oacc[on][2] *= al1; oacc[on][3] *= al1;
                }
            }

            // ---- pack P (bf16 hi/lo) ----
            uint32_t pah[4], pal[4];
#pragma unroll
            for (int q = 0; q < 4; q++) {
                int nf = q >> 1;
                float x = sacc[nf][(q & 1) * 2 + 0];
                float y = sacc[nf][(q & 1) * 2 + 1];
                __nv_bfloat16 hx = __float2bfloat16(x);
                __nv_bfloat16 hy = __float2bfloat16(y);
                pah[q] = (uint32_t)__bfloat16_as_ushort(hx) |
                         ((uint32_t)__bfloat16_as_ushort(hy) << 16);
                pal[q] = pack_bf2(x - __bfloat162float(hx),
                                  y - __bfloat162float(hy));
            }

            // ---- O += P V (16 V rows) ----
            int krow = (lane & 7) + ((lane >> 3) & 1) * 8;
#pragma unroll
            for (int vb = 0; vb < 8; vb++) {
                int ncol = vb * 16 + (lane >> 4) * 8;
                uint32_t vaddr = bVh + (krow * FSTR + ncol) * 2;
                uint32_t waddr = bVl + (krow * FSTR + ncol) * 2;
                uint32_t v0, v1, v2, v3, w0, w1, w2, w3;
                ldsm4t(v0, v1, v2, v3, vaddr);
                ldsm4t(w0, w1, w2, w3, waddr);
                mma16816(oacc[2 * vb],     pah, v0, v1);
                mma16816(oacc[2 * vb],     pal, v0, v1);
                mma16816(oacc[2 * vb],     pah, w0, w1);
                mma16816(oacc[2 * vb + 1], pah, v2, v3);
                mma16816(oacc[2 * vb + 1], pal, v2, v3);
                mma16816(oacc[2 * vb + 1], pah, w2, w3);
            }
        }
        __syncthreads();
    }

    // ---- finalize: write bf16 hi/lo ----
    float inv0 = 1.0f / l0, inv1 = 1.0f / l1;
    const int row0 = q0 + rw + g, row1 = row0 + 8;
#pragma unroll
    for (int on = 0; on < 16; on++) {
        int col = h * HD + on * 8 + 2 * tq;
        float x0 = oacc[on][0] * inv0, y0 = oacc[on][1] * inv0;
        float x1 = oacc[on][2] * inv1, y1 = oacc[on][3] * inv1;
        __nv_bfloat16 hx0 = __float2bfloat16(x0), hy0 = __float2bfloat16(y0);
        __nv_bfloat16 hx1 = __float2bfloat16(x1), hy1 = __float2bfloat16(y1);
        *(uint32_t*)(Oh + (size_t)row0 * NQD + col) =
            (uint32_t)__bfloat16_as_ushort(hx0) | ((uint32_t)__bfloat16_as_ushort(hy0) << 16);
        *(uint32_t*)(Oh + (size_t)row1 * NQD + col) =
            (uint32_t)__bfloat16_as_ushort(hx1) | ((uint32_t)__bfloat16_as_ushort(hy1) << 16);
        *(uint32_t*)(Ol + (size_t)row0 * NQD + col) =
            pack_bf2(x0 - __bfloat162float(hx0), y0 - __bfloat162float(hy0));
        *(uint32_t*)(Ol + (size_t)row1 * NQD + col) =
            pack_bf2(x1 - __bfloat162float(hx1), y1 - __bfloat162float(hy1));
    }
}

// ---------------------------------------------------------------------------
extern "C" void kernel_launch(void* const* d_in, const int* in_sizes, int n_in,
                              void* d_out, int out_size) {
    const float* x  = (const float*)d_in[0];
    // d_in[1] = attention_mask (deterministic sliding-window; computed analytically)
    const float* wq = (const float*)d_in[2];
    const float* wk = (const float*)d_in[3];
    const float* wv = (const float*)d_in[4];
    const float* wo = (const float*)d_in[5];
    float* out = (float*)d_out;

    float *Qb, *Kb;
    cudaGetSymbolAddress((void**)&Qb, g_Q);
    cudaGetSymbolAddress((void**)&Kb, g_K);
    __nv_bfloat16 *xh, *xl, *wqh, *wql, *wkh, *wkl, *wvh, *wvl, *woh, *wol, *ah, *al;
    __nv_bfloat16 *qhh, *qll, *khh, *kll, *vhh, *vll;
    cudaGetSymbolAddress((void**)&xh, g_xh);   cudaGetSymbolAddress((void**)&xl, g_xl);
    cudaGetSymbolAddress((void**)&wqh, g_wqh); cudaGetSymbolAddress((void**)&wql, g_wql);
    cudaGetSymbolAddress((void**)&wkh, g_wkh); cudaGetSymbolAddress((void**)&wkl, g_wkl);
    cudaGetSymbolAddress((void**)&wvh, g_wvh); cudaGetSymbolAddress((void**)&wvl, g_wvl);
    cudaGetSymbolAddress((void**)&woh, g_woh); cudaGetSymbolAddress((void**)&wol, g_wol);
    cudaGetSymbolAddress((void**)&ah, g_ah);   cudaGetSymbolAddress((void**)&al, g_al);
    cudaGetSymbolAddress((void**)&qhh, g_Qh);  cudaGetSymbolAddress((void**)&qll, g_Ql);
    cudaGetSymbolAddress((void**)&khh, g_Kh);  cudaGetSymbolAddress((void**)&kll, g_Kl);
    cudaGetSymbolAddress((void**)&vhh, g_Vh);  cudaGetSymbolAddress((void**)&vll, g_Vl);

    static bool attr_set = false;
    if (!attr_set) {
        cudaFuncSetAttribute(gemm_qkv, cudaFuncAttributeMaxDynamicSharedMemorySize,
                             (int)GEMM_SMEM);
        cudaFuncSetAttribute(gemm_plain, cudaFuncAttributeMaxDynamicSharedMemorySize,
                             (int)GEMM_SMEM);
        cudaFuncSetAttribute(flash_hmma, cudaFuncAttributeMaxDynamicSharedMemorySize,
                             (int)FLASH_SMEM);
        attr_set = true;
    }

    // 1. fused split of x + all weights
    splitAll_kernel<<<SPLIT_THREADS / 256, 256>>>(x, wq, wk, wv, wo,
                                                  xh, xl, wqh, wql, wkh, wkl,
                                                  wvh, wvl, woh, wol);
    // 2. fused QKV projection (V written directly as bf16 hi/lo)
    {
        dim3 gq(24, S_LEN / BM);
        gemm_qkv<<<gq, 256, GEMM_SMEM>>>(xh, xl, wqh, wql, wkh, wkl, wvh, wvl,
                                         Qb, Kb, vhh, vll);
    }
    // 3. fused RoPE Q+K -> bf16 hi/lo
    {
        int tot = S_LEN * 64;
        ropeQK_kernel<<<(tot + 255) / 256, 256>>>(Qb, Kb, qhh, qll, khh, kll);
    }
    // 4. HMMA flash attention (2 CTAs/SM)
    {
        dim3 g(S_LEN / FQ, NH);
        flash_hmma<<<g, 256, FLASH_SMEM>>>(qhh, qll, khh, kll, vhh, vll, ah, al);
    }
    // 5. output projection
    {
        dim3 go(HIDDIM / BN, S_LEN / BM);
        gemm_plain<<<go, 256, GEMM_SMEM>>>(ah, al, woh, wol, out, HIDDIM);
    }
}